// round 6
// baseline (speedup 1.0000x reference)
#include <cuda_runtime.h>
#include <cuda_bf16.h>
#include <math.h>
#include <stdint.h>

typedef __nv_bfloat16 bf16;

// ---------------- problem dims ----------------
#define B_    2
#define SQ_   1024
#define D_    2048
#define H_    16
#define HD_   128
#define SP_   1024
#define SS_   1024
#define SM_   512
#define SKV_  2560
#define DP_   1280
#define DS_   1024
#define DM_   768
#define INNER_ 8192

// ---------------- scratch (device globals; no allocations) ----------------
__device__ float g_h  [B_*SQ_*D_];
__device__ float g_kvmask[B_*SKV_];
__device__ bf16 g_qn_h [B_*SQ_*D_];   __device__ bf16 g_qn_l [B_*SQ_*D_];
__device__ bf16 g_ap_h [B_*SP_*DP_];  __device__ bf16 g_ap_l [B_*SP_*DP_];
__device__ bf16 g_as_h [B_*SS_*DS_];  __device__ bf16 g_as_l [B_*SS_*DS_];
__device__ bf16 g_am_h [B_*SM_*DM_];  __device__ bf16 g_am_l [B_*SM_*DM_];
__device__ bf16 g_qh   [B_*SQ_*D_];   __device__ bf16 g_ql   [B_*SQ_*D_];
__device__ bf16 g_kh   [B_*SKV_*D_];  __device__ bf16 g_kl   [B_*SKV_*D_];
__device__ bf16 g_vh   [B_*SKV_*D_];  __device__ bf16 g_vl   [B_*SKV_*D_];
__device__ bf16 g_cx_h [B_*SQ_*D_];   __device__ bf16 g_cx_l [B_*SQ_*D_];
__device__ bf16 g_ln_h [B_*SQ_*D_];   __device__ bf16 g_ln_l [B_*SQ_*D_];
__device__ bf16 g_ff_h [B_*SQ_*INNER_]; __device__ bf16 g_ff_l [B_*SQ_*INNER_];
__device__ bf16 g_Wq_h [D_*D_];       __device__ bf16 g_Wq_l [D_*D_];
__device__ bf16 g_Wkp_h[D_*DP_];      __device__ bf16 g_Wkp_l[D_*DP_];
__device__ bf16 g_Wvp_h[D_*DP_];      __device__ bf16 g_Wvp_l[D_*DP_];
__device__ bf16 g_Wks_h[D_*DS_];      __device__ bf16 g_Wks_l[D_*DS_];
__device__ bf16 g_Wvs_h[D_*DS_];      __device__ bf16 g_Wvs_l[D_*DS_];
__device__ bf16 g_Wkm_h[D_*DM_];      __device__ bf16 g_Wkm_l[D_*DM_];
__device__ bf16 g_Wvm_h[D_*DM_];      __device__ bf16 g_Wvm_l[D_*DM_];
__device__ bf16 g_Wo_h [D_*D_];       __device__ bf16 g_Wo_l [D_*D_];
__device__ bf16 g_W1_h [INNER_*D_];   __device__ bf16 g_W1_l [INNER_*D_];
__device__ bf16 g_W2_h [D_*INNER_];   __device__ bf16 g_W2_l [D_*INNER_];

// ---------------- helpers ----------------
__device__ __forceinline__ uint32_t s2u(const void* p) {
    uint32_t a;
    asm("{ .reg .u64 t; cvta.to.shared.u64 t, %1; cvt.u32.u64 %0, t; }" : "=r"(a) : "l"(p));
    return a;
}
__device__ __forceinline__ void cp16(uint32_t s, const void* g) {
    asm volatile("cp.async.cg.shared.global [%0], [%1], 16;" :: "r"(s), "l"(g) : "memory");
}
#define LDSM4(r0, r1, r2, r3, addr) \
    asm volatile("ldmatrix.sync.aligned.m8n8.x4.shared.b16 {%0,%1,%2,%3}, [%4];" \
                 : "=r"(r0), "=r"(r1), "=r"(r2), "=r"(r3) : "r"(addr))
#define LDSM4T(r0, r1, r2, r3, addr) \
    asm volatile("ldmatrix.sync.aligned.m8n8.x4.trans.shared.b16 {%0,%1,%2,%3}, [%4];" \
                 : "=r"(r0), "=r"(r1), "=r"(r2), "=r"(r3) : "r"(addr))
#define MMA16816(d, a, b) \
    asm volatile("mma.sync.aligned.m16n8k16.row.col.f32.bf16.bf16.f32 " \
                 "{%0,%1,%2,%3},{%4,%5,%6,%7},{%8,%9},{%0,%1,%2,%3};" \
                 : "+f"((d)[0]), "+f"((d)[1]), "+f"((d)[2]), "+f"((d)[3]) \
                 : "r"((a)[0]), "r"((a)[1]), "r"((a)[2]), "r"((a)[3]), \
                   "r"((b)[0]), "r"((b)[1]))

__device__ __forceinline__ float gelu_f(float x) {
    return 0.5f * x * (1.0f + erff(x * 0.70710678118654752f));
}
__device__ __forceinline__ void bsplit(float v, bf16* h, bf16* l) {
    bf16 hh = __float2bfloat16(v);
    *h = hh;
    *l = __float2bfloat16(v - __bfloat162float(hh));
}
__device__ __forceinline__ uint32_t pack2h(float a, float b) {
    __nv_bfloat162 t(__float2bfloat16(a), __float2bfloat16(b));
    return *(uint32_t*)&t;
}

// 64B-row swizzle for BK=32 tiles (4 chunks of 16B per row)
__device__ __forceinline__ uint32_t sw64(int r, int c) {
    return (uint32_t)(r * 64 + ((c ^ ((r >> 1) & 3)) << 4));
}

// ---------------- block reduce ----------------
__device__ __forceinline__ float blockReduceSum(float v) {
    __shared__ float sh[32];
    __syncthreads();
    int lane = threadIdx.x & 31, w = threadIdx.x >> 5;
    #pragma unroll
    for (int o = 16; o > 0; o >>= 1) v += __shfl_xor_sync(0xffffffffu, v, o);
    if (lane == 0) sh[w] = v;
    __syncthreads();
    float r = 0.f;
    if (threadIdx.x < (blockDim.x >> 5)) r = sh[threadIdx.x];
    if (w == 0) {
        #pragma unroll
        for (int o = 16; o > 0; o >>= 1) r += __shfl_xor_sync(0xffffffffu, r, o);
        if (lane == 0) sh[0] = r;
    }
    __syncthreads();
    return sh[0];
}

// ---------------- RMSNorm / LayerNorm / splits ----------------
__global__ __launch_bounds__(256) void rmsnorm_split(const float* __restrict__ x,
                                                     const float* __restrict__ w,
                                                     bf16* __restrict__ yh,
                                                     bf16* __restrict__ yl) {
    int row = blockIdx.x;
    const float* xr = x + (size_t)row * D_;
    float ss = 0.f;
    for (int t = threadIdx.x; t < D_; t += 256) { float v = xr[t]; ss += v * v; }
    ss = blockReduceSum(ss);
    float inv = rsqrtf(ss / (float)D_ + 1e-6f);
    for (int t = threadIdx.x; t < D_; t += 256) {
        float v = xr[t] * inv * w[t];
        bsplit(v, yh + (size_t)row * D_ + t, yl + (size_t)row * D_ + t);
    }
}

__global__ __launch_bounds__(256) void layernorm_split(const float* __restrict__ x,
                                                       const float* __restrict__ gg,
                                                       const float* __restrict__ bb,
                                                       bf16* __restrict__ yh,
                                                       bf16* __restrict__ yl) {
    int row = blockIdx.x;
    const float* xr = x + (size_t)row * D_;
    float s = 0.f;
    for (int t = threadIdx.x; t < D_; t += 256) s += xr[t];
    s = blockReduceSum(s);
    float mu = s / (float)D_;
    float vs = 0.f;
    for (int t = threadIdx.x; t < D_; t += 256) { float d = xr[t] - mu; vs += d * d; }
    vs = blockReduceSum(vs);
    float inv = rsqrtf(vs / (float)D_ + 1e-5f);
    for (int t = threadIdx.x; t < D_; t += 256) {
        float v = (xr[t] - mu) * inv * gg[t] + bb[t];
        bsplit(v, yh + (size_t)row * D_ + t, yl + (size_t)row * D_ + t);
    }
}

// vectorized elementwise split (n multiple of 4)
__global__ __launch_bounds__(256) void split_k(const float* __restrict__ x,
                                               bf16* __restrict__ h,
                                               bf16* __restrict__ l, int n4) {
    int i = blockIdx.x * 256 + threadIdx.x;
    if (i >= n4) return;
    float4 v = ((const float4*)x)[i];
    bf16 h0, l0, h1, l1, h2, l2, h3, l3;
    bsplit(v.x, &h0, &l0); bsplit(v.y, &h1, &l1);
    bsplit(v.z, &h2, &l2); bsplit(v.w, &h3, &l3);
    __nv_bfloat162 hv0(h0, h1), hv1(h2, h3), lv0(l0, l1), lv1(l2, l3);
    uint2 hu = make_uint2(*(uint32_t*)&hv0, *(uint32_t*)&hv1);
    uint2 lu = make_uint2(*(uint32_t*)&lv0, *(uint32_t*)&lv1);
    ((uint2*)h)[i] = hu;
    ((uint2*)l)[i] = lu;
}

__global__ __launch_bounds__(256) void maskcat_k(const float* __restrict__ pm,
                                                 const float* __restrict__ sm,
                                                 const float* __restrict__ mm,
                                                 float* __restrict__ out) {
    int i = blockIdx.x * 256 + threadIdx.x;
    if (i >= B_ * SKV_) return;
    int b = i / SKV_, s = i % SKV_;
    float v;
    if (s < SP_) v = pm[b * SP_ + s];
    else if (s < SP_ + SS_) v = sm[b * SS_ + s - SP_];
    else v = mm[b * SM_ + s - SP_ - SS_];
    out[i] = v;
}

// ---------------- weight transpose+split (vectorized): W[K,N] -> T[N,K] hi/lo ----------------
// 64x64 tile, float4 loads, 16B packed stores.
__global__ __launch_bounds__(256) void wsplit_T(const float* __restrict__ W,
                                                bf16* __restrict__ Th,
                                                bf16* __restrict__ Tl,
                                                int K, int N) {
    __shared__ float tile[64][65];
    const int tid = threadIdx.x;
    const int n0 = blockIdx.x * 64, k0 = blockIdx.y * 64;
    #pragma unroll
    for (int i = 0; i < 4; i++) {
        int idx = tid + 256 * i;          // 1024 float4 chunks
        int r = idx >> 4, c4 = (idx & 15) * 4;
        float4 v = *(const float4*)&W[(size_t)(k0 + r) * N + n0 + c4];
        tile[r][c4] = v.x; tile[r][c4 + 1] = v.y;
        tile[r][c4 + 2] = v.z; tile[r][c4 + 3] = v.w;
    }
    __syncthreads();
    #pragma unroll
    for (int i = 0; i < 2; i++) {
        int idx = tid + 256 * i;          // 512 stores: 64 n x 8 kc
        int n = idx >> 3, kc = (idx & 7) * 8;
        float v0 = tile[kc + 0][n], v1 = tile[kc + 1][n];
        float v2 = tile[kc + 2][n], v3 = tile[kc + 3][n];
        float v4 = tile[kc + 4][n], v5 = tile[kc + 5][n];
        float v6 = tile[kc + 6][n], v7 = tile[kc + 7][n];
        uint32_t h0 = pack2h(v0, v1), h1 = pack2h(v2, v3);
        uint32_t h2 = pack2h(v4, v5), h3 = pack2h(v6, v7);
        __nv_bfloat162 b0 = *(__nv_bfloat162*)&h0, b1 = *(__nv_bfloat162*)&h1;
        __nv_bfloat162 b2 = *(__nv_bfloat162*)&h2, b3 = *(__nv_bfloat162*)&h3;
        uint32_t l0 = pack2h(v0 - __bfloat162float(b0.x), v1 - __bfloat162float(b0.y));
        uint32_t l1 = pack2h(v2 - __bfloat162float(b1.x), v3 - __bfloat162float(b1.y));
        uint32_t l2 = pack2h(v4 - __bfloat162float(b2.x), v5 - __bfloat162float(b2.y));
        uint32_t l3 = pack2h(v6 - __bfloat162float(b3.x), v7 - __bfloat162float(b3.y));
        size_t o = (size_t)(n0 + n) * K + k0 + kc;
        *(uint4*)(Th + o) = make_uint4(h0, h1, h2, h3);
        *(uint4*)(Tl + o) = make_uint4(l0, l1, l2, l3);
    }
}

// ---------------- mma.sync GEMM: BM=128, BN=256, BK=32, warp tile 64x64 ----------------
// EPI 2: Cf = res + tanh(gate)*(acc + bias)
// EPI 3: Ch/Cl = bsplit(gelu(acc))
// EPI 4: Cf = res + tanh(gate)*acc
// EPI 5: Ch/Cl = bsplit((acc+bias)*scale), with row remap (K/V concat)
#define GB_M 128
#define GB_N 256
#define GB_K 32
#define STG_B 49152            // Ah 8K | Al 8K | Bh 16K | Bl 16K
#define GEMM_SMEM (2 * STG_B)

template <int EPI>
__global__ __launch_bounds__(256) void gemm_mma(
    const bf16* __restrict__ Ah, const bf16* __restrict__ Al,
    const bf16* __restrict__ Bh, const bf16* __restrict__ Bl,
    const float* __restrict__ bias, const float* __restrict__ res,
    const float* __restrict__ gate,
    float* __restrict__ Cf, bf16* __restrict__ Ch, bf16* __restrict__ Cl,
    int M, int N, int K, float scale, int oShift, int oStride, int oOff) {
    extern __shared__ __align__(1024) char smem[];
    uint32_t sb = s2u(smem);
    const int tid = threadIdx.x, wid = tid >> 5, lane = tid & 31;
    const int n0 = blockIdx.x * GB_N, m0 = blockIdx.y * GB_M;
    const int wm0 = (wid >> 2) * 64;      // 2 m-groups
    const int wn0 = (wid & 3) * 64;       // 4 n-groups

    auto stage_load = [&](int st, int k0) {
        uint32_t s0 = sb + st * STG_B;
        // A: 512 chunks per array (128 rows x 4 chunks)
        #pragma unroll
        for (int i = 0; i < 2; i++) {
            int ca = tid + 256 * i;
            int r = ca >> 2, c = ca & 3;
            uint32_t sw = sw64(r, c);
            size_t go = (size_t)(m0 + r) * K + k0 + c * 8;
            cp16(s0 + sw,        Ah + go);
            cp16(s0 + 8192 + sw, Al + go);
        }
        // B: 1024 chunks per array (256 rows x 4 chunks)
        #pragma unroll
        for (int i = 0; i < 4; i++) {
            int cb = tid + 256 * i;
            int r = cb >> 2, c = cb & 3;
            uint32_t sw = sw64(r, c);
            size_t go = (size_t)(n0 + r) * K + k0 + c * 8;
            cp16(s0 + 16384 + sw, Bh + go);
            cp16(s0 + 32768 + sw, Bl + go);
        }
        asm volatile("cp.async.commit_group;" ::: "memory");
    };

    float acc[4][8][4];
    #pragma unroll
    for (int i = 0; i < 4; i++)
        #pragma unroll
        for (int j = 0; j < 8; j++)
            #pragma unroll
            for (int c = 0; c < 4; c++) acc[i][j][c] = 0.f;

    const int nIter = K / GB_K;
    stage_load(0, 0);

    const int a_row = lane & 15;
    const int a_ch  = lane >> 4;
    const int b_row = (lane & 7) + ((lane >> 4) & 1) * 8;
    const int b_ch  = (lane >> 3) & 1;

    for (int it = 0; it < nIter; ++it) {
        if (it + 1 < nIter) stage_load((it + 1) & 1, (it + 1) * GB_K);
        if (it + 1 < nIter) {
            asm volatile("cp.async.wait_group 1;" ::: "memory");
        } else {
            asm volatile("cp.async.wait_group 0;" ::: "memory");
        }
        __syncthreads();

        uint32_t s0 = sb + (it & 1) * STG_B;
        uint32_t sAh = s0, sAl = s0 + 8192, sBh = s0 + 16384, sBl = s0 + 32768;

        #pragma unroll
        for (int ks = 0; ks < 2; ks++) {
            uint32_t ahi[4][4], alo[4][4], bhi[8][2], blo[8][2];
            #pragma unroll
            for (int i = 0; i < 4; i++) {
                uint32_t sw = sw64(wm0 + i * 16 + a_row, ks * 2 + a_ch);
                LDSM4(ahi[i][0], ahi[i][1], ahi[i][2], ahi[i][3], sAh + sw);
                LDSM4(alo[i][0], alo[i][1], alo[i][2], alo[i][3], sAl + sw);
            }
            #pragma unroll
            for (int jj = 0; jj < 4; jj++) {
                uint32_t sw = sw64(wn0 + jj * 16 + b_row, ks * 2 + b_ch);
                uint32_t r0, r1, r2, r3;
                LDSM4(r0, r1, r2, r3, sBh + sw);
                bhi[jj * 2][0] = r0; bhi[jj * 2][1] = r1;
                bhi[jj * 2 + 1][0] = r2; bhi[jj * 2 + 1][1] = r3;
                LDSM4(r0, r1, r2, r3, sBl + sw);
                blo[jj * 2][0] = r0; blo[jj * 2][1] = r1;
                blo[jj * 2 + 1][0] = r2; blo[jj * 2 + 1][1] = r3;
            }
            #pragma unroll
            for (int i = 0; i < 4; i++)
                #pragma unroll
                for (int j = 0; j < 8; j++) {
                    MMA16816(acc[i][j], ahi[i], bhi[j]);
                    MMA16816(acc[i][j], ahi[i], blo[j]);
                    MMA16816(acc[i][j], alo[i], bhi[j]);
                }
        }
        __syncthreads();
    }

    float gt = 0.f;
    if (EPI == 2 || EPI == 4) gt = tanhf(gate[0]);
    const int cr = lane >> 2;
    const int cc = (lane & 3) * 2;

    #pragma unroll
    for (int i = 0; i < 4; i++) {
        #pragma unroll
        for (int j = 0; j < 8; j++) {
            int gcol = n0 + wn0 + j * 8 + cc;
            #pragma unroll
            for (int half = 0; half < 2; half++) {
                int grow = m0 + wm0 + i * 16 + cr + half * 8;
                float v0 = acc[i][j][half * 2 + 0];
                float v1 = acc[i][j][half * 2 + 1];
                size_t o = (size_t)grow * N + gcol;
                if (EPI == 2) {
                    float2 rr = *(const float2*)(res + o);
                    *(float2*)(Cf + o) = make_float2(rr.x + gt * (v0 + bias[gcol]),
                                                     rr.y + gt * (v1 + bias[gcol + 1]));
                } else if (EPI == 3) {
                    float a0 = gelu_f(v0), a1 = gelu_f(v1);
                    bf16 h0, l0, h1, l1;
                    bsplit(a0, &h0, &l0);
                    bsplit(a1, &h1, &l1);
                    *(__nv_bfloat162*)(Ch + o) = __nv_bfloat162(h0, h1);
                    *(__nv_bfloat162*)(Cl + o) = __nv_bfloat162(l0, l1);
                } else if (EPI == 4) {
                    float2 rr = *(const float2*)(res + o);
                    *(float2*)(Cf + o) = make_float2(rr.x + gt * v0, rr.y + gt * v1);
                } else {  // EPI 5
                    int ib = grow >> oShift;
                    int ir = grow & ((1 << oShift) - 1);
                    size_t oo = ((size_t)ib * oStride + oOff + ir) * N + gcol;
                    float a0 = (v0 + bias[gcol]) * scale;
                    float a1 = (v1 + bias[gcol + 1]) * scale;
                    bf16 h0, l0, h1, l1;
                    bsplit(a0, &h0, &l0);
                    bsplit(a1, &h1, &l1);
                    *(__nv_bfloat162*)(Ch + oo) = __nv_bfloat162(h0, h1);
                    *(__nv_bfloat162*)(Cl + oo) = __nv_bfloat162(l0, l1);
                }
            }
        }
    }
}

// ---------------- register-resident FA2 attention (unchanged from R5) ----------------
#define AQ_H 0u
#define AQ_L 32768u
#define AKV  65536u
#define AST  65792u
#define ATTN_SMEM (65536 + 2 * 65792)

__global__ __launch_bounds__(256) void attn_fa2(
    const bf16* __restrict__ Qh, const bf16* __restrict__ Ql,
    const bf16* __restrict__ Kh, const bf16* __restrict__ Kl,
    const bf16* __restrict__ Vh, const bf16* __restrict__ Vl,
    const float* __restrict__ qmask, const float* __restrict__ kvmask,
    bf16* __restrict__ Oh, bf16* __restrict__ Ol) {
    extern __shared__ __align__(1024) char smem[];
    uint32_t sb = s2u(smem);

    const int qt = blockIdx.x, h = blockIdx.y, b = blockIdx.z;
    const int q0 = qt * 128;
    const int tid = threadIdx.x, wid = tid >> 5, lane = tid & 31;
    const int wrow = wid * 16;
    const int a_row = lane & 15, a_ch = lane >> 4;
    const int b_row = (lane & 7) + ((lane >> 4) & 1) * 8;
    const int b_ch  = (lane >> 3) & 1;
    const int cr = lane >> 2, cc = (lane & 3) * 2;

    auto kv_load = [&](int st, int t) {
        uint32_t s0 = sb + AKV + st * AST;
        int kv0 = t * 64;
        #pragma unroll
        for (int i = 0; i < 4; i++) {
            int idx = tid + 256 * i;
            int r = idx >> 4, c16 = idx & 15;
            uint32_t off = r * 256 + (((uint32_t)(c16 ^ (r & 7))) << 4);
            size_t go = (size_t)(b * SKV_ + kv0 + r) * D_ + h * HD_ + c16 * 8;
            cp16(s0 + off,          Kh + go);
            cp16(s0 + 16384 + off,  Kl + go);
            cp16(s0 + 32768 + off,  Vh + go);
            cp16(s0 + 49152 + off,  Vl + go);
        }
        if (tid < 16)
            cp16(s0 + 65536 + tid * 16, kvmask + b * SKV_ + t * 64 + tid * 4);
        asm volatile("cp.async.commit_group;" ::: "memory");
    };

    #pragma unroll
    for (int i = 0; i < 8; i++) {
        int idx = tid + 256 * i;
        int r = idx >> 4, c16 = idx & 15;
        uint32_t off = r * 256 + (((uint32_t)(c16 ^ (r & 7))) << 4);
        size_t go = (size_t)(b * SQ_ + q0 + r) * D_ + h * HD_ + c16 * 8;
        cp16(sb + AQ_H + off, Qh + go);
        cp16(sb + AQ_L + off, Ql + go);
    }
    asm volatile("cp.async.commit_group;" ::: "memory");
    kv_load(0, 0);
    asm volatile("cp.async.wait_group 0;" ::: "memory");
    __syncthreads();

    uint32_t qhf[8][4], qlf[8][4];
    #pragma unroll
    for (int ks = 0; ks < 8; ks++) {
        int row = wrow + a_row;
        int c16 = ks * 2 + a_ch;
        uint32_t off = row * 256 + (((uint32_t)(c16 ^ (row & 7))) << 4);
        LDSM4(qhf[ks][0], qhf[ks][1], qhf[ks][2], qhf[ks][3], sb + AQ_H + off);
        LDSM4(qlf[ks][0], qlf[ks][1], qlf[ks][2], qlf[ks][3], sb + AQ_L + off);
    }

    const float qm0 = qmask[b * SQ_ + q0 + wrow + cr];
    const float qm8 = qmask[b * SQ_ + q0 + wrow + cr + 8];

    float m0 = -1e30f, m8 = -1e30f, l0 = 0.f, l8 = 0.f;
    float oacc[16][4];
    #pragma unroll
    for (int j = 0; j < 16; j++)
        #pragma unroll
        for (int c = 0; c < 4; c++) oacc[j][c] = 0.f;

    const int T = SKV_ / 64;
    for (int t = 0; t < T; ++t) {
        if (t + 1 < T) kv_load((t + 1) & 1, t + 1);
        if (t + 1 < T) {
            asm volatile("cp.async.wait_group 1;" ::: "memory");
        } else {
            asm volatile("cp.async.wait_group 0;" ::: "memory");
        }
        __syncthreads();

        uint32_t s0 = sb + AKV + (t & 1) * AST;
        uint32_t sKh = s0, sKl = s0 + 16384, sVh = s0 + 32768, sVl = s0 + 49152;
        const float* msk = (const float*)(smem + AKV + (t & 1) * AST + 65536);

        float sacc[8][4];
        #pragma unroll
        for (int j = 0; j < 8; j++)
            #pragma unroll
            for (int c = 0; c < 4; c++) sacc[j][c] = 0.f;

        #pragma unroll
        for (int ks = 0; ks < 8; ks++) {
            #pragma unroll
            for (int jj = 0; jj < 4; jj++) {
                int row = jj * 16 + b_row;
                int c16 = ks * 2 + b_ch;
                uint32_t off = row * 256 + (((uint32_t)(c16 ^ (row & 7))) << 4);
                uint32_t k0, k1, k2, k3, e0, e1, e2, e3;
                LDSM4(k0, k1, k2, k3, sKh + off);
                LDSM4(e0, e1, e2, e3, sKl + off);
                uint32_t bh0[2] = {k0, k1}, bh1[2] = {k2, k3};
                uint32_t bl0[2] = {e0, e1}, bl1[2] = {e2, e3};
                MMA16816(sacc[jj * 2],     qhf[ks], bh0);
                MMA16816(sacc[jj * 2],     qhf[ks], bl0);
                MMA16816(sacc[jj * 2],     qlf[ks], bh0);
                MMA16816(sacc[jj * 2 + 1], qhf[ks], bh1);
                MMA16816(sacc[jj * 2 + 1], qhf[ks], bl1);
                MMA16816(sacc[jj * 2 + 1], qlf[ks], bh1);
            }
        }

        #pragma unroll
        for (int j = 0; j < 8; j++) {
            float2 km = *(const float2*)&msk[j * 8 + cc];
            if (qm0 == 0.f || km.x == 0.f) sacc[j][0] = -3.0e38f;
            if (qm0 == 0.f || km.y == 0.f) sacc[j][1] = -3.0e38f;
            if (qm8 == 0.f || km.x == 0.f) sacc[j][2] = -3.0e38f;
            if (qm8 == 0.f || km.y == 0.f) sacc[j][3] = -3.0e38f;
        }
        float mx0 = sacc[0][0], mx8 = sacc[0][2];
        #pragma unroll
        for (int j = 0; j < 8; j++) {
            mx0 = fmaxf(mx0, fmaxf(sacc[j][0], sacc[j][1]));
            mx8 = fmaxf(mx8, fmaxf(sacc[j][2], sacc[j][3]));
        }
        mx0 = fmaxf(mx0, __shfl_xor_sync(0xffffffffu, mx0, 1));
        mx0 = fmaxf(mx0, __shfl_xor_sync(0xffffffffu, mx0, 2));
        mx8 = fmaxf(mx8, __shfl_xor_sync(0xffffffffu, mx8, 1));
        mx8 = fmaxf(mx8, __shfl_xor_sync(0xffffffffu, mx8, 2));
        float m0n = fmaxf(m0, mx0), m8n = fmaxf(m8, mx8);
        float al0 = __expf(m0 - m0n), al8 = __expf(m8 - m8n);
        float sum0 = 0.f, sum8 = 0.f;
        #pragma unroll
        for (int j = 0; j < 8; j++) {
            sacc[j][0] = __expf(sacc[j][0] - m0n);
            sacc[j][1] = __expf(sacc[j][1] - m0n);
            sacc[j][2] = __expf(sacc[j][2] - m8n);
            sacc[j][3] = __expf(sacc[j][3] - m8n);
            sum0 += sacc[j][0] + sacc[j][1];
            sum8 += sacc[j][2] + sacc[j][3];
        }
        sum0 += __shfl_xor_sync(0xffffffffu, sum0, 1);
        sum0 += __shfl_xor_sync(0xffffffffu, sum0, 2);
        sum8 += __shfl_xor_sync(0xffffffffu, sum8, 1);
        sum8 += __shfl_xor_sync(0xffffffffu, sum8, 2);
        l0 = l0 * al0 + sum0; l8 = l8 * al8 + sum8;
        m0 = m0n; m8 = m8n;

        #pragma unroll
        for (int j = 0; j < 16; j++) {
            oacc[j][0] *= al0; oacc[j][1] *= al0;
            oacc[j][2] *= al8; oacc[j][3] *= al8;
        }

        #pragma unroll
        for (int ks = 0; ks < 4; ks++) {
            uint32_t ph[4], pl[4];
            {
                float v00 = sacc[ks * 2][0],     v01 = sacc[ks * 2][1];
                float v02 = sacc[ks * 2][2],     v03 = sacc[ks * 2][3];
                float v10 = sacc[ks * 2 + 1][0], v11 = sacc[ks * 2 + 1][1];
                float v12 = sacc[ks * 2 + 1][2], v13 = sacc[ks * 2 + 1][3];
                ph[0] = pack2h(v00, v01); ph[1] = pack2h(v02, v03);
                ph[2] = pack2h(v10, v11); ph[3] = pack2h(v12, v13);
                __nv_bfloat162 h0 = *(__nv_bfloat162*)&ph[0];
                __nv_bfloat162 h1 = *(__nv_bfloat162*)&ph[1];
                __nv_bfloat162 h2 = *(__nv_bfloat162*)&ph[2];
                __nv_bfloat162 h3 = *(__nv_bfloat162*)&ph[3];
                pl[0] = pack2h(v00 - __bfloat162float(h0.x), v01 - __bfloat162float(h0.y));
                pl[1] = pack2h(v02 - __bfloat162float(h1.x), v03 - __bfloat162float(h1.y));
                pl[2] = pack2h(v10 - __bfloat162float(h2.x), v11 - __bfloat162float(h2.y));
                pl[3] = pack2h(v12 - __bfloat162float(h3.x), v13 - __bfloat162float(h3.y));
            }
            #pragma unroll
            for (int ng = 0; ng < 8; ng++) {
                int k_row = ks * 16 + (lane & 15);
                int c16v = ng * 2 + (lane >> 4);
                uint32_t off = k_row * 256 + (((uint32_t)(c16v ^ (k_row & 7))) << 4);
                uint32_t v0, v1, v2, v3, w0, w1, w2, w3;
                LDSM4T(v0, v1, v2, v3, sVh + off);
                LDSM4T(w0, w1, w2, w3, sVl + off);
                uint32_t bh0[2] = {v0, v1}, bh1[2] = {v2, v3};
                uint32_t bl0[2] = {w0, w1}, bl1[2] = {w2, w3};
                MMA16816(oacc[ng * 2],     ph, bh0);
                MMA16816(oacc[ng * 2],     ph, bl0);
                MMA16816(oacc[ng * 2],     pl, bh0);
                MMA16816(oacc[ng * 2 + 1], ph, bh1);
                MMA16816(oacc[ng * 2 + 1], ph, bl1);
                MMA16816(oacc[ng * 2 + 1], pl, bh1);
            }
        }
        __syncthreads();
    }

    float inv0 = 1.0f / l0, inv8 = 1.0f / l8;
    #pragma unroll
    for (int j = 0; j < 16; j++) {
        int gcol = h * HD_ + j * 8 + cc;
        int r0 = q0 + wrow + cr;
        size_t o0 = (size_t)(b * SQ_ + r0) * D_ + gcol;
        size_t o8 = o0 + (size_t)8 * D_;
        float a0 = oacc[j][0] * inv0, a1 = oacc[j][1] * inv0;
        float a2 = oacc[j][2] * inv8, a3 = oacc[j][3] * inv8;
        bf16 h0, l0b, h1, l1b;
        bsplit(a0, &h0, &l0b); bsplit(a1, &h1, &l1b);
        *(__nv_bfloat162*)(Oh + o0) = __nv_bfloat162(h0, h1);
        *(__nv_bfloat162*)(Ol + o0) = __nv_bfloat162(l0b, l1b);
        bsplit(a2, &h0, &l0b); bsplit(a3, &h1, &l1b);
        *(__nv_bfloat162*)(Oh + o8) = __nv_bfloat162(h0, h1);
        *(__nv_bfloat162*)(Ol + o8) = __nv_bfloat162(l0b, l1b);
    }
}

// ---------------- launcher ----------------
extern "C" void kernel_launch(void* const* d_in, const int* in_sizes, int n_in,
                              void* d_out, int out_size) {
    const float* x     = (const float*)d_in[0];
    const float* pkv   = (const float*)d_in[1];
    const float* skv   = (const float*)d_in[2];
    const float* mkv   = (const float*)d_in[3];
    const float* qmask = (const float*)d_in[4];
    const float* pmask = (const float*)d_in[5];
    const float* smask = (const float*)d_in[6];
    const float* mmask = (const float*)d_in[7];
    const float* rmsw  = (const float*)d_in[8];
    const float* Wq  = (const float*)d_in[9];   const float* bq  = (const float*)d_in[10];
    const float* Wkp = (const float*)d_in[11];  const float* bkp = (const float*)d_in[12];
    const float* Wvp = (const float*)d_in[13];  const float* bvp = (const float*)d_in[14];
    const float* Wks = (const float*)d_in[15];  const float* bks = (const float*)d_in[16];
    const float* Wvs = (const float*)d_in[17];  const float* bvs = (const float*)d_in[18];
    const float* Wkm = (const float*)d_in[19];  const float* bkm = (const float*)d_in[20];
    const float* Wvm = (const float*)d_in[21];  const float* bvm = (const float*)d_in[22];
    const float* Wo  = (const float*)d_in[23];  const float* bo  = (const float*)d_in[24];
    const float* lng = (const float*)d_in[25];  const float* lnb = (const float*)d_in[26];
    const float* W1  = (const float*)d_in[27];  const float* W2  = (const float*)d_in[28];
    const float* ga  = (const float*)d_in[29];  const float* gf  = (const float*)d_in[30];
    float* out = (float*)d_out;

    float *hh, *kvm;
    cudaGetSymbolAddress((void**)&hh,  g_h);
    cudaGetSymbolAddress((void**)&kvm, g_kvmask);

    bf16 *qnh,*qnl,*aph,*apl,*ash,*asl,*amh,*aml;
    bf16 *qh,*ql,*kh,*kl,*vh,*vl,*cxh,*cxl,*lnh,*lnl,*ffh,*ffl;
    cudaGetSymbolAddress((void**)&qnh, g_qn_h);  cudaGetSymbolAddress((void**)&qnl, g_qn_l);
    cudaGetSymbolAddress((void**)&aph, g_ap_h);  cudaGetSymbolAddress((void**)&apl, g_ap_l);
    cudaGetSymbolAddress((void**)&ash, g_as_h);  cudaGetSymbolAddress((void**)&asl, g_as_l);
    cudaGetSymbolAddress((void**)&amh, g_am_h);  cudaGetSymbolAddress((void**)&aml, g_am_l);
    cudaGetSymbolAddress((void**)&qh,  g_qh);    cudaGetSymbolAddress((void**)&ql,  g_ql);
    cudaGetSymbolAddress((void**)&kh,  g_kh);    cudaGetSymbolAddress((void**)&kl,  g_kl);
    cudaGetSymbolAddress((void**)&vh,  g_vh);    cudaGetSymbolAddress((void**)&vl,  g_vl);
    cudaGetSymbolAddress((void**)&cxh, g_cx_h);  cudaGetSymbolAddress((void**)&cxl, g_cx_l);
    cudaGetSymbolAddress((void**)&lnh, g_ln_h);  cudaGetSymbolAddress((void**)&lnl, g_ln_l);
    cudaGetSymbolAddress((void**)&ffh, g_ff_h);  cudaGetSymbolAddress((void**)&ffl, g_ff_l);

    bf16 *tWqh,*tWql,*tWkph,*tWkpl,*tWvph,*tWvpl,*tWksh,*tWksl,*tWvsh,*tWvsl;
    bf16 *tWkmh,*tWkml,*tWvmh,*tWvml,*tWoh,*tWol,*tW1h,*tW1l,*tW2h,*tW2l;
    cudaGetSymbolAddress((void**)&tWqh,  g_Wq_h);   cudaGetSymbolAddress((void**)&tWql,  g_Wq_l);
    cudaGetSymbolAddress((void**)&tWkph, g_Wkp_h);  cudaGetSymbolAddress((void**)&tWkpl, g_Wkp_l);
    cudaGetSymbolAddress((void**)&tWvph, g_Wvp_h);  cudaGetSymbolAddress((void**)&tWvpl, g_Wvp_l);
    cudaGetSymbolAddress((void**)&tWksh, g_Wks_h);  cudaGetSymbolAddress((void**)&tWksl, g_Wks_l);
    cudaGetSymbolAddress((void**)&tWvsh, g_Wvs_h);  cudaGetSymbolAddress((void**)&tWvsl, g_Wvs_l);
    cudaGetSymbolAddress((void**)&tWkmh, g_Wkm_h);  cudaGetSymbolAddress((void**)&tWkml, g_Wkm_l);
    cudaGetSymbolAddress((void**)&tWvmh, g_Wvm_h);  cudaGetSymbolAddress((void**)&tWvml, g_Wvm_l);
    cudaGetSymbolAddress((void**)&tWoh,  g_Wo_h);   cudaGetSymbolAddress((void**)&tWol,  g_Wo_l);
    cudaGetSymbolAddress((void**)&tW1h,  g_W1_h);   cudaGetSymbolAddress((void**)&tW1l,  g_W1_l);
    cudaGetSymbolAddress((void**)&tW2h,  g_W2_h);   cudaGetSymbolAddress((void**)&tW2l,  g_W2_l);

    cudaFuncSetAttribute(gemm_mma<2>, cudaFuncAttributeMaxDynamicSharedMemorySize, GEMM_SMEM);
    cudaFuncSetAttribute(gemm_mma<3>, cudaFuncAttributeMaxDynamicSharedMemorySize, GEMM_SMEM);
    cudaFuncSetAttribute(gemm_mma<4>, cudaFuncAttributeMaxDynamicSharedMemorySize, GEMM_SMEM);
    cudaFuncSetAttribute(gemm_mma<5>, cudaFuncAttributeMaxDynamicSharedMemorySize, GEMM_SMEM);
    cudaFuncSetAttribute(attn_fa2, cudaFuncAttributeMaxDynamicSharedMemorySize, ATTN_SMEM);

    // weight transpose+split (64x64 tiles)
    wsplit_T<<<dim3(D_ / 64,     D_ / 64),     256>>>(Wq,  tWqh,  tWql,  D_,     D_);
    wsplit_T<<<dim3(D_ / 64,     DP_ / 64),    256>>>(Wkp, tWkph, tWkpl, DP_,    D_);
    wsplit_T<<<dim3(D_ / 64,     DP_ / 64),    256>>>(Wvp, tWvph, tWvpl, DP_,    D_);
    wsplit_T<<<dim3(D_ / 64,     DS_ / 64),    256>>>(Wks, tWksh, tWksl, DS_,    D_);
    wsplit_T<<<dim3(D_ / 64,     DS_ / 64),    256>>>(Wvs, tWvsh, tWvsl, DS_,    D_);
    wsplit_T<<<dim3(D_ / 64,     DM_ / 64),    256>>>(Wkm, tWkmh, tWkml, DM_,    D_);
    wsplit_T<<<dim3(D_ / 64,     DM_ / 64),    256>>>(Wvm, tWvmh, tWvml, DM_,    D_);
    wsplit_T<<<dim3(D_ / 64,     D_ / 64),     256>>>(Wo,  tWoh,  tWol,  D_,     D_);
    wsplit_T<<<dim3(INNER_ / 64, D_ / 64),     256>>>(W1,  tW1h,  tW1l,  D_,     INNER_);
    wsplit_T<<<dim3(D_ / 64,     INNER_ / 64), 256>>>(W2,  tW2h,  tW2l,  INNER_, D_);

    // activation splits + mask concat
    rmsnorm_split<<<B_ * SQ_, 256>>>(x, rmsw, qnh, qnl);
    split_k<<<(B_ * SP_ * DP_ / 4 + 255) / 256, 256>>>(pkv, aph, apl, B_ * SP_ * DP_ / 4);
    split_k<<<(B_ * SS_ * DS_ / 4 + 255) / 256, 256>>>(skv, ash, asl, B_ * SS_ * DS_ / 4);
    split_k<<<(B_ * SM_ * DM_ / 4 + 255) / 256, 256>>>(mkv, amh, aml, B_ * SM_ * DM_ / 4);
    maskcat_k<<<(B_ * SKV_ + 255) / 256, 256>>>(pmask, smask, mmask, kvm);

    // projections -> bf16 hi/lo (EPI 5)
    gemm_mma<5><<<dim3(8, 16), 256, GEMM_SMEM>>>(qnh, qnl, tWqh, tWql, bq, nullptr, nullptr,
        nullptr, qh, ql, 2048, 2048, 2048, 0.25f, 10, 1024, 0);
    gemm_mma<5><<<dim3(8, 16), 256, GEMM_SMEM>>>(aph, apl, tWkph, tWkpl, bkp, nullptr, nullptr,
        nullptr, kh, kl, 2048, 2048, 1280, 1.f, 10, SKV_, 0);
    gemm_mma<5><<<dim3(8, 16), 256, GEMM_SMEM>>>(aph, apl, tWvph, tWvpl, bvp, nullptr, nullptr,
        nullptr, vh, vl, 2048, 2048, 1280, 1.f, 10, SKV_, 0);
    gemm_mma<5><<<dim3(8, 16), 256, GEMM_SMEM>>>(ash, asl, tWksh, tWksl, bks, nullptr, nullptr,
        nullptr, kh, kl, 2048, 2048, 1024, 1.f, 10, SKV_, SP_);
    gemm_mma<5><<<dim3(8, 16), 256, GEMM_SMEM>>>(ash, asl, tWvsh, tWvsl, bvs, nullptr, nullptr,
        nullptr, vh, vl, 2048, 2048, 1024, 1.f, 10, SKV_, SP_);
    gemm_mma<5><<<dim3(8, 8), 256, GEMM_SMEM>>>(amh, aml, tWkmh, tWkml, bkm, nullptr, nullptr,
        nullptr, kh, kl, 1024, 2048, 768, 1.f, 9, SKV_, SP_ + SS_);
    gemm_mma<5><<<dim3(8, 8), 256, GEMM_SMEM>>>(amh, aml, tWvmh, tWvml, bvm, nullptr, nullptr,
        nullptr, vh, vl, 1024, 2048, 768, 1.f, 9, SKV_, SP_ + SS_);

    // attention
    attn_fa2<<<dim3(8, 16, 2), 256, ATTN_SMEM>>>(qh, ql, kh, kl, vh, vl,
                                                 qmask, kvm, cxh, cxl);

    // h = x + tanh(ga)*(ctx@Wo + bo)
    gemm_mma<2><<<dim3(8, 16), 256, GEMM_SMEM>>>(cxh, cxl, tWoh, tWol, bo, x, ga,
        hh, nullptr, nullptr, 2048, 2048, 2048, 1.f, 0, 0, 0);

    // LayerNorm
    layernorm_split<<<B_ * SQ_, 256>>>(hh, lng, lnb, lnh, lnl);

    // FFW
    gemm_mma<3><<<dim3(32, 16), 256, GEMM_SMEM>>>(lnh, lnl, tW1h, tW1l, nullptr, nullptr, nullptr,
        nullptr, ffh, ffl, 2048, INNER_, 2048, 1.f, 0, 0, 0);
    gemm_mma<4><<<dim3(8, 16), 256, GEMM_SMEM>>>(ffh, ffl, tW2h, tW2l, nullptr, hh, gf,
        out, nullptr, nullptr, 2048, 2048, INNER_, 1.f, 0, 0, 0);
}

// round 7
// speedup vs baseline: 1.1368x; 1.1368x over previous
#include <cuda_runtime.h>
#include <cuda_bf16.h>
#include <math.h>
#include <stdint.h>

typedef __nv_bfloat16 bf16;

// ---------------- problem dims ----------------
#define B_    2
#define SQ_   1024
#define D_    2048
#define H_    16
#define HD_   128
#define SP_   1024
#define SS_   1024
#define SM_   512
#define SKV_  2560
#define DP_   1280
#define DS_   1024
#define DM_   768
#define INNER_ 8192

// ---------------- scratch (device globals; no allocations) ----------------
__device__ float g_h  [B_*SQ_*D_];
__device__ float g_kvmask[B_*SKV_];
__device__ bf16 g_qn_h [B_*SQ_*D_];   __device__ bf16 g_qn_l [B_*SQ_*D_];
__device__ bf16 g_ap_h [B_*SP_*DP_];  __device__ bf16 g_ap_l [B_*SP_*DP_];
__device__ bf16 g_as_h [B_*SS_*DS_];  __device__ bf16 g_as_l [B_*SS_*DS_];
__device__ bf16 g_am_h [B_*SM_*DM_];  __device__ bf16 g_am_l [B_*SM_*DM_];
__device__ bf16 g_qh   [B_*SQ_*D_];   __device__ bf16 g_ql   [B_*SQ_*D_];
__device__ bf16 g_kh   [B_*SKV_*D_];  __device__ bf16 g_kl   [B_*SKV_*D_];
__device__ bf16 g_vh   [B_*SKV_*D_];  __device__ bf16 g_vl   [B_*SKV_*D_];
__device__ bf16 g_cx_h [B_*SQ_*D_];   __device__ bf16 g_cx_l [B_*SQ_*D_];
__device__ bf16 g_ln_h [B_*SQ_*D_];   __device__ bf16 g_ln_l [B_*SQ_*D_];
__device__ bf16 g_ff_h [B_*SQ_*INNER_]; __device__ bf16 g_ff_l [B_*SQ_*INNER_];
__device__ bf16 g_Wq_h [D_*D_];       __device__ bf16 g_Wq_l [D_*D_];
__device__ bf16 g_Wkp_h[D_*DP_];      __device__ bf16 g_Wkp_l[D_*DP_];
__device__ bf16 g_Wvp_h[D_*DP_];      __device__ bf16 g_Wvp_l[D_*DP_];
__device__ bf16 g_Wks_h[D_*DS_];      __device__ bf16 g_Wks_l[D_*DS_];
__device__ bf16 g_Wvs_h[D_*DS_];      __device__ bf16 g_Wvs_l[D_*DS_];
__device__ bf16 g_Wkm_h[D_*DM_];      __device__ bf16 g_Wkm_l[D_*DM_];
__device__ bf16 g_Wvm_h[D_*DM_];      __device__ bf16 g_Wvm_l[D_*DM_];
__device__ bf16 g_Wo_h [D_*D_];       __device__ bf16 g_Wo_l [D_*D_];
__device__ bf16 g_W1_h [INNER_*D_];   __device__ bf16 g_W1_l [INNER_*D_];
__device__ bf16 g_W2_h [D_*INNER_];   __device__ bf16 g_W2_l [D_*INNER_];

// ---------------- helpers ----------------
__device__ __forceinline__ uint32_t s2u(const void* p) {
    uint32_t a;
    asm("{ .reg .u64 t; cvta.to.shared.u64 t, %1; cvt.u32.u64 %0, t; }" : "=r"(a) : "l"(p));
    return a;
}
__device__ __forceinline__ void cp16(uint32_t s, const void* g) {
    asm volatile("cp.async.cg.shared.global [%0], [%1], 16;" :: "r"(s), "l"(g) : "memory");
}
#define LDSM4(r0, r1, r2, r3, addr) \
    asm volatile("ldmatrix.sync.aligned.m8n8.x4.shared.b16 {%0,%1,%2,%3}, [%4];" \
                 : "=r"(r0), "=r"(r1), "=r"(r2), "=r"(r3) : "r"(addr))
#define LDSM4T(r0, r1, r2, r3, addr) \
    asm volatile("ldmatrix.sync.aligned.m8n8.x4.trans.shared.b16 {%0,%1,%2,%3}, [%4];" \
                 : "=r"(r0), "=r"(r1), "=r"(r2), "=r"(r3) : "r"(addr))
#define MMA16816(d, a, b) \
    asm volatile("mma.sync.aligned.m16n8k16.row.col.f32.bf16.bf16.f32 " \
                 "{%0,%1,%2,%3},{%4,%5,%6,%7},{%8,%9},{%0,%1,%2,%3};" \
                 : "+f"((d)[0]), "+f"((d)[1]), "+f"((d)[2]), "+f"((d)[3]) \
                 : "r"((a)[0]), "r"((a)[1]), "r"((a)[2]), "r"((a)[3]), \
                   "r"((b)[0]), "r"((b)[1]))

__device__ __forceinline__ float gelu_f(float x) {
    return 0.5f * x * (1.0f + erff(x * 0.70710678118654752f));
}
__device__ __forceinline__ void bsplit(float v, bf16* h, bf16* l) {
    bf16 hh = __float2bfloat16(v);
    *h = hh;
    *l = __float2bfloat16(v - __bfloat162float(hh));
}
__device__ __forceinline__ uint32_t pack2h(float a, float b) {
    __nv_bfloat162 t(__float2bfloat16(a), __float2bfloat16(b));
    return *(uint32_t*)&t;
}
// split float4 -> packed hi (uint2) + lo (uint2)
__device__ __forceinline__ void split4(float4 v, uint2* hu, uint2* lu) {
    uint32_t h0 = pack2h(v.x, v.y), h1 = pack2h(v.z, v.w);
    __nv_bfloat162 b0 = *(__nv_bfloat162*)&h0, b1 = *(__nv_bfloat162*)&h1;
    uint32_t l0 = pack2h(v.x - __bfloat162float(b0.x), v.y - __bfloat162float(b0.y));
    uint32_t l1 = pack2h(v.z - __bfloat162float(b1.x), v.w - __bfloat162float(b1.y));
    *hu = make_uint2(h0, h1);
    *lu = make_uint2(l0, l1);
}

// ---------------- block reduce ----------------
__device__ __forceinline__ float blockReduceSum(float v) {
    __shared__ float sh[32];
    __syncthreads();
    int lane = threadIdx.x & 31, w = threadIdx.x >> 5;
    #pragma unroll
    for (int o = 16; o > 0; o >>= 1) v += __shfl_xor_sync(0xffffffffu, v, o);
    if (lane == 0) sh[w] = v;
    __syncthreads();
    float r = 0.f;
    if (threadIdx.x < (blockDim.x >> 5)) r = sh[threadIdx.x];
    if (w == 0) {
        #pragma unroll
        for (int o = 16; o > 0; o >>= 1) r += __shfl_xor_sync(0xffffffffu, r, o);
        if (lane == 0) sh[0] = r;
    }
    __syncthreads();
    return sh[0];
}

// ---------------- RMSNorm -> bf16 split (vectorized) ----------------
__global__ __launch_bounds__(256) void rmsnorm_split(const float* __restrict__ x,
                                                     const float* __restrict__ w,
                                                     bf16* __restrict__ yh,
                                                     bf16* __restrict__ yl) {
    int row = blockIdx.x;
    const float4* xr = (const float4*)(x + (size_t)row * D_);
    const float4* wr = (const float4*)w;
    float ss = 0.f;
    float4 xv[2];
    #pragma unroll
    for (int i = 0; i < 2; i++) {
        xv[i] = xr[threadIdx.x + 256 * i];
        ss += xv[i].x * xv[i].x + xv[i].y * xv[i].y + xv[i].z * xv[i].z + xv[i].w * xv[i].w;
    }
    ss = blockReduceSum(ss);
    float inv = rsqrtf(ss / (float)D_ + 1e-6f);
    uint2* yh2 = (uint2*)(yh + (size_t)row * D_);
    uint2* yl2 = (uint2*)(yl + (size_t)row * D_);
    #pragma unroll
    for (int i = 0; i < 2; i++) {
        int t = threadIdx.x + 256 * i;
        float4 wv = wr[t];
        float4 v = make_float4(xv[i].x * inv * wv.x, xv[i].y * inv * wv.y,
                               xv[i].z * inv * wv.z, xv[i].w * inv * wv.w);
        uint2 hu, lu;
        split4(v, &hu, &lu);
        yh2[t] = hu; yl2[t] = lu;
    }
}

// ---------------- LayerNorm -> bf16 split (vectorized) ----------------
__global__ __launch_bounds__(256) void layernorm_split(const float* __restrict__ x,
                                                       const float* __restrict__ gg,
                                                       const float* __restrict__ bb,
                                                       bf16* __restrict__ yh,
                                                       bf16* __restrict__ yl) {
    int row = blockIdx.x;
    const float4* xr = (const float4*)(x + (size_t)row * D_);
    float4 xv[2];
    float s = 0.f;
    #pragma unroll
    for (int i = 0; i < 2; i++) {
        xv[i] = xr[threadIdx.x + 256 * i];
        s += xv[i].x + xv[i].y + xv[i].z + xv[i].w;
    }
    s = blockReduceSum(s);
    float mu = s / (float)D_;
    float vs = 0.f;
    #pragma unroll
    for (int i = 0; i < 2; i++) {
        float dx = xv[i].x - mu, dy = xv[i].y - mu, dz = xv[i].z - mu, dw = xv[i].w - mu;
        vs += dx * dx + dy * dy + dz * dz + dw * dw;
    }
    vs = blockReduceSum(vs);
    float inv = rsqrtf(vs / (float)D_ + 1e-5f);
    uint2* yh2 = (uint2*)(yh + (size_t)row * D_);
    uint2* yl2 = (uint2*)(yl + (size_t)row * D_);
    #pragma unroll
    for (int i = 0; i < 2; i++) {
        int t = threadIdx.x + 256 * i;
        float4 gv = ((const float4*)gg)[t];
        float4 bv = ((const float4*)bb)[t];
        float4 v = make_float4((xv[i].x - mu) * inv * gv.x + bv.x,
                               (xv[i].y - mu) * inv * gv.y + bv.y,
                               (xv[i].z - mu) * inv * gv.z + bv.z,
                               (xv[i].w - mu) * inv * gv.w + bv.w);
        uint2 hu, lu;
        split4(v, &hu, &lu);
        yh2[t] = hu; yl2[t] = lu;
    }
}

// vectorized elementwise split (n multiple of 4)
__global__ __launch_bounds__(256) void split_k(const float* __restrict__ x,
                                               bf16* __restrict__ h,
                                               bf16* __restrict__ l, int n4) {
    int i = blockIdx.x * 256 + threadIdx.x;
    if (i >= n4) return;
    float4 v = ((const float4*)x)[i];
    uint2 hu, lu;
    split4(v, &hu, &lu);
    ((uint2*)h)[i] = hu;
    ((uint2*)l)[i] = lu;
}

__global__ __launch_bounds__(256) void maskcat_k(const float* __restrict__ pm,
                                                 const float* __restrict__ sm,
                                                 const float* __restrict__ mm,
                                                 float* __restrict__ out) {
    int i = blockIdx.x * 256 + threadIdx.x;
    if (i >= B_ * SKV_) return;
    int b = i / SKV_, s = i % SKV_;
    float v;
    if (s < SP_) v = pm[b * SP_ + s];
    else if (s < SP_ + SS_) v = sm[b * SS_ + s - SP_];
    else v = mm[b * SM_ + s - SP_ - SS_];
    out[i] = v;
}

// ---------------- weight transpose+split (vectorized): W[K,N] -> T[N,K] hi/lo ----------------
__global__ __launch_bounds__(256) void wsplit_T(const float* __restrict__ W,
                                                bf16* __restrict__ Th,
                                                bf16* __restrict__ Tl,
                                                int K, int N) {
    __shared__ float tile[64][65];
    const int tid = threadIdx.x;
    const int n0 = blockIdx.x * 64, k0 = blockIdx.y * 64;
    #pragma unroll
    for (int i = 0; i < 4; i++) {
        int idx = tid + 256 * i;
        int r = idx >> 4, c4 = (idx & 15) * 4;
        float4 v = *(const float4*)&W[(size_t)(k0 + r) * N + n0 + c4];
        tile[r][c4] = v.x; tile[r][c4 + 1] = v.y;
        tile[r][c4 + 2] = v.z; tile[r][c4 + 3] = v.w;
    }
    __syncthreads();
    #pragma unroll
    for (int i = 0; i < 2; i++) {
        int idx = tid + 256 * i;
        int n = idx >> 3, kc = (idx & 7) * 8;
        float v0 = tile[kc + 0][n], v1 = tile[kc + 1][n];
        float v2 = tile[kc + 2][n], v3 = tile[kc + 3][n];
        float v4 = tile[kc + 4][n], v5 = tile[kc + 5][n];
        float v6 = tile[kc + 6][n], v7 = tile[kc + 7][n];
        uint32_t h0 = pack2h(v0, v1), h1 = pack2h(v2, v3);
        uint32_t h2 = pack2h(v4, v5), h3 = pack2h(v6, v7);
        __nv_bfloat162 b0 = *(__nv_bfloat162*)&h0, b1 = *(__nv_bfloat162*)&h1;
        __nv_bfloat162 b2 = *(__nv_bfloat162*)&h2, b3 = *(__nv_bfloat162*)&h3;
        uint32_t l0 = pack2h(v0 - __bfloat162float(b0.x), v1 - __bfloat162float(b0.y));
        uint32_t l1 = pack2h(v2 - __bfloat162float(b1.x), v3 - __bfloat162float(b1.y));
        uint32_t l2 = pack2h(v4 - __bfloat162float(b2.x), v5 - __bfloat162float(b2.y));
        uint32_t l3 = pack2h(v6 - __bfloat162float(b3.x), v7 - __bfloat162float(b3.y));
        size_t o = (size_t)(n0 + n) * K + k0 + kc;
        *(uint4*)(Th + o) = make_uint4(h0, h1, h2, h3);
        *(uint4*)(Tl + o) = make_uint4(l0, l1, l2, l3);
    }
}

// ---------------- mma.sync GEMM: BM=128, BN=128, BK=64, warp tile 64x32 (R5 config) ----------------
// EPI 2: Cf = res + tanh(gate)*(acc + bias)
// EPI 3: Ch/Cl = bsplit(gelu(acc))
// EPI 4: Cf = res + tanh(gate)*acc
// EPI 5: Ch/Cl = bsplit((acc+bias)*scale), with row remap (K/V concat)
#define GB_M 128
#define GB_N 128
#define GB_K 64
#define STAGE_BYTES 65536
#define GEMM_SMEM (2 * STAGE_BYTES)

template <int EPI>
__global__ __launch_bounds__(256) void gemm_mma(
    const bf16* __restrict__ Ah, const bf16* __restrict__ Al,
    const bf16* __restrict__ Bh, const bf16* __restrict__ Bl,
    const float* __restrict__ bias, const float* __restrict__ res,
    const float* __restrict__ gate,
    float* __restrict__ Cf, bf16* __restrict__ Ch, bf16* __restrict__ Cl,
    int M, int N, int K, float scale, int oShift, int oStride, int oOff) {
    extern __shared__ __align__(1024) char smem[];
    uint32_t sb = s2u(smem);
    const int tid = threadIdx.x, wid = tid >> 5, lane = tid & 31;
    const int n0 = blockIdx.x * GB_N, m0 = blockIdx.y * GB_M;
    const int wm0 = (wid >> 2) * 64;
    const int wn0 = (wid & 3) * 32;

    auto stage_load = [&](int st, int k0) {
        uint32_t s0 = sb + st * STAGE_BYTES;
        #pragma unroll
        for (int i = 0; i < 4; i++) {
            int idx = tid + 256 * i;
            int r = idx >> 3, c = idx & 7;
            uint32_t byte = r * 128 + c * 16;
            uint32_t sw = byte ^ ((byte >> 3) & 0x70);
            size_t goA = (size_t)(m0 + r) * K + k0 + c * 8;
            size_t goB = (size_t)(n0 + r) * K + k0 + c * 8;
            cp16(s0 + sw,         Ah + goA);
            cp16(s0 + 16384 + sw, Al + goA);
            cp16(s0 + 32768 + sw, Bh + goB);
            cp16(s0 + 49152 + sw, Bl + goB);
        }
        asm volatile("cp.async.commit_group;" ::: "memory");
    };

    float acc[4][4][4];
    #pragma unroll
    for (int i = 0; i < 4; i++)
        #pragma unroll
        for (int j = 0; j < 4; j++)
            #pragma unroll
            for (int c = 0; c < 4; c++) acc[i][j][c] = 0.f;

    const int nIter = K / GB_K;
    stage_load(0, 0);

    const int a_row = lane & 15;
    const int a_ch  = lane >> 4;
    const int b_row = (lane & 7) + ((lane >> 4) & 1) * 8;
    const int b_ch  = (lane >> 3) & 1;

    for (int it = 0; it < nIter; ++it) {
        if (it + 1 < nIter) stage_load((it + 1) & 1, (it + 1) * GB_K);
        if (it + 1 < nIter) {
            asm volatile("cp.async.wait_group 1;" ::: "memory");
        } else {
            asm volatile("cp.async.wait_group 0;" ::: "memory");
        }
        __syncthreads();

        uint32_t s0 = sb + (it & 1) * STAGE_BYTES;
        uint32_t sAh = s0, sAl = s0 + 16384, sBh = s0 + 32768, sBl = s0 + 49152;

        #pragma unroll
        for (int ks = 0; ks < 4; ks++) {
            uint32_t ahi[4][4], alo[4][4], bhi[4][2], blo[4][2];
            #pragma unroll
            for (int i = 0; i < 4; i++) {
                uint32_t byte = (wm0 + i * 16 + a_row) * 128 + (ks * 2 + a_ch) * 16;
                uint32_t sw = byte ^ ((byte >> 3) & 0x70);
                LDSM4(ahi[i][0], ahi[i][1], ahi[i][2], ahi[i][3], sAh + sw);
                LDSM4(alo[i][0], alo[i][1], alo[i][2], alo[i][3], sAl + sw);
            }
            #pragma unroll
            for (int jj = 0; jj < 2; jj++) {
                uint32_t byte = (wn0 + jj * 16 + b_row) * 128 + (ks * 2 + b_ch) * 16;
                uint32_t sw = byte ^ ((byte >> 3) & 0x70);
                uint32_t r0, r1, r2, r3;
                LDSM4(r0, r1, r2, r3, sBh + sw);
                bhi[jj * 2][0] = r0; bhi[jj * 2][1] = r1;
                bhi[jj * 2 + 1][0] = r2; bhi[jj * 2 + 1][1] = r3;
                LDSM4(r0, r1, r2, r3, sBl + sw);
                blo[jj * 2][0] = r0; blo[jj * 2][1] = r1;
                blo[jj * 2 + 1][0] = r2; blo[jj * 2 + 1][1] = r3;
            }
            #pragma unroll
            for (int i = 0; i < 4; i++)
                #pragma unroll
                for (int j = 0; j < 4; j++) {
                    MMA16816(acc[i][j], ahi[i], bhi[j]);
                    MMA16816(acc[i][j], ahi[i], blo[j]);
                    MMA16816(acc[i][j], alo[i], bhi[j]);
                }
        }
        __syncthreads();
    }

    float gt = 0.f;
    if (EPI == 2 || EPI == 4) gt = tanhf(gate[0]);
    const int cr = lane >> 2;
    const int cc = (lane & 3) * 2;

    #pragma unroll
    for (int i = 0; i < 4; i++) {
        #pragma unroll
        for (int j = 0; j < 4; j++) {
            int gcol = n0 + wn0 + j * 8 + cc;
            #pragma unroll
            for (int half = 0; half < 2; half++) {
                int grow = m0 + wm0 + i * 16 + cr + half * 8;
                float v0 = acc[i][j][half * 2 + 0];
                float v1 = acc[i][j][half * 2 + 1];
                size_t o = (size_t)grow * N + gcol;
                if (EPI == 2) {
                    float2 rr = *(const float2*)(res + o);
                    *(float2*)(Cf + o) = make_float2(rr.x + gt * (v0 + bias[gcol]),
                                                     rr.y + gt * (v1 + bias[gcol + 1]));
                } else if (EPI == 3) {
                    float a0 = gelu_f(v0), a1 = gelu_f(v1);
                    bf16 h0, l0, h1, l1;
                    bsplit(a0, &h0, &l0);
                    bsplit(a1, &h1, &l1);
                    *(__nv_bfloat162*)(Ch + o) = __nv_bfloat162(h0, h1);
                    *(__nv_bfloat162*)(Cl + o) = __nv_bfloat162(l0, l1);
                } else if (EPI == 4) {
                    float2 rr = *(const float2*)(res + o);
                    *(float2*)(Cf + o) = make_float2(rr.x + gt * v0, rr.y + gt * v1);
                } else {  // EPI 5
                    int ib = grow >> oShift;
                    int ir = grow & ((1 << oShift) - 1);
                    size_t oo = ((size_t)ib * oStride + oOff + ir) * N + gcol;
                    float a0 = (v0 + bias[gcol]) * scale;
                    float a1 = (v1 + bias[gcol + 1]) * scale;
                    bf16 h0, l0, h1, l1;
                    bsplit(a0, &h0, &l0);
                    bsplit(a1, &h1, &l1);
                    *(__nv_bfloat162*)(Ch + oo) = __nv_bfloat162(h0, h1);
                    *(__nv_bfloat162*)(Cl + oo) = __nv_bfloat162(l0, l1);
                }
            }
        }
    }
}

// ---------------- register-resident FA2 attention (R5) ----------------
#define AQ_H 0u
#define AQ_L 32768u
#define AKV  65536u
#define AST  65792u
#define ATTN_SMEM (65536 + 2 * 65792)

__global__ __launch_bounds__(256) void attn_fa2(
    const bf16* __restrict__ Qh, const bf16* __restrict__ Ql,
    const bf16* __restrict__ Kh, const bf16* __restrict__ Kl,
    const bf16* __restrict__ Vh, const bf16* __restrict__ Vl,
    const float* __restrict__ qmask, const float* __restrict__ kvmask,
    bf16* __restrict__ Oh, bf16* __restrict__ Ol) {
    extern __shared__ __align__(1024) char smem[];
    uint32_t sb = s2u(smem);

    const int qt = blockIdx.x, h = blockIdx.y, b = blockIdx.z;
    const int q0 = qt * 128;
    const int tid = threadIdx.x, wid = tid >> 5, lane = tid & 31;
    const int wrow = wid * 16;
    const int a_row = lane & 15, a_ch = lane >> 4;
    const int b_row = (lane & 7) + ((lane >> 4) & 1) * 8;
    const int b_ch  = (lane >> 3) & 1;
    const int cr = lane >> 2, cc = (lane & 3) * 2;

    auto kv_load = [&](int st, int t) {
        uint32_t s0 = sb + AKV + st * AST;
        int kv0 = t * 64;
        #pragma unroll
        for (int i = 0; i < 4; i++) {
            int idx = tid + 256 * i;
            int r = idx >> 4, c16 = idx & 15;
            uint32_t off = r * 256 + (((uint32_t)(c16 ^ (r & 7))) << 4);
            size_t go = (size_t)(b * SKV_ + kv0 + r) * D_ + h * HD_ + c16 * 8;
            cp16(s0 + off,          Kh + go);
            cp16(s0 + 16384 + off,  Kl + go);
            cp16(s0 + 32768 + off,  Vh + go);
            cp16(s0 + 49152 + off,  Vl + go);
        }
        if (tid < 16)
            cp16(s0 + 65536 + tid * 16, kvmask + b * SKV_ + t * 64 + tid * 4);
        asm volatile("cp.async.commit_group;" ::: "memory");
    };

    #pragma unroll
    for (int i = 0; i < 8; i++) {
        int idx = tid + 256 * i;
        int r = idx >> 4, c16 = idx & 15;
        uint32_t off = r * 256 + (((uint32_t)(c16 ^ (r & 7))) << 4);
        size_t go = (size_t)(b * SQ_ + q0 + r) * D_ + h * HD_ + c16 * 8;
        cp16(sb + AQ_H + off, Qh + go);
        cp16(sb + AQ_L + off, Ql + go);
    }
    asm volatile("cp.async.commit_group;" ::: "memory");
    kv_load(0, 0);
    asm volatile("cp.async.wait_group 0;" ::: "memory");
    __syncthreads();

    uint32_t qhf[8][4], qlf[8][4];
    #pragma unroll
    for (int ks = 0; ks < 8; ks++) {
        int row = wrow + a_row;
        int c16 = ks * 2 + a_ch;
        uint32_t off = row * 256 + (((uint32_t)(c16 ^ (row & 7))) << 4);
        LDSM4(qhf[ks][0], qhf[ks][1], qhf[ks][2], qhf[ks][3], sb + AQ_H + off);
        LDSM4(qlf[ks][0], qlf[ks][1], qlf[ks][2], qlf[ks][3], sb + AQ_L + off);
    }

    const float qm0 = qmask[b * SQ_ + q0 + wrow + cr];
    const float qm8 = qmask[b * SQ_ + q0 + wrow + cr + 8];

    float m0 = -1e30f, m8 = -1e30f, l0 = 0.f, l8 = 0.f;
    float oacc[16][4];
    #pragma unroll
    for (int j = 0; j < 16; j++)
        #pragma unroll
        for (int c = 0; c < 4; c++) oacc[j][c] = 0.f;

    const int T = SKV_ / 64;
    for (int t = 0; t < T; ++t) {
        if (t + 1 < T) kv_load((t + 1) & 1, t + 1);
        if (t + 1 < T) {
            asm volatile("cp.async.wait_group 1;" ::: "memory");
        } else {
            asm volatile("cp.async.wait_group 0;" ::: "memory");
        }
        __syncthreads();

        uint32_t s0 = sb + AKV + (t & 1) * AST;
        uint32_t sKh = s0, sKl = s0 + 16384, sVh = s0 + 32768, sVl = s0 + 49152;
        const float* msk = (const float*)(smem + AKV + (t & 1) * AST + 65536);

        float sacc[8][4];
        #pragma unroll
        for (int j = 0; j < 8; j++)
            #pragma unroll
            for (int c = 0; c < 4; c++) sacc[j][c] = 0.f;

        #pragma unroll
        for (int ks = 0; ks < 8; ks++) {
            #pragma unroll
            for (int jj = 0; jj < 4; jj++) {
                int row = jj * 16 + b_row;
                int c16 = ks * 2 + b_ch;
                uint32_t off = row * 256 + (((uint32_t)(c16 ^ (row & 7))) << 4);
                uint32_t k0, k1, k2, k3, e0, e1, e2, e3;
                LDSM4(k0, k1, k2, k3, sKh + off);
                LDSM4(e0, e1, e2, e3, sKl + off);
                uint32_t bh0[2] = {k0, k1}, bh1[2] = {k2, k3};
                uint32_t bl0[2] = {e0, e1}, bl1[2] = {e2, e3};
                MMA16816(sacc[jj * 2],     qhf[ks], bh0);
                MMA16816(sacc[jj * 2],     qhf[ks], bl0);
                MMA16816(sacc[jj * 2],     qlf[ks], bh0);
                MMA16816(sacc[jj * 2 + 1], qhf[ks], bh1);
                MMA16816(sacc[jj * 2 + 1], qhf[ks], bl1);
                MMA16816(sacc[jj * 2 + 1], qlf[ks], bh1);
            }
        }

        #pragma unroll
        for (int j = 0; j < 8; j++) {
            float2 km = *(const float2*)&msk[j * 8 + cc];
            if (qm0 == 0.f || km.x == 0.f) sacc[j][0] = -3.0e38f;
            if (qm0 == 0.f || km.y == 0.f) sacc[j][1] = -3.0e38f;
            if (qm8 == 0.f || km.x == 0.f) sacc[j][2] = -3.0e38f;
            if (qm8 == 0.f || km.y == 0.f) sacc[j][3] = -3.0e38f;
        }
        float mx0 = sacc[0][0], mx8 = sacc[0][2];
        #pragma unroll
        for (int j = 0; j < 8; j++) {
            mx0 = fmaxf(mx0, fmaxf(sacc[j][0], sacc[j][1]));
            mx8 = fmaxf(mx8, fmaxf(sacc[j][2], sacc[j][3]));
        }
        mx0 = fmaxf(mx0, __shfl_xor_sync(0xffffffffu, mx0, 1));
        mx0 = fmaxf(mx0, __shfl_xor_sync(0xffffffffu, mx0, 2));
        mx8 = fmaxf(mx8, __shfl_xor_sync(0xffffffffu, mx8, 1));
        mx8 = fmaxf(mx8, __shfl_xor_sync(0xffffffffu, mx8, 2));
        float m0n = fmaxf(m0, mx0), m8n = fmaxf(m8, mx8);
        float al0 = __expf(m0 - m0n), al8 = __expf(m8 - m8n);
        float sum0 = 0.f, sum8 = 0.f;
        #pragma unroll
        for (int j = 0; j < 8; j++) {
            sacc[j][0] = __expf(sacc[j][0] - m0n);
            sacc[j][1] = __expf(sacc[j][1] - m0n);
            sacc[j][2] = __expf(sacc[j][2] - m8n);
            sacc[j][3] = __expf(sacc[j][3] - m8n);
            sum0 += sacc[j][0] + sacc[j][1];
            sum8 += sacc[j][2] + sacc[j][3];
        }
        sum0 += __shfl_xor_sync(0xffffffffu, sum0, 1);
        sum0 += __shfl_xor_sync(0xffffffffu, sum0, 2);
        sum8 += __shfl_xor_sync(0xffffffffu, sum8, 1);
        sum8 += __shfl_xor_sync(0xffffffffu, sum8, 2);
        l0 = l0 * al0 + sum0; l8 = l8 * al8 + sum8;
        m0 = m0n; m8 = m8n;

        #pragma unroll
        for (int j = 0; j < 16; j++) {
            oacc[j][0] *= al0; oacc[j][1] *= al0;
            oacc[j][2] *= al8; oacc[j][3] *= al8;
        }

        #pragma unroll
        for (int ks = 0; ks < 4; ks++) {
            uint32_t ph[4], pl[4];
            {
                float v00 = sacc[ks * 2][0],     v01 = sacc[ks * 2][1];
                float v02 = sacc[ks * 2][2],     v03 = sacc[ks * 2][3];
                float v10 = sacc[ks * 2 + 1][0], v11 = sacc[ks * 2 + 1][1];
                float v12 = sacc[ks * 2 + 1][2], v13 = sacc[ks * 2 + 1][3];
                ph[0] = pack2h(v00, v01); ph[1] = pack2h(v02, v03);
                ph[2] = pack2h(v10, v11); ph[3] = pack2h(v12, v13);
                __nv_bfloat162 h0 = *(__nv_bfloat162*)&ph[0];
                __nv_bfloat162 h1 = *(__nv_bfloat162*)&ph[1];
                __nv_bfloat162 h2 = *(__nv_bfloat162*)&ph[2];
                __nv_bfloat162 h3 = *(__nv_bfloat162*)&ph[3];
                pl[0] = pack2h(v00 - __bfloat162float(h0.x), v01 - __bfloat162float(h0.y));
                pl[1] = pack2h(v02 - __bfloat162float(h1.x), v03 - __bfloat162float(h1.y));
                pl[2] = pack2h(v10 - __bfloat162float(h2.x), v11 - __bfloat162float(h2.y));
                pl[3] = pack2h(v12 - __bfloat162float(h3.x), v13 - __bfloat162float(h3.y));
            }
            #pragma unroll
            for (int ng = 0; ng < 8; ng++) {
                int k_row = ks * 16 + (lane & 15);
                int c16v = ng * 2 + (lane >> 4);
                uint32_t off = k_row * 256 + (((uint32_t)(c16v ^ (k_row & 7))) << 4);
                uint32_t v0, v1, v2, v3, w0, w1, w2, w3;
                LDSM4T(v0, v1, v2, v3, sVh + off);
                LDSM4T(w0, w1, w2, w3, sVl + off);
                uint32_t bh0[2] = {v0, v1}, bh1[2] = {v2, v3};
                uint32_t bl0[2] = {w0, w1}, bl1[2] = {w2, w3};
                MMA16816(oacc[ng * 2],     ph, bh0);
                MMA16816(oacc[ng * 2],     ph, bl0);
                MMA16816(oacc[ng * 2],     pl, bh0);
                MMA16816(oacc[ng * 2 + 1], ph, bh1);
                MMA16816(oacc[ng * 2 + 1], ph, bl1);
                MMA16816(oacc[ng * 2 + 1], pl, bh1);
            }
        }
        __syncthreads();
    }

    float inv0 = 1.0f / l0, inv8 = 1.0f / l8;
    #pragma unroll
    for (int j = 0; j < 16; j++) {
        int gcol = h * HD_ + j * 8 + cc;
        int r0 = q0 + wrow + cr;
        size_t o0 = (size_t)(b * SQ_ + r0) * D_ + gcol;
        size_t o8 = o0 + (size_t)8 * D_;
        float a0 = oacc[j][0] * inv0, a1 = oacc[j][1] * inv0;
        float a2 = oacc[j][2] * inv8, a3 = oacc[j][3] * inv8;
        bf16 h0, l0b, h1, l1b;
        bsplit(a0, &h0, &l0b); bsplit(a1, &h1, &l1b);
        *(__nv_bfloat162*)(Oh + o0) = __nv_bfloat162(h0, h1);
        *(__nv_bfloat162*)(Ol + o0) = __nv_bfloat162(l0b, l1b);
        bsplit(a2, &h0, &l0b); bsplit(a3, &h1, &l1b);
        *(__nv_bfloat162*)(Oh + o8) = __nv_bfloat162(h0, h1);
        *(__nv_bfloat162*)(Ol + o8) = __nv_bfloat162(l0b, l1b);
    }
}

// ---------------- launcher ----------------
extern "C" void kernel_launch(void* const* d_in, const int* in_sizes, int n_in,
                              void* d_out, int out_size) {
    const float* x     = (const float*)d_in[0];
    const float* pkv   = (const float*)d_in[1];
    const float* skv   = (const float*)d_in[2];
    const float* mkv   = (const float*)d_in[3];
    const float* qmask = (const float*)d_in[4];
    const float* pmask = (const float*)d_in[5];
    const float* smask = (const float*)d_in[6];
    const float* mmask = (const float*)d_in[7];
    const float* rmsw  = (const float*)d_in[8];
    const float* Wq  = (const float*)d_in[9];   const float* bq  = (const float*)d_in[10];
    const float* Wkp = (const float*)d_in[11];  const float* bkp = (const float*)d_in[12];
    const float* Wvp = (const float*)d_in[13];  const float* bvp = (const float*)d_in[14];
    const float* Wks = (const float*)d_in[15];  const float* bks = (const float*)d_in[16];
    const float* Wvs = (const float*)d_in[17];  const float* bvs = (const float*)d_in[18];
    const float* Wkm = (const float*)d_in[19];  const float* bkm = (const float*)d_in[20];
    const float* Wvm = (const float*)d_in[21];  const float* bvm = (const float*)d_in[22];
    const float* Wo  = (const float*)d_in[23];  const float* bo  = (const float*)d_in[24];
    const float* lng = (const float*)d_in[25];  const float* lnb = (const float*)d_in[26];
    const float* W1  = (const float*)d_in[27];  const float* W2  = (const float*)d_in[28];
    const float* ga  = (const float*)d_in[29];  const float* gf  = (const float*)d_in[30];
    float* out = (float*)d_out;

    float *hh, *kvm;
    cudaGetSymbolAddress((void**)&hh,  g_h);
    cudaGetSymbolAddress((void**)&kvm, g_kvmask);

    bf16 *qnh,*qnl,*aph,*apl,*ash,*asl,*amh,*aml;
    bf16 *qh,*ql,*kh,*kl,*vh,*vl,*cxh,*cxl,*lnh,*lnl,*ffh,*ffl;
    cudaGetSymbolAddress((void**)&qnh, g_qn_h);  cudaGetSymbolAddress((void**)&qnl, g_qn_l);
    cudaGetSymbolAddress((void**)&aph, g_ap_h);  cudaGetSymbolAddress((void**)&apl, g_ap_l);
    cudaGetSymbolAddress((void**)&ash, g_as_h);  cudaGetSymbolAddress((void**)&asl, g_as_l);
    cudaGetSymbolAddress((void**)&amh, g_am_h);  cudaGetSymbolAddress((void**)&aml, g_am_l);
    cudaGetSymbolAddress((void**)&qh,  g_qh);    cudaGetSymbolAddress((void**)&ql,  g_ql);
    cudaGetSymbolAddress((void**)&kh,  g_kh);    cudaGetSymbolAddress((void**)&kl,  g_kl);
    cudaGetSymbolAddress((void**)&vh,  g_vh);    cudaGetSymbolAddress((void**)&vl,  g_vl);
    cudaGetSymbolAddress((void**)&cxh, g_cx_h);  cudaGetSymbolAddress((void**)&cxl, g_cx_l);
    cudaGetSymbolAddress((void**)&lnh, g_ln_h);  cudaGetSymbolAddress((void**)&lnl, g_ln_l);
    cudaGetSymbolAddress((void**)&ffh, g_ff_h);  cudaGetSymbolAddress((void**)&ffl, g_ff_l);

    bf16 *tWqh,*tWql,*tWkph,*tWkpl,*tWvph,*tWvpl,*tWksh,*tWksl,*tWvsh,*tWvsl;
    bf16 *tWkmh,*tWkml,*tWvmh,*tWvml,*tWoh,*tWol,*tW1h,*tW1l,*tW2h,*tW2l;
    cudaGetSymbolAddress((void**)&tWqh,  g_Wq_h);   cudaGetSymbolAddress((void**)&tWql,  g_Wq_l);
    cudaGetSymbolAddress((void**)&tWkph, g_Wkp_h);  cudaGetSymbolAddress((void**)&tWkpl, g_Wkp_l);
    cudaGetSymbolAddress((void**)&tWvph, g_Wvp_h);  cudaGetSymbolAddress((void**)&tWvpl, g_Wvp_l);
    cudaGetSymbolAddress((void**)&tWksh, g_Wks_h);  cudaGetSymbolAddress((void**)&tWksl, g_Wks_l);
    cudaGetSymbolAddress((void**)&tWvsh, g_Wvs_h);  cudaGetSymbolAddress((void**)&tWvsl, g_Wvs_l);
    cudaGetSymbolAddress((void**)&tWkmh, g_Wkm_h);  cudaGetSymbolAddress((void**)&tWkml, g_Wkm_l);
    cudaGetSymbolAddress((void**)&tWvmh, g_Wvm_h);  cudaGetSymbolAddress((void**)&tWvml, g_Wvm_l);
    cudaGetSymbolAddress((void**)&tWoh,  g_Wo_h);   cudaGetSymbolAddress((void**)&tWol,  g_Wo_l);
    cudaGetSymbolAddress((void**)&tW1h,  g_W1_h);   cudaGetSymbolAddress((void**)&tW1l,  g_W1_l);
    cudaGetSymbolAddress((void**)&tW2h,  g_W2_h);   cudaGetSymbolAddress((void**)&tW2l,  g_W2_l);

    cudaFuncSetAttribute(gemm_mma<2>, cudaFuncAttributeMaxDynamicSharedMemorySize, GEMM_SMEM);
    cudaFuncSetAttribute(gemm_mma<3>, cudaFuncAttributeMaxDynamicSharedMemorySize, GEMM_SMEM);
    cudaFuncSetAttribute(gemm_mma<4>, cudaFuncAttributeMaxDynamicSharedMemorySize, GEMM_SMEM);
    cudaFuncSetAttribute(gemm_mma<5>, cudaFuncAttributeMaxDynamicSharedMemorySize, GEMM_SMEM);
    cudaFuncSetAttribute(attn_fa2, cudaFuncAttributeMaxDynamicSharedMemorySize, ATTN_SMEM);

    // weight transpose+split (64x64 tiles, vectorized)
    wsplit_T<<<dim3(D_ / 64,     D_ / 64),     256>>>(Wq,  tWqh,  tWql,  D_,     D_);
    wsplit_T<<<dim3(D_ / 64,     DP_ / 64),    256>>>(Wkp, tWkph, tWkpl, DP_,    D_);
    wsplit_T<<<dim3(D_ / 64,     DP_ / 64),    256>>>(Wvp, tWvph, tWvpl, DP_,    D_);
    wsplit_T<<<dim3(D_ / 64,     DS_ / 64),    256>>>(Wks, tWksh, tWksl, DS_,    D_);
    wsplit_T<<<dim3(D_ / 64,     DS_ / 64),    256>>>(Wvs, tWvsh, tWvsl, DS_,    D_);
    wsplit_T<<<dim3(D_ / 64,     DM_ / 64),    256>>>(Wkm, tWkmh, tWkml, DM_,    D_);
    wsplit_T<<<dim3(D_ / 64,     DM_ / 64),    256>>>(Wvm, tWvmh, tWvml, DM_,    D_);
    wsplit_T<<<dim3(D_ / 64,     D_ / 64),     256>>>(Wo,  tWoh,  tWol,  D_,     D_);
    wsplit_T<<<dim3(INNER_ / 64, D_ / 64),     256>>>(W1,  tW1h,  tW1l,  D_,     INNER_);
    wsplit_T<<<dim3(D_ / 64,     INNER_ / 64), 256>>>(W2,  tW2h,  tW2l,  INNER_, D_);

    // activation splits + mask concat
    rmsnorm_split<<<B_ * SQ_, 256>>>(x, rmsw, qnh, qnl);
    split_k<<<(B_ * SP_ * DP_ / 4 + 255) / 256, 256>>>(pkv, aph, apl, B_ * SP_ * DP_ / 4);
    split_k<<<(B_ * SS_ * DS_ / 4 + 255) / 256, 256>>>(skv, ash, asl, B_ * SS_ * DS_ / 4);
    split_k<<<(B_ * SM_ * DM_ / 4 + 255) / 256, 256>>>(mkv, amh, aml, B_ * SM_ * DM_ / 4);
    maskcat_k<<<(B_ * SKV_ + 255) / 256, 256>>>(pmask, smask, mmask, kvm);

    // projections -> bf16 hi/lo (EPI 5). Q: scale 0.25 folded; K/V remap to concat [B,SKV,D].
    gemm_mma<5><<<dim3(16, 16), 256, GEMM_SMEM>>>(qnh, qnl, tWqh, tWql, bq, nullptr, nullptr,
        nullptr, qh, ql, 2048, 2048, 2048, 0.25f, 10, 1024, 0);
    gemm_mma<5><<<dim3(16, 16), 256, GEMM_SMEM>>>(aph, apl, tWkph, tWkpl, bkp, nullptr, nullptr,
        nullptr, kh, kl, 2048, 2048, 1280, 1.f, 10, SKV_, 0);
    gemm_mma<5><<<dim3(16, 16), 256, GEMM_SMEM>>>(aph, apl, tWvph, tWvpl, bvp, nullptr, nullptr,
        nullptr, vh, vl, 2048, 2048, 1280, 1.f, 10, SKV_, 0);
    gemm_mma<5><<<dim3(16, 16), 256, GEMM_SMEM>>>(ash, asl, tWksh, tWksl, bks, nullptr, nullptr,
        nullptr, kh, kl, 2048, 2048, 1024, 1.f, 10, SKV_, SP_);
    gemm_mma<5><<<dim3(16, 16), 256, GEMM_SMEM>>>(ash, asl, tWvsh, tWvsl, bvs, nullptr, nullptr,
        nullptr, vh, vl, 2048, 2048, 1024, 1.f, 10, SKV_, SP_);
    gemm_mma<5><<<dim3(16, 8), 256, GEMM_SMEM>>>(amh, aml, tWkmh, tWkml, bkm, nullptr, nullptr,
        nullptr, kh, kl, 1024, 2048, 768, 1.f, 9, SKV_, SP_ + SS_);
    gemm_mma<5><<<dim3(16, 8), 256, GEMM_SMEM>>>(amh, aml, tWvmh, tWvml, bvm, nullptr, nullptr,
        nullptr, vh, vl, 1024, 2048, 768, 1.f, 9, SKV_, SP_ + SS_);

    // attention (register-resident FA2) -> ctx bf16 hi/lo
    attn_fa2<<<dim3(8, 16, 2), 256, ATTN_SMEM>>>(qh, ql, kh, kl, vh, vl,
                                                 qmask, kvm, cxh, cxl);

    // h = x + tanh(ga)*(ctx@Wo + bo)
    gemm_mma<2><<<dim3(16, 16), 256, GEMM_SMEM>>>(cxh, cxl, tWoh, tWol, bo, x, ga,
        hh, nullptr, nullptr, 2048, 2048, 2048, 1.f, 0, 0, 0);

    // LayerNorm
    layernorm_split<<<B_ * SQ_, 256>>>(hh, lng, lnb, lnh, lnl);

    // FFW
    gemm_mma<3><<<dim3(64, 16), 256, GEMM_SMEM>>>(lnh, lnl, tW1h, tW1l, nullptr, nullptr, nullptr,
        nullptr, ffh, ffl, 2048, INNER_, 2048, 1.f, 0, 0, 0);
    gemm_mma<4><<<dim3(16, 16), 256, GEMM_SMEM>>>(ffh, ffl, tW2h, tW2l, nullptr, hh, gf,
        out, nullptr, nullptr, 2048, 2048, INNER_, 1.f, 0, 0, 0);
}

// round 8
// speedup vs baseline: 1.5198x; 1.3370x over previous
#include <cuda_runtime.h>
#include <cuda_fp16.h>
#include <math.h>
#include <stdint.h>

typedef __half hlf;

// ---------------- problem dims ----------------
#define B_    2
#define SQ_   1024
#define D_    2048
#define H_    16
#define HD_   128
#define SP_   1024
#define SS_   1024
#define SM_   512
#define SKV_  2560
#define DP_   1280
#define DS_   1024
#define DM_   768
#define INNER_ 8192

// ---------------- scratch (device globals; no allocations) ----------------
__device__ float g_h  [B_*SQ_*D_];
__device__ float g_kvmask[B_*SKV_];
__device__ hlf g_qn_h [B_*SQ_*D_];   __device__ hlf g_qn_l [B_*SQ_*D_];
__device__ hlf g_ap_h [B_*SP_*DP_];  __device__ hlf g_ap_l [B_*SP_*DP_];
__device__ hlf g_as_h [B_*SS_*DS_];  __device__ hlf g_as_l [B_*SS_*DS_];
__device__ hlf g_am_h [B_*SM_*DM_];  __device__ hlf g_am_l [B_*SM_*DM_];
__device__ hlf g_qh   [B_*SQ_*D_];   __device__ hlf g_ql   [B_*SQ_*D_];
__device__ hlf g_kh   [B_*SKV_*D_];  __device__ hlf g_kl   [B_*SKV_*D_];
__device__ hlf g_vh   [B_*SKV_*D_];
__device__ hlf g_cx_h [B_*SQ_*D_];
__device__ hlf g_ln_h [B_*SQ_*D_];
__device__ hlf g_ff_h [B_*SQ_*INNER_];
__device__ hlf g_Wq_h [D_*D_];       __device__ hlf g_Wq_l [D_*D_];
__device__ hlf g_Wkp_h[D_*DP_];      __device__ hlf g_Wkp_l[D_*DP_];
__device__ hlf g_Wvp_h[D_*DP_];      __device__ hlf g_Wvp_l[D_*DP_];
__device__ hlf g_Wks_h[D_*DS_];      __device__ hlf g_Wks_l[D_*DS_];
__device__ hlf g_Wvs_h[D_*DS_];      __device__ hlf g_Wvs_l[D_*DS_];
__device__ hlf g_Wkm_h[D_*DM_];      __device__ hlf g_Wkm_l[D_*DM_];
__device__ hlf g_Wvm_h[D_*DM_];      __device__ hlf g_Wvm_l[D_*DM_];
__device__ hlf g_Wo_h [D_*D_];       __device__ hlf g_Wo_l [D_*D_];
__device__ hlf g_W1_h [INNER_*D_];   __device__ hlf g_W1_l [INNER_*D_];
__device__ hlf g_W2_h [D_*INNER_];   __device__ hlf g_W2_l [D_*INNER_];

// ---------------- helpers ----------------
__device__ __forceinline__ uint32_t s2u(const void* p) {
    uint32_t a;
    asm("{ .reg .u64 t; cvta.to.shared.u64 t, %1; cvt.u32.u64 %0, t; }" : "=r"(a) : "l"(p));
    return a;
}
__device__ __forceinline__ void cp16(uint32_t s, const void* g) {
    asm volatile("cp.async.cg.shared.global [%0], [%1], 16;" :: "r"(s), "l"(g) : "memory");
}
#define LDSM4(r0, r1, r2, r3, addr) \
    asm volatile("ldmatrix.sync.aligned.m8n8.x4.shared.b16 {%0,%1,%2,%3}, [%4];" \
                 : "=r"(r0), "=r"(r1), "=r"(r2), "=r"(r3) : "r"(addr))
#define LDSM4T(r0, r1, r2, r3, addr) \
    asm volatile("ldmatrix.sync.aligned.m8n8.x4.trans.shared.b16 {%0,%1,%2,%3}, [%4];" \
                 : "=r"(r0), "=r"(r1), "=r"(r2), "=r"(r3) : "r"(addr))
#define MMA16816(d, a, b) \
    asm volatile("mma.sync.aligned.m16n8k16.row.col.f32.f16.f16.f32 " \
                 "{%0,%1,%2,%3},{%4,%5,%6,%7},{%8,%9},{%0,%1,%2,%3};" \
                 : "+f"((d)[0]), "+f"((d)[1]), "+f"((d)[2]), "+f"((d)[3]) \
                 : "r"((a)[0]), "r"((a)[1]), "r"((a)[2]), "r"((a)[3]), \
                   "r"((b)[0]), "r"((b)[1]))

__device__ __forceinline__ float gelu_f(float x) {
    return 0.5f * x * (1.0f + erff(x * 0.70710678118654752f));
}
__device__ __forceinline__ void hsplit(float v, hlf* h, hlf* l) {
    hlf hh = __float2half_rn(v);
    *h = hh;
    *l = __float2half_rn(v - __half2float(hh));
}
__device__ __forceinline__ uint32_t pack2h(float a, float b) {
    __half2 t = __floats2half2_rn(a, b);
    return *(uint32_t*)&t;
}
// split float4 -> packed hi (uint2) + lo (uint2)
__device__ __forceinline__ void split4(float4 v, uint2* hu, uint2* lu) {
    uint32_t h0 = pack2h(v.x, v.y), h1 = pack2h(v.z, v.w);
    __half2 b0 = *(__half2*)&h0, b1 = *(__half2*)&h1;
    uint32_t l0 = pack2h(v.x - __half2float(b0.x), v.y - __half2float(b0.y));
    uint32_t l1 = pack2h(v.z - __half2float(b1.x), v.w - __half2float(b1.y));
    *hu = make_uint2(h0, h1);
    *lu = make_uint2(l0, l1);
}
__device__ __forceinline__ uint2 pack4h(float4 v) {
    return make_uint2(pack2h(v.x, v.y), pack2h(v.z, v.w));
}

// ---------------- block reduce ----------------
__device__ __forceinline__ float blockReduceSum(float v) {
    __shared__ float sh[32];
    __syncthreads();
    int lane = threadIdx.x & 31, w = threadIdx.x >> 5;
    #pragma unroll
    for (int o = 16; o > 0; o >>= 1) v += __shfl_xor_sync(0xffffffffu, v, o);
    if (lane == 0) sh[w] = v;
    __syncthreads();
    float r = 0.f;
    if (threadIdx.x < (blockDim.x >> 5)) r = sh[threadIdx.x];
    if (w == 0) {
        #pragma unroll
        for (int o = 16; o > 0; o >>= 1) r += __shfl_xor_sync(0xffffffffu, r, o);
        if (lane == 0) sh[0] = r;
    }
    __syncthreads();
    return sh[0];
}

// ---------------- RMSNorm -> fp16 split (hi/lo; feeds 3-term Q-proj) ----------------
__global__ __launch_bounds__(256) void rmsnorm_split(const float* __restrict__ x,
                                                     const float* __restrict__ w,
                                                     hlf* __restrict__ yh,
                                                     hlf* __restrict__ yl) {
    int row = blockIdx.x;
    const float4* xr = (const float4*)(x + (size_t)row * D_);
    const float4* wr = (const float4*)w;
    float ss = 0.f;
    float4 xv[2];
    #pragma unroll
    for (int i = 0; i < 2; i++) {
        xv[i] = xr[threadIdx.x + 256 * i];
        ss += xv[i].x * xv[i].x + xv[i].y * xv[i].y + xv[i].z * xv[i].z + xv[i].w * xv[i].w;
    }
    ss = blockReduceSum(ss);
    float inv = rsqrtf(ss / (float)D_ + 1e-6f);
    uint2* yh2 = (uint2*)(yh + (size_t)row * D_);
    uint2* yl2 = (uint2*)(yl + (size_t)row * D_);
    #pragma unroll
    for (int i = 0; i < 2; i++) {
        int t = threadIdx.x + 256 * i;
        float4 wv = wr[t];
        float4 v = make_float4(xv[i].x * inv * wv.x, xv[i].y * inv * wv.y,
                               xv[i].z * inv * wv.z, xv[i].w * inv * wv.w);
        uint2 hu, lu;
        split4(v, &hu, &lu);
        yh2[t] = hu; yl2[t] = lu;
    }
}

// ---------------- LayerNorm -> single fp16 (feeds 2-term W1) ----------------
__global__ __launch_bounds__(256) void layernorm_h(const float* __restrict__ x,
                                                   const float* __restrict__ gg,
                                                   const float* __restrict__ bb,
                                                   hlf* __restrict__ yh) {
    int row = blockIdx.x;
    const float4* xr = (const float4*)(x + (size_t)row * D_);
    float4 xv[2];
    float s = 0.f;
    #pragma unroll
    for (int i = 0; i < 2; i++) {
        xv[i] = xr[threadIdx.x + 256 * i];
        s += xv[i].x + xv[i].y + xv[i].z + xv[i].w;
    }
    s = blockReduceSum(s);
    float mu = s / (float)D_;
    float vs = 0.f;
    #pragma unroll
    for (int i = 0; i < 2; i++) {
        float dx = xv[i].x - mu, dy = xv[i].y - mu, dz = xv[i].z - mu, dw = xv[i].w - mu;
        vs += dx * dx + dy * dy + dz * dz + dw * dw;
    }
    vs = blockReduceSum(vs);
    float inv = rsqrtf(vs / (float)D_ + 1e-5f);
    uint2* yh2 = (uint2*)(yh + (size_t)row * D_);
    #pragma unroll
    for (int i = 0; i < 2; i++) {
        int t = threadIdx.x + 256 * i;
        float4 gv = ((const float4*)gg)[t];
        float4 bv = ((const float4*)bb)[t];
        float4 v = make_float4((xv[i].x - mu) * inv * gv.x + bv.x,
                               (xv[i].y - mu) * inv * gv.y + bv.y,
                               (xv[i].z - mu) * inv * gv.z + bv.z,
                               (xv[i].w - mu) * inv * gv.w + bv.w);
        yh2[t] = pack4h(v);
    }
}

// vectorized elementwise split (hi/lo)
__global__ __launch_bounds__(256) void split_k(const float* __restrict__ x,
                                               hlf* __restrict__ h,
                                               hlf* __restrict__ l, int n4) {
    int i = blockIdx.x * 256 + threadIdx.x;
    if (i >= n4) return;
    float4 v = ((const float4*)x)[i];
    uint2 hu, lu;
    split4(v, &hu, &lu);
    ((uint2*)h)[i] = hu;
    ((uint2*)l)[i] = lu;
}

__global__ __launch_bounds__(256) void maskcat_k(const float* __restrict__ pm,
                                                 const float* __restrict__ sm,
                                                 const float* __restrict__ mm,
                                                 float* __restrict__ out) {
    int i = blockIdx.x * 256 + threadIdx.x;
    if (i >= B_ * SKV_) return;
    int b = i / SKV_, s = i % SKV_;
    float v;
    if (s < SP_) v = pm[b * SP_ + s];
    else if (s < SP_ + SS_) v = sm[b * SS_ + s - SP_];
    else v = mm[b * SM_ + s - SP_ - SS_];
    out[i] = v;
}

// ---------------- weight transpose+split: W[K,N] -> T[N,K] hi/lo ----------------
__global__ __launch_bounds__(256) void wsplit_T(const float* __restrict__ W,
                                                hlf* __restrict__ Th,
                                                hlf* __restrict__ Tl,
                                                int K, int N) {
    __shared__ float tile[64][65];
    const int tid = threadIdx.x;
    const int n0 = blockIdx.x * 64, k0 = blockIdx.y * 64;
    #pragma unroll
    for (int i = 0; i < 4; i++) {
        int idx = tid + 256 * i;
        int r = idx >> 4, c4 = (idx & 15) * 4;
        float4 v = *(const float4*)&W[(size_t)(k0 + r) * N + n0 + c4];
        tile[r][c4] = v.x; tile[r][c4 + 1] = v.y;
        tile[r][c4 + 2] = v.z; tile[r][c4 + 3] = v.w;
    }
    __syncthreads();
    #pragma unroll
    for (int i = 0; i < 2; i++) {
        int idx = tid + 256 * i;
        int n = idx >> 3, kc = (idx & 7) * 8;
        float v0 = tile[kc + 0][n], v1 = tile[kc + 1][n];
        float v2 = tile[kc + 2][n], v3 = tile[kc + 3][n];
        float v4 = tile[kc + 4][n], v5 = tile[kc + 5][n];
        float v6 = tile[kc + 6][n], v7 = tile[kc + 7][n];
        uint32_t h0 = pack2h(v0, v1), h1 = pack2h(v2, v3);
        uint32_t h2 = pack2h(v4, v5), h3 = pack2h(v6, v7);
        __half2 b0 = *(__half2*)&h0, b1 = *(__half2*)&h1;
        __half2 b2 = *(__half2*)&h2, b3 = *(__half2*)&h3;
        uint32_t l0 = pack2h(v0 - __half2float(b0.x), v1 - __half2float(b0.y));
        uint32_t l1 = pack2h(v2 - __half2float(b1.x), v3 - __half2float(b1.y));
        uint32_t l2 = pack2h(v4 - __half2float(b2.x), v5 - __half2float(b2.y));
        uint32_t l3 = pack2h(v6 - __half2float(b3.x), v7 - __half2float(b3.y));
        size_t o = (size_t)(n0 + n) * K + k0 + kc;
        *(uint4*)(Th + o) = make_uint4(h0, h1, h2, h3);
        *(uint4*)(Tl + o) = make_uint4(l0, l1, l2, l3);
    }
}

// ============== 3-term GEMM (A hi/lo, B hi/lo): BM=128, BN=128, BK=64 ==============
// EPI 5: Ch/Cl = hsplit((acc+bias)*scale), with row remap (K concat)
#define GB_K 64
#define STG3 65536
#define GEMM3_SMEM (2 * STG3)

template <int EPI>
__global__ __launch_bounds__(256) void gemm3(
    const hlf* __restrict__ Ah, const hlf* __restrict__ Al,
    const hlf* __restrict__ Bh, const hlf* __restrict__ Bl,
    const float* __restrict__ bias,
    hlf* __restrict__ Ch, hlf* __restrict__ Cl,
    int M, int N, int K, float scale, int oShift, int oStride, int oOff) {
    extern __shared__ __align__(1024) char smem[];
    uint32_t sb = s2u(smem);
    const int tid = threadIdx.x, wid = tid >> 5, lane = tid & 31;
    const int n0 = blockIdx.x * 128, m0 = blockIdx.y * 128;
    const int wm0 = (wid >> 2) * 64;
    const int wn0 = (wid & 3) * 32;

    auto stage_load = [&](int st, int k0) {
        uint32_t s0 = sb + st * STG3;
        #pragma unroll
        for (int i = 0; i < 4; i++) {
            int idx = tid + 256 * i;
            int r = idx >> 3, c = idx & 7;
            uint32_t byte = r * 128 + c * 16;
            uint32_t sw = byte ^ ((byte >> 3) & 0x70);
            size_t goA = (size_t)(m0 + r) * K + k0 + c * 8;
            size_t goB = (size_t)(n0 + r) * K + k0 + c * 8;
            cp16(s0 + sw,         Ah + goA);
            cp16(s0 + 16384 + sw, Al + goA);
            cp16(s0 + 32768 + sw, Bh + goB);
            cp16(s0 + 49152 + sw, Bl + goB);
        }
        asm volatile("cp.async.commit_group;" ::: "memory");
    };

    float acc[4][4][4];
    #pragma unroll
    for (int i = 0; i < 4; i++)
        #pragma unroll
        for (int j = 0; j < 4; j++)
            #pragma unroll
            for (int c = 0; c < 4; c++) acc[i][j][c] = 0.f;

    const int nIter = K / GB_K;
    stage_load(0, 0);

    const int a_row = lane & 15;
    const int a_ch  = lane >> 4;
    const int b_row = (lane & 7) + ((lane >> 4) & 1) * 8;
    const int b_ch  = (lane >> 3) & 1;

    for (int it = 0; it < nIter; ++it) {
        if (it + 1 < nIter) stage_load((it + 1) & 1, (it + 1) * GB_K);
        if (it + 1 < nIter) {
            asm volatile("cp.async.wait_group 1;" ::: "memory");
        } else {
            asm volatile("cp.async.wait_group 0;" ::: "memory");
        }
        __syncthreads();

        uint32_t s0 = sb + (it & 1) * STG3;
        uint32_t sAh = s0, sAl = s0 + 16384, sBh = s0 + 32768, sBl = s0 + 49152;

        #pragma unroll
        for (int ks = 0; ks < 4; ks++) {
            uint32_t ahi[4][4], alo[4][4], bhi[4][2], blo[4][2];
            #pragma unroll
            for (int i = 0; i < 4; i++) {
                uint32_t byte = (wm0 + i * 16 + a_row) * 128 + (ks * 2 + a_ch) * 16;
                uint32_t sw = byte ^ ((byte >> 3) & 0x70);
                LDSM4(ahi[i][0], ahi[i][1], ahi[i][2], ahi[i][3], sAh + sw);
                LDSM4(alo[i][0], alo[i][1], alo[i][2], alo[i][3], sAl + sw);
            }
            #pragma unroll
            for (int jj = 0; jj < 2; jj++) {
                uint32_t byte = (wn0 + jj * 16 + b_row) * 128 + (ks * 2 + b_ch) * 16;
                uint32_t sw = byte ^ ((byte >> 3) & 0x70);
                uint32_t r0, r1, r2, r3;
                LDSM4(r0, r1, r2, r3, sBh + sw);
                bhi[jj * 2][0] = r0; bhi[jj * 2][1] = r1;
                bhi[jj * 2 + 1][0] = r2; bhi[jj * 2 + 1][1] = r3;
                LDSM4(r0, r1, r2, r3, sBl + sw);
                blo[jj * 2][0] = r0; blo[jj * 2][1] = r1;
                blo[jj * 2 + 1][0] = r2; blo[jj * 2 + 1][1] = r3;
            }
            #pragma unroll
            for (int i = 0; i < 4; i++)
                #pragma unroll
                for (int j = 0; j < 4; j++) {
                    MMA16816(acc[i][j], ahi[i], bhi[j]);
                    MMA16816(acc[i][j], ahi[i], blo[j]);
                    MMA16816(acc[i][j], alo[i], bhi[j]);
                }
        }
        __syncthreads();
    }

    const int cr = lane >> 2;
    const int cc = (lane & 3) * 2;
    #pragma unroll
    for (int i = 0; i < 4; i++) {
        #pragma unroll
        for (int j = 0; j < 4; j++) {
            int gcol = n0 + wn0 + j * 8 + cc;
            #pragma unroll
            for (int half = 0; half < 2; half++) {
                int grow = m0 + wm0 + i * 16 + cr + half * 8;
                float v0 = acc[i][j][half * 2 + 0];
                float v1 = acc[i][j][half * 2 + 1];
                // EPI 5
                int ib = grow >> oShift;
                int ir = grow & ((1 << oShift) - 1);
                size_t oo = ((size_t)ib * oStride + oOff + ir) * N + gcol;
                float a0 = (v0 + bias[gcol]) * scale;
                float a1 = (v1 + bias[gcol + 1]) * scale;
                hlf h0, l0, h1, l1;
                hsplit(a0, &h0, &l0);
                hsplit(a1, &h1, &l1);
                *(__half2*)(Ch + oo) = __half2(h0, h1);
                *(__half2*)(Cl + oo) = __half2(l0, l1);
            }
        }
    }
}

// ============== 2-term GEMM (A single fp16, B hi/lo): BM=128, BN=128, BK=64 ==============
// EPI 2: Cf = res + tanh(gate)*(acc + bias)
// EPI 3: Ch = fp16(gelu(acc))
// EPI 4: Cf = res + tanh(gate)*acc
// EPI 6: Ch = fp16((acc+bias)*scale), with row remap (V concat)
#define STG2 49152
#define GEMM2_SMEM (2 * STG2)

template <int EPI>
__global__ __launch_bounds__(256, 2) void gemm2(
    const hlf* __restrict__ Ah,
    const hlf* __restrict__ Bh, const hlf* __restrict__ Bl,
    const float* __restrict__ bias, const float* __restrict__ res,
    const float* __restrict__ gate,
    float* __restrict__ Cf, hlf* __restrict__ Ch,
    int M, int N, int K, float scale, int oShift, int oStride, int oOff) {
    extern __shared__ __align__(1024) char smem[];
    uint32_t sb = s2u(smem);
    const int tid = threadIdx.x, wid = tid >> 5, lane = tid & 31;
    const int n0 = blockIdx.x * 128, m0 = blockIdx.y * 128;
    const int wm0 = (wid >> 2) * 64;
    const int wn0 = (wid & 3) * 32;

    auto stage_load = [&](int st, int k0) {
        uint32_t s0 = sb + st * STG2;
        #pragma unroll
        for (int i = 0; i < 4; i++) {
            int idx = tid + 256 * i;
            int r = idx >> 3, c = idx & 7;
            uint32_t byte = r * 128 + c * 16;
            uint32_t sw = byte ^ ((byte >> 3) & 0x70);
            size_t goA = (size_t)(m0 + r) * K + k0 + c * 8;
            size_t goB = (size_t)(n0 + r) * K + k0 + c * 8;
            cp16(s0 + sw,         Ah + goA);
            cp16(s0 + 16384 + sw, Bh + goB);
            cp16(s0 + 32768 + sw, Bl + goB);
        }
        asm volatile("cp.async.commit_group;" ::: "memory");
    };

    float acc[4][4][4];
    #pragma unroll
    for (int i = 0; i < 4; i++)
        #pragma unroll
        for (int j = 0; j < 4; j++)
            #pragma unroll
            for (int c = 0; c < 4; c++) acc[i][j][c] = 0.f;

    const int nIter = K / GB_K;
    stage_load(0, 0);

    const int a_row = lane & 15;
    const int a_ch  = lane >> 4;
    const int b_row = (lane & 7) + ((lane >> 4) & 1) * 8;
    const int b_ch  = (lane >> 3) & 1;

    for (int it = 0; it < nIter; ++it) {
        if (it + 1 < nIter) stage_load((it + 1) & 1, (it + 1) * GB_K);
        if (it + 1 < nIter) {
            asm volatile("cp.async.wait_group 1;" ::: "memory");
        } else {
            asm volatile("cp.async.wait_group 0;" ::: "memory");
        }
        __syncthreads();

        uint32_t s0 = sb + (it & 1) * STG2;
        uint32_t sAh = s0, sBh = s0 + 16384, sBl = s0 + 32768;

        #pragma unroll
        for (int ks = 0; ks < 4; ks++) {
            uint32_t ahi[4][4], bhi[4][2], blo[4][2];
            #pragma unroll
            for (int i = 0; i < 4; i++) {
                uint32_t byte = (wm0 + i * 16 + a_row) * 128 + (ks * 2 + a_ch) * 16;
                uint32_t sw = byte ^ ((byte >> 3) & 0x70);
                LDSM4(ahi[i][0], ahi[i][1], ahi[i][2], ahi[i][3], sAh + sw);
            }
            #pragma unroll
            for (int jj = 0; jj < 2; jj++) {
                uint32_t byte = (wn0 + jj * 16 + b_row) * 128 + (ks * 2 + b_ch) * 16;
                uint32_t sw = byte ^ ((byte >> 3) & 0x70);
                uint32_t r0, r1, r2, r3;
                LDSM4(r0, r1, r2, r3, sBh + sw);
                bhi[jj * 2][0] = r0; bhi[jj * 2][1] = r1;
                bhi[jj * 2 + 1][0] = r2; bhi[jj * 2 + 1][1] = r3;
                LDSM4(r0, r1, r2, r3, sBl + sw);
                blo[jj * 2][0] = r0; blo[jj * 2][1] = r1;
                blo[jj * 2 + 1][0] = r2; blo[jj * 2 + 1][1] = r3;
            }
            #pragma unroll
            for (int i = 0; i < 4; i++)
                #pragma unroll
                for (int j = 0; j < 4; j++) {
                    MMA16816(acc[i][j], ahi[i], bhi[j]);
                    MMA16816(acc[i][j], ahi[i], blo[j]);
                }
        }
        __syncthreads();
    }

    float gt = 0.f;
    if (EPI == 2 || EPI == 4) gt = tanhf(gate[0]);
    const int cr = lane >> 2;
    const int cc = (lane & 3) * 2;

    #pragma unroll
    for (int i = 0; i < 4; i++) {
        #pragma unroll
        for (int j = 0; j < 4; j++) {
            int gcol = n0 + wn0 + j * 8 + cc;
            #pragma unroll
            for (int half = 0; half < 2; half++) {
                int grow = m0 + wm0 + i * 16 + cr + half * 8;
                float v0 = acc[i][j][half * 2 + 0];
                float v1 = acc[i][j][half * 2 + 1];
                size_t o = (size_t)grow * N + gcol;
                if (EPI == 2) {
                    float2 rr = *(const float2*)(res + o);
                    *(float2*)(Cf + o) = make_float2(rr.x + gt * (v0 + bias[gcol]),
                                                     rr.y + gt * (v1 + bias[gcol + 1]));
                } else if (EPI == 3) {
                    *(uint32_t*)(Ch + o) = pack2h(gelu_f(v0), gelu_f(v1));
                } else if (EPI == 4) {
                    float2 rr = *(const float2*)(res + o);
                    *(float2*)(Cf + o) = make_float2(rr.x + gt * v0, rr.y + gt * v1);
                } else {  // EPI 6
                    int ib = grow >> oShift;
                    int ir = grow & ((1 << oShift) - 1);
                    size_t oo = ((size_t)ib * oStride + oOff + ir) * N + gcol;
                    *(uint32_t*)(Ch + oo) = pack2h((v0 + bias[gcol]) * scale,
                                                   (v1 + bias[gcol + 1]) * scale);
                }
            }
        }
    }
}

// ---------------- register-resident FA2 attention (fp16; V single) ----------------
// smem: Q hi 32K | Q lo 32K | 2 stages x (Kh 16K | Kl 16K | Vh 16K | mask 256B)
#define AQ_H 0u
#define AQ_L 32768u
#define AKV  65536u
#define AST  49408u
#define ATTN_SMEM (65536 + 2 * 49408)

__global__ __launch_bounds__(256) void attn_fa2(
    const hlf* __restrict__ Qh, const hlf* __restrict__ Ql,
    const hlf* __restrict__ Kh, const hlf* __restrict__ Kl,
    const hlf* __restrict__ Vh,
    const float* __restrict__ qmask, const float* __restrict__ kvmask,
    hlf* __restrict__ Oh) {
    extern __shared__ __align__(1024) char smem[];
    uint32_t sb = s2u(smem);

    const int qt = blockIdx.x, h = blockIdx.y, b = blockIdx.z;
    const int q0 = qt * 128;
    const int tid = threadIdx.x, wid = tid >> 5, lane = tid & 31;
    const int wrow = wid * 16;
    const int a_row = lane & 15, a_ch = lane >> 4;
    const int b_row = (lane & 7) + ((lane >> 4) & 1) * 8;
    const int b_ch  = (lane >> 3) & 1;
    const int cr = lane >> 2, cc = (lane & 3) * 2;

    auto kv_load = [&](int st, int t) {
        uint32_t s0 = sb + AKV + st * AST;
        int kv0 = t * 64;
        #pragma unroll
        for (int i = 0; i < 4; i++) {
            int idx = tid + 256 * i;
            int r = idx >> 4, c16 = idx & 15;
            uint32_t off = r * 256 + (((uint32_t)(c16 ^ (r & 7))) << 4);
            size_t go = (size_t)(b * SKV_ + kv0 + r) * D_ + h * HD_ + c16 * 8;
            cp16(s0 + off,          Kh + go);
            cp16(s0 + 16384 + off,  Kl + go);
            cp16(s0 + 32768 + off,  Vh + go);
        }
        if (tid < 16)
            cp16(s0 + 49152 + tid * 16, kvmask + b * SKV_ + t * 64 + tid * 4);
        asm volatile("cp.async.commit_group;" ::: "memory");
    };

    #pragma unroll
    for (int i = 0; i < 8; i++) {
        int idx = tid + 256 * i;
        int r = idx >> 4, c16 = idx & 15;
        uint32_t off = r * 256 + (((uint32_t)(c16 ^ (r & 7))) << 4);
        size_t go = (size_t)(b * SQ_ + q0 + r) * D_ + h * HD_ + c16 * 8;
        cp16(sb + AQ_H + off, Qh + go);
        cp16(sb + AQ_L + off, Ql + go);
    }
    asm volatile("cp.async.commit_group;" ::: "memory");
    kv_load(0, 0);
    asm volatile("cp.async.wait_group 0;" ::: "memory");
    __syncthreads();

    uint32_t qhf[8][4], qlf[8][4];
    #pragma unroll
    for (int ks = 0; ks < 8; ks++) {
        int row = wrow + a_row;
        int c16 = ks * 2 + a_ch;
        uint32_t off = row * 256 + (((uint32_t)(c16 ^ (row & 7))) << 4);
        LDSM4(qhf[ks][0], qhf[ks][1], qhf[ks][2], qhf[ks][3], sb + AQ_H + off);
        LDSM4(qlf[ks][0], qlf[ks][1], qlf[ks][2], qlf[ks][3], sb + AQ_L + off);
    }

    const float qm0 = qmask[b * SQ_ + q0 + wrow + cr];
    const float qm8 = qmask[b * SQ_ + q0 + wrow + cr + 8];

    float m0 = -1e30f, m8 = -1e30f, l0 = 0.f, l8 = 0.f;
    float oacc[16][4];
    #pragma unroll
    for (int j = 0; j < 16; j++)
        #pragma unroll
        for (int c = 0; c < 4; c++) oacc[j][c] = 0.f;

    const int T = SKV_ / 64;
    for (int t = 0; t < T; ++t) {
        if (t + 1 < T) kv_load((t + 1) & 1, t + 1);
        if (t + 1 < T) {
            asm volatile("cp.async.wait_group 1;" ::: "memory");
        } else {
            asm volatile("cp.async.wait_group 0;" ::: "memory");
        }
        __syncthreads();

        uint32_t s0 = sb + AKV + (t & 1) * AST;
        uint32_t sKh = s0, sKl = s0 + 16384, sVh = s0 + 32768;
        const float* msk = (const float*)(smem + AKV + (t & 1) * AST + 49152);

        float sacc[8][4];
        #pragma unroll
        for (int j = 0; j < 8; j++)
            #pragma unroll
            for (int c = 0; c < 4; c++) sacc[j][c] = 0.f;

        #pragma unroll
        for (int ks = 0; ks < 8; ks++) {
            #pragma unroll
            for (int jj = 0; jj < 4; jj++) {
                int row = jj * 16 + b_row;
                int c16 = ks * 2 + b_ch;
                uint32_t off = row * 256 + (((uint32_t)(c16 ^ (row & 7))) << 4);
                uint32_t k0, k1, k2, k3, e0, e1, e2, e3;
                LDSM4(k0, k1, k2, k3, sKh + off);
                LDSM4(e0, e1, e2, e3, sKl + off);
                uint32_t bh0[2] = {k0, k1}, bh1[2] = {k2, k3};
                uint32_t bl0[2] = {e0, e1}, bl1[2] = {e2, e3};
                MMA16816(sacc[jj * 2],     qhf[ks], bh0);
                MMA16816(sacc[jj * 2],     qhf[ks], bl0);
                MMA16816(sacc[jj * 2],     qlf[ks], bh0);
                MMA16816(sacc[jj * 2 + 1], qhf[ks], bh1);
                MMA16816(sacc[jj * 2 + 1], qhf[ks], bl1);
                MMA16816(sacc[jj * 2 + 1], qlf[ks], bh1);
            }
        }

        #pragma unroll
        for (int j = 0; j < 8; j++) {
            float2 km = *(const float2*)&msk[j * 8 + cc];
            if (qm0 == 0.f || km.x == 0.f) sacc[j][0] = -3.0e38f;
            if (qm0 == 0.f || km.y == 0.f) sacc[j][1] = -3.0e38f;
            if (qm8 == 0.f || km.x == 0.f) sacc[j][2] = -3.0e38f;
            if (qm8 == 0.f || km.y == 0.f) sacc[j][3] = -3.0e38f;
        }
        float mx0 = sacc[0][0], mx8 = sacc[0][2];
        #pragma unroll
        for (int j = 0; j < 8; j++) {
            mx0 = fmaxf(mx0, fmaxf(sacc[j][0], sacc[j][1]));
            mx8 = fmaxf(mx8, fmaxf(sacc[j][2], sacc[j][3]));
        }
        mx0 = fmaxf(mx0, __shfl_xor_sync(0xffffffffu, mx0, 1));
        mx0 = fmaxf(mx0, __shfl_xor_sync(0xffffffffu, mx0, 2));
        mx8 = fmaxf(mx8, __shfl_xor_sync(0xffffffffu, mx8, 1));
        mx8 = fmaxf(mx8, __shfl_xor_sync(0xffffffffu, mx8, 2));
        float m0n = fmaxf(m0, mx0), m8n = fmaxf(m8, mx8);
        float al0 = __expf(m0 - m0n), al8 = __expf(m8 - m8n);
        float sum0 = 0.f, sum8 = 0.f;
        #pragma unroll
        for (int j = 0; j < 8; j++) {
            sacc[j][0] = __expf(sacc[j][0] - m0n);
            sacc[j][1] = __expf(sacc[j][1] - m0n);
            sacc[j][2] = __expf(sacc[j][2] - m8n);
            sacc[j][3] = __expf(sacc[j][3] - m8n);
            sum0 += sacc[j][0] + sacc[j][1];
            sum8 += sacc[j][2] + sacc[j][3];
        }
        sum0 += __shfl_xor_sync(0xffffffffu, sum0, 1);
        sum0 += __shfl_xor_sync(0xffffffffu, sum0, 2);
        sum8 += __shfl_xor_sync(0xffffffffu, sum8, 1);
        sum8 += __shfl_xor_sync(0xffffffffu, sum8, 2);
        l0 = l0 * al0 + sum0; l8 = l8 * al8 + sum8;
        m0 = m0n; m8 = m8n;

        #pragma unroll
        for (int j = 0; j < 16; j++) {
            oacc[j][0] *= al0; oacc[j][1] *= al0;
            oacc[j][2] *= al8; oacc[j][3] *= al8;
        }

        // O += P @ V (P split hi/lo in regs, V single)
        #pragma unroll
        for (int ks = 0; ks < 4; ks++) {
            uint32_t ph[4], pl[4];
            {
                float v00 = sacc[ks * 2][0],     v01 = sacc[ks * 2][1];
                float v02 = sacc[ks * 2][2],     v03 = sacc[ks * 2][3];
                float v10 = sacc[ks * 2 + 1][0], v11 = sacc[ks * 2 + 1][1];
                float v12 = sacc[ks * 2 + 1][2], v13 = sacc[ks * 2 + 1][3];
                ph[0] = pack2h(v00, v01); ph[1] = pack2h(v02, v03);
                ph[2] = pack2h(v10, v11); ph[3] = pack2h(v12, v13);
                __half2 h0 = *(__half2*)&ph[0];
                __half2 h1 = *(__half2*)&ph[1];
                __half2 h2 = *(__half2*)&ph[2];
                __half2 h3 = *(__half2*)&ph[3];
                pl[0] = pack2h(v00 - __half2float(h0.x), v01 - __half2float(h0.y));
                pl[1] = pack2h(v02 - __half2float(h1.x), v03 - __half2float(h1.y));
                pl[2] = pack2h(v10 - __half2float(h2.x), v11 - __half2float(h2.y));
                pl[3] = pack2h(v12 - __half2float(h3.x), v13 - __half2float(h3.y));
            }
            #pragma unroll
            for (int ng = 0; ng < 8; ng++) {
                int k_row = ks * 16 + (lane & 15);
                int c16v = ng * 2 + (lane >> 4);
                uint32_t off = k_row * 256 + (((uint32_t)(c16v ^ (k_row & 7))) << 4);
                uint32_t v0, v1, v2, v3;
                LDSM4T(v0, v1, v2, v3, sVh + off);
                uint32_t bh0[2] = {v0, v1}, bh1[2] = {v2, v3};
                MMA16816(oacc[ng * 2],     ph, bh0);
                MMA16816(oacc[ng * 2],     pl, bh0);
                MMA16816(oacc[ng * 2 + 1], ph, bh1);
                MMA16816(oacc[ng * 2 + 1], pl, bh1);
            }
        }
        __syncthreads();
    }

    float inv0 = 1.0f / l0, inv8 = 1.0f / l8;
    #pragma unroll
    for (int j = 0; j < 16; j++) {
        int gcol = h * HD_ + j * 8 + cc;
        int r0 = q0 + wrow + cr;
        size_t o0 = (size_t)(b * SQ_ + r0) * D_ + gcol;
        size_t o8 = o0 + (size_t)8 * D_;
        *(uint32_t*)(Oh + o0) = pack2h(oacc[j][0] * inv0, oacc[j][1] * inv0);
        *(uint32_t*)(Oh + o8) = pack2h(oacc[j][2] * inv8, oacc[j][3] * inv8);
    }
}

// ---------------- launcher ----------------
extern "C" void kernel_launch(void* const* d_in, const int* in_sizes, int n_in,
                              void* d_out, int out_size) {
    const float* x     = (const float*)d_in[0];
    const float* pkv   = (const float*)d_in[1];
    const float* skv   = (const float*)d_in[2];
    const float* mkv   = (const float*)d_in[3];
    const float* qmask = (const float*)d_in[4];
    const float* pmask = (const float*)d_in[5];
    const float* smask = (const float*)d_in[6];
    const float* mmask = (const float*)d_in[7];
    const float* rmsw  = (const float*)d_in[8];
    const float* Wq  = (const float*)d_in[9];   const float* bq  = (const float*)d_in[10];
    const float* Wkp = (const float*)d_in[11];  const float* bkp = (const float*)d_in[12];
    const float* Wvp = (const float*)d_in[13];  const float* bvp = (const float*)d_in[14];
    const float* Wks = (const float*)d_in[15];  const float* bks = (const float*)d_in[16];
    const float* Wvs = (const float*)d_in[17];  const float* bvs = (const float*)d_in[18];
    const float* Wkm = (const float*)d_in[19];  const float* bkm = (const float*)d_in[20];
    const float* Wvm = (const float*)d_in[21];  const float* bvm = (const float*)d_in[22];
    const float* Wo  = (const float*)d_in[23];  const float* bo  = (const float*)d_in[24];
    const float* lng = (const float*)d_in[25];  const float* lnb = (const float*)d_in[26];
    const float* W1  = (const float*)d_in[27];  const float* W2  = (const float*)d_in[28];
    const float* ga  = (const float*)d_in[29];  const float* gf  = (const float*)d_in[30];
    float* out = (float*)d_out;

    float *hh, *kvm;
    cudaGetSymbolAddress((void**)&hh,  g_h);
    cudaGetSymbolAddress((void**)&kvm, g_kvmask);

    hlf *qnh,*qnl,*aph,*apl,*ash,*asl,*amh,*aml;
    hlf *qh,*ql,*kh,*kl,*vh,*cxh,*lnh,*ffh;
    cudaGetSymbolAddress((void**)&qnh, g_qn_h);  cudaGetSymbolAddress((void**)&qnl, g_qn_l);
    cudaGetSymbolAddress((void**)&aph, g_ap_h);  cudaGetSymbolAddress((void**)&apl, g_ap_l);
    cudaGetSymbolAddress((void**)&ash, g_as_h);  cudaGetSymbolAddress((void**)&asl, g_as_l);
    cudaGetSymbolAddress((void**)&amh, g_am_h);  cudaGetSymbolAddress((void**)&aml, g_am_l);
    cudaGetSymbolAddress((void**)&qh,  g_qh);    cudaGetSymbolAddress((void**)&ql,  g_ql);
    cudaGetSymbolAddress((void**)&kh,  g_kh);    cudaGetSymbolAddress((void**)&kl,  g_kl);
    cudaGetSymbolAddress((void**)&vh,  g_vh);
    cudaGetSymbolAddress((void**)&cxh, g_cx_h);
    cudaGetSymbolAddress((void**)&lnh, g_ln_h);
    cudaGetSymbolAddress((void**)&ffh, g_ff_h);

    hlf *tWqh,*tWql,*tWkph,*tWkpl,*tWvph,*tWvpl,*tWksh,*tWksl,*tWvsh,*tWvsl;
    hlf *tWkmh,*tWkml,*tWvmh,*tWvml,*tWoh,*tWol,*tW1h,*tW1l,*tW2h,*tW2l;
    cudaGetSymbolAddress((void**)&tWqh,  g_Wq_h);   cudaGetSymbolAddress((void**)&tWql,  g_Wq_l);
    cudaGetSymbolAddress((void**)&tWkph, g_Wkp_h);  cudaGetSymbolAddress((void**)&tWkpl, g_Wkp_l);
    cudaGetSymbolAddress((void**)&tWvph, g_Wvp_h);  cudaGetSymbolAddress((void**)&tWvpl, g_Wvp_l);
    cudaGetSymbolAddress((void**)&tWksh, g_Wks_h);  cudaGetSymbolAddress((void**)&tWksl, g_Wks_l);
    cudaGetSymbolAddress((void**)&tWvsh, g_Wvs_h);  cudaGetSymbolAddress((void**)&tWvsl, g_Wvs_l);
    cudaGetSymbolAddress((void**)&tWkmh, g_Wkm_h);  cudaGetSymbolAddress((void**)&tWkml, g_Wkm_l);
    cudaGetSymbolAddress((void**)&tWvmh, g_Wvm_h);  cudaGetSymbolAddress((void**)&tWvml, g_Wvm_l);
    cudaGetSymbolAddress((void**)&tWoh,  g_Wo_h);   cudaGetSymbolAddress((void**)&tWol,  g_Wo_l);
    cudaGetSymbolAddress((void**)&tW1h,  g_W1_h);   cudaGetSymbolAddress((void**)&tW1l,  g_W1_l);
    cudaGetSymbolAddress((void**)&tW2h,  g_W2_h);   cudaGetSymbolAddress((void**)&tW2l,  g_W2_l);

    cudaFuncSetAttribute(gemm3<5>, cudaFuncAttributeMaxDynamicSharedMemorySize, GEMM3_SMEM);
    cudaFuncSetAttribute(gemm2<2>, cudaFuncAttributeMaxDynamicSharedMemorySize, GEMM2_SMEM);
    cudaFuncSetAttribute(gemm2<3>, cudaFuncAttributeMaxDynamicSharedMemorySize, GEMM2_SMEM);
    cudaFuncSetAttribute(gemm2<4>, cudaFuncAttributeMaxDynamicSharedMemorySize, GEMM2_SMEM);
    cudaFuncSetAttribute(gemm2<6>, cudaFuncAttributeMaxDynamicSharedMemorySize, GEMM2_SMEM);
    cudaFuncSetAttribute(attn_fa2, cudaFuncAttributeMaxDynamicSharedMemorySize, ATTN_SMEM);

    // weight transpose+split
    wsplit_T<<<dim3(D_ / 64,     D_ / 64),     256>>>(Wq,  tWqh,  tWql,  D_,     D_);
    wsplit_T<<<dim3(D_ / 64,     DP_ / 64),    256>>>(Wkp, tWkph, tWkpl, DP_,    D_);
    wsplit_T<<<dim3(D_ / 64,     DP_ / 64),    256>>>(Wvp, tWvph, tWvpl, DP_,    D_);
    wsplit_T<<<dim3(D_ / 64,     DS_ / 64),    256>>>(Wks, tWksh, tWksl, DS_,    D_);
    wsplit_T<<<dim3(D_ / 64,     DS_ / 64),    256>>>(Wvs, tWvsh, tWvsl, DS_,    D_);
    wsplit_T<<<dim3(D_ / 64,     DM_ / 64),    256>>>(Wkm, tWkmh, tWkml, DM_,    D_);
    wsplit_T<<<dim3(D_ / 64,     DM_ / 64),    256>>>(Wvm, tWvmh, tWvml, DM_,    D_);
    wsplit_T<<<dim3(D_ / 64,     D_ / 64),     256>>>(Wo,  tWoh,  tWol,  D_,     D_);
    wsplit_T<<<dim3(INNER_ / 64, D_ / 64),     256>>>(W1,  tW1h,  tW1l,  D_,     INNER_);
    wsplit_T<<<dim3(D_ / 64,     INNER_ / 64), 256>>>(W2,  tW2h,  tW2l,  INNER_, D_);

    // activation splits + mask concat
    rmsnorm_split<<<B_ * SQ_, 256>>>(x, rmsw, qnh, qnl);
    split_k<<<(B_ * SP_ * DP_ / 4 + 255) / 256, 256>>>(pkv, aph, apl, B_ * SP_ * DP_ / 4);
    split_k<<<(B_ * SS_ * DS_ / 4 + 255) / 256, 256>>>(skv, ash, asl, B_ * SS_ * DS_ / 4);
    split_k<<<(B_ * SM_ * DM_ / 4 + 255) / 256, 256>>>(mkv, amh, aml, B_ * SM_ * DM_ / 4);
    maskcat_k<<<(B_ * SKV_ + 255) / 256, 256>>>(pmask, smask, mmask, kvm);

    // Q/K projections (3-term, hi/lo out, remap). Q: scale 0.25 folded.
    gemm3<5><<<dim3(16, 16), 256, GEMM3_SMEM>>>(qnh, qnl, tWqh, tWql, bq,
        qh, ql, 2048, 2048, 2048, 0.25f, 10, 1024, 0);
    gemm3<5><<<dim3(16, 16), 256, GEMM3_SMEM>>>(aph, apl, tWkph, tWkpl, bkp,
        kh, kl, 2048, 2048, 1280, 1.f, 10, SKV_, 0);
    gemm3<5><<<dim3(16, 16), 256, GEMM3_SMEM>>>(ash, asl, tWksh, tWksl, bks,
        kh, kl, 2048, 2048, 1024, 1.f, 10, SKV_, SP_);
    gemm3<5><<<dim3(16, 8), 256, GEMM3_SMEM>>>(amh, aml, tWkmh, tWkml, bkm,
        kh, kl, 1024, 2048, 768, 1.f, 9, SKV_, SP_ + SS_);

    // V projections (2-term, single out, remap)
    gemm2<6><<<dim3(16, 16), 256, GEMM2_SMEM>>>(aph, tWvph, tWvpl, bvp, nullptr, nullptr,
        nullptr, vh, 2048, 2048, 1280, 1.f, 10, SKV_, 0);
    gemm2<6><<<dim3(16, 16), 256, GEMM2_SMEM>>>(ash, tWvsh, tWvsl, bvs, nullptr, nullptr,
        nullptr, vh, 2048, 2048, 1024, 1.f, 10, SKV_, SP_);
    gemm2<6><<<dim3(16, 8), 256, GEMM2_SMEM>>>(amh, tWvmh, tWvml, bvm, nullptr, nullptr,
        nullptr, vh, 1024, 2048, 768, 1.f, 9, SKV_, SP_ + SS_);

    // attention -> ctx single fp16
    attn_fa2<<<dim3(8, 16, 2), 256, ATTN_SMEM>>>(qh, ql, kh, kl, vh,
                                                 qmask, kvm, cxh);

    // h = x + tanh(ga)*(ctx@Wo + bo)   (2-term)
    gemm2<2><<<dim3(16, 16), 256, GEMM2_SMEM>>>(cxh, tWoh, tWol, bo, x, ga,
        hh, nullptr, 2048, 2048, 2048, 1.f, 0, 0, 0);

    // LayerNorm -> single fp16
    layernorm_h<<<B_ * SQ_, 256>>>(hh, lng, lnb, lnh);

    // FFW (2-term)
    gemm2<3><<<dim3(64, 16), 256, GEMM2_SMEM>>>(lnh, tW1h, tW1l, nullptr, nullptr, nullptr,
        nullptr, ffh, 2048, INNER_, 2048, 1.f, 0, 0, 0);
    gemm2<4><<<dim3(16, 16), 256, GEMM2_SMEM>>>(ffh, tW2h, tW2l, nullptr, hh, gf,
        out, nullptr, 2048, 2048, INNER_, 1.f, 0, 0, 0);
}

// round 9
// speedup vs baseline: 1.6389x; 1.0783x over previous
#include <cuda_runtime.h>
#include <cuda_fp16.h>
#include <math.h>
#include <stdint.h>

typedef __half hlf;

// ---------------- problem dims ----------------
#define B_    2
#define SQ_   1024
#define D_    2048
#define H_    16
#define HD_   128
#define SP_   1024
#define SS_   1024
#define SM_   512
#define SKV_  2560
#define DP_   1280
#define DS_   1024
#define DM_   768
#define INNER_ 8192

// ---------------- scratch (device globals; no allocations) ----------------
__device__ float g_h  [B_*SQ_*D_];
__device__ float g_kvmask[B_*SKV_];
__device__ hlf g_qn  [B_*SQ_*D_];
__device__ hlf g_ap  [B_*SP_*DP_];
__device__ hlf g_as  [B_*SS_*DS_];
__device__ hlf g_am  [B_*SM_*DM_];
__device__ hlf g_qh  [B_*SQ_*D_];   __device__ hlf g_ql  [B_*SQ_*D_];
__device__ hlf g_kh  [B_*SKV_*D_];  __device__ hlf g_kl  [B_*SKV_*D_];
__device__ hlf g_vh  [B_*SKV_*D_];
__device__ hlf g_cx_h[B_*SQ_*D_];
__device__ hlf g_ln_h[B_*SQ_*D_];
__device__ hlf g_ff_h[B_*SQ_*INNER_];
__device__ hlf g_Wq_h [D_*D_];       __device__ hlf g_Wq_l [D_*D_];
__device__ hlf g_Wkp_h[D_*DP_];      __device__ hlf g_Wkp_l[D_*DP_];
__device__ hlf g_Wvp_h[D_*DP_];      __device__ hlf g_Wvp_l[D_*DP_];
__device__ hlf g_Wks_h[D_*DS_];      __device__ hlf g_Wks_l[D_*DS_];
__device__ hlf g_Wvs_h[D_*DS_];      __device__ hlf g_Wvs_l[D_*DS_];
__device__ hlf g_Wkm_h[D_*DM_];      __device__ hlf g_Wkm_l[D_*DM_];
__device__ hlf g_Wvm_h[D_*DM_];      __device__ hlf g_Wvm_l[D_*DM_];
__device__ hlf g_Wo_h [D_*D_];       __device__ hlf g_Wo_l [D_*D_];
__device__ hlf g_W1_h [INNER_*D_];   __device__ hlf g_W1_l [INNER_*D_];
__device__ hlf g_W2_h [D_*INNER_];   __device__ hlf g_W2_l [D_*INNER_];

// ---------------- helpers ----------------
__device__ __forceinline__ uint32_t s2u(const void* p) {
    uint32_t a;
    asm("{ .reg .u64 t; cvta.to.shared.u64 t, %1; cvt.u32.u64 %0, t; }" : "=r"(a) : "l"(p));
    return a;
}
__device__ __forceinline__ void cp16(uint32_t s, const void* g) {
    asm volatile("cp.async.cg.shared.global [%0], [%1], 16;" :: "r"(s), "l"(g) : "memory");
}
#define LDSM4(r0, r1, r2, r3, addr) \
    asm volatile("ldmatrix.sync.aligned.m8n8.x4.shared.b16 {%0,%1,%2,%3}, [%4];" \
                 : "=r"(r0), "=r"(r1), "=r"(r2), "=r"(r3) : "r"(addr))
#define LDSM4T(r0, r1, r2, r3, addr) \
    asm volatile("ldmatrix.sync.aligned.m8n8.x4.trans.shared.b16 {%0,%1,%2,%3}, [%4];" \
                 : "=r"(r0), "=r"(r1), "=r"(r2), "=r"(r3) : "r"(addr))
#define MMA16816(d, a, b) \
    asm volatile("mma.sync.aligned.m16n8k16.row.col.f32.f16.f16.f32 " \
                 "{%0,%1,%2,%3},{%4,%5,%6,%7},{%8,%9},{%0,%1,%2,%3};" \
                 : "+f"((d)[0]), "+f"((d)[1]), "+f"((d)[2]), "+f"((d)[3]) \
                 : "r"((a)[0]), "r"((a)[1]), "r"((a)[2]), "r"((a)[3]), \
                   "r"((b)[0]), "r"((b)[1]))

__device__ __forceinline__ float gelu_f(float x) {
    return 0.5f * x * (1.0f + erff(x * 0.70710678118654752f));
}
__device__ __forceinline__ void hsplit(float v, hlf* h, hlf* l) {
    hlf hh = __float2half_rn(v);
    *h = hh;
    *l = __float2half_rn(v - __half2float(hh));
}
__device__ __forceinline__ uint32_t pack2h(float a, float b) {
    __half2 t = __floats2half2_rn(a, b);
    return *(uint32_t*)&t;
}
__device__ __forceinline__ uint2 pack4h(float4 v) {
    return make_uint2(pack2h(v.x, v.y), pack2h(v.z, v.w));
}

// ---------------- block reduce ----------------
__device__ __forceinline__ float blockReduceSum(float v) {
    __shared__ float sh[32];
    __syncthreads();
    int lane = threadIdx.x & 31, w = threadIdx.x >> 5;
    #pragma unroll
    for (int o = 16; o > 0; o >>= 1) v += __shfl_xor_sync(0xffffffffu, v, o);
    if (lane == 0) sh[w] = v;
    __syncthreads();
    float r = 0.f;
    if (threadIdx.x < (blockDim.x >> 5)) r = sh[threadIdx.x];
    if (w == 0) {
        #pragma unroll
        for (int o = 16; o > 0; o >>= 1) r += __shfl_xor_sync(0xffffffffu, r, o);
        if (lane == 0) sh[0] = r;
    }
    __syncthreads();
    return sh[0];
}

// ---------------- RMSNorm -> single fp16 ----------------
__global__ __launch_bounds__(256) void rmsnorm_h(const float* __restrict__ x,
                                                 const float* __restrict__ w,
                                                 hlf* __restrict__ yh) {
    int row = blockIdx.x;
    const float4* xr = (const float4*)(x + (size_t)row * D_);
    const float4* wr = (const float4*)w;
    float ss = 0.f;
    float4 xv[2];
    #pragma unroll
    for (int i = 0; i < 2; i++) {
        xv[i] = xr[threadIdx.x + 256 * i];
        ss += xv[i].x * xv[i].x + xv[i].y * xv[i].y + xv[i].z * xv[i].z + xv[i].w * xv[i].w;
    }
    ss = blockReduceSum(ss);
    float inv = rsqrtf(ss / (float)D_ + 1e-6f);
    uint2* yh2 = (uint2*)(yh + (size_t)row * D_);
    #pragma unroll
    for (int i = 0; i < 2; i++) {
        int t = threadIdx.x + 256 * i;
        float4 wv = wr[t];
        float4 v = make_float4(xv[i].x * inv * wv.x, xv[i].y * inv * wv.y,
                               xv[i].z * inv * wv.z, xv[i].w * inv * wv.w);
        yh2[t] = pack4h(v);
    }
}

// ---------------- LayerNorm -> single fp16 ----------------
__global__ __launch_bounds__(256) void layernorm_h(const float* __restrict__ x,
                                                   const float* __restrict__ gg,
                                                   const float* __restrict__ bb,
                                                   hlf* __restrict__ yh) {
    int row = blockIdx.x;
    const float4* xr = (const float4*)(x + (size_t)row * D_);
    float4 xv[2];
    float s = 0.f;
    #pragma unroll
    for (int i = 0; i < 2; i++) {
        xv[i] = xr[threadIdx.x + 256 * i];
        s += xv[i].x + xv[i].y + xv[i].z + xv[i].w;
    }
    s = blockReduceSum(s);
    float mu = s / (float)D_;
    float vs = 0.f;
    #pragma unroll
    for (int i = 0; i < 2; i++) {
        float dx = xv[i].x - mu, dy = xv[i].y - mu, dz = xv[i].z - mu, dw = xv[i].w - mu;
        vs += dx * dx + dy * dy + dz * dz + dw * dw;
    }
    vs = blockReduceSum(vs);
    float inv = rsqrtf(vs / (float)D_ + 1e-5f);
    uint2* yh2 = (uint2*)(yh + (size_t)row * D_);
    #pragma unroll
    for (int i = 0; i < 2; i++) {
        int t = threadIdx.x + 256 * i;
        float4 gv = ((const float4*)gg)[t];
        float4 bv = ((const float4*)bb)[t];
        float4 v = make_float4((xv[i].x - mu) * inv * gv.x + bv.x,
                               (xv[i].y - mu) * inv * gv.y + bv.y,
                               (xv[i].z - mu) * inv * gv.z + bv.z,
                               (xv[i].w - mu) * inv * gv.w + bv.w);
        yh2[t] = pack4h(v);
    }
}

// fp32 -> single fp16 pack (n multiple of 4)
__global__ __launch_bounds__(256) void pack_k(const float* __restrict__ x,
                                              hlf* __restrict__ h, int n4) {
    int i = blockIdx.x * 256 + threadIdx.x;
    if (i >= n4) return;
    float4 v = ((const float4*)x)[i];
    ((uint2*)h)[i] = pack4h(v);
}

__global__ __launch_bounds__(256) void maskcat_k(const float* __restrict__ pm,
                                                 const float* __restrict__ sm,
                                                 const float* __restrict__ mm,
                                                 float* __restrict__ out) {
    int i = blockIdx.x * 256 + threadIdx.x;
    if (i >= B_ * SKV_) return;
    int b = i / SKV_, s = i % SKV_;
    float v;
    if (s < SP_) v = pm[b * SP_ + s];
    else if (s < SP_ + SS_) v = sm[b * SS_ + s - SP_];
    else v = mm[b * SM_ + s - SP_ - SS_];
    out[i] = v;
}

// ---------------- weight transpose+split: W[K,N] -> T[N,K] hi/lo ----------------
__global__ __launch_bounds__(256) void wsplit_T(const float* __restrict__ W,
                                                hlf* __restrict__ Th,
                                                hlf* __restrict__ Tl,
                                                int K, int N) {
    __shared__ float tile[64][65];
    const int tid = threadIdx.x;
    const int n0 = blockIdx.x * 64, k0 = blockIdx.y * 64;
    #pragma unroll
    for (int i = 0; i < 4; i++) {
        int idx = tid + 256 * i;
        int r = idx >> 4, c4 = (idx & 15) * 4;
        float4 v = *(const float4*)&W[(size_t)(k0 + r) * N + n0 + c4];
        tile[r][c4] = v.x; tile[r][c4 + 1] = v.y;
        tile[r][c4 + 2] = v.z; tile[r][c4 + 3] = v.w;
    }
    __syncthreads();
    #pragma unroll
    for (int i = 0; i < 2; i++) {
        int idx = tid + 256 * i;
        int n = idx >> 3, kc = (idx & 7) * 8;
        float v0 = tile[kc + 0][n], v1 = tile[kc + 1][n];
        float v2 = tile[kc + 2][n], v3 = tile[kc + 3][n];
        float v4 = tile[kc + 4][n], v5 = tile[kc + 5][n];
        float v6 = tile[kc + 6][n], v7 = tile[kc + 7][n];
        uint32_t h0 = pack2h(v0, v1), h1 = pack2h(v2, v3);
        uint32_t h2 = pack2h(v4, v5), h3 = pack2h(v6, v7);
        __half2 b0 = *(__half2*)&h0, b1 = *(__half2*)&h1;
        __half2 b2 = *(__half2*)&h2, b3 = *(__half2*)&h3;
        uint32_t l0 = pack2h(v0 - __half2float(b0.x), v1 - __half2float(b0.y));
        uint32_t l1 = pack2h(v2 - __half2float(b1.x), v3 - __half2float(b1.y));
        uint32_t l2 = pack2h(v4 - __half2float(b2.x), v5 - __half2float(b2.y));
        uint32_t l3 = pack2h(v6 - __half2float(b3.x), v7 - __half2float(b3.y));
        size_t o = (size_t)(n0 + n) * K + k0 + kc;
        *(uint4*)(Th + o) = make_uint4(h0, h1, h2, h3);
        *(uint4*)(Tl + o) = make_uint4(l0, l1, l2, l3);
    }
}

// ============== 2-term GEMM (A single fp16, B hi/lo): BM=128, BN=128, BK=64 ==============
// EPI 2: Cf = res + tanh(gate)*(acc + bias)
// EPI 3: Ch = fp16(gelu(acc))
// EPI 4: Cf = res + tanh(gate)*acc
// EPI 5: Ch/Cl = hsplit((acc+bias)*scale), row remap (Q/K concat)
// EPI 6: Ch = fp16((acc+bias)*scale), row remap (V concat)
#define GB_K 64
#define STG2 49152
#define GEMM2_SMEM (2 * STG2)

template <int EPI>
__global__ __launch_bounds__(256, 2) void gemm2(
    const hlf* __restrict__ Ah,
    const hlf* __restrict__ Bh, const hlf* __restrict__ Bl,
    const float* __restrict__ bias, const float* __restrict__ res,
    const float* __restrict__ gate,
    float* __restrict__ Cf, hlf* __restrict__ Ch, hlf* __restrict__ Cl,
    int M, int N, int K, float scale, int oShift, int oStride, int oOff) {
    extern __shared__ __align__(1024) char smem[];
    uint32_t sb = s2u(smem);
    const int tid = threadIdx.x, wid = tid >> 5, lane = tid & 31;
    const int n0 = blockIdx.x * 128, m0 = blockIdx.y * 128;
    const int wm0 = (wid >> 2) * 64;
    const int wn0 = (wid & 3) * 32;

    auto stage_load = [&](int st, int k0) {
        uint32_t s0 = sb + st * STG2;
        #pragma unroll
        for (int i = 0; i < 4; i++) {
            int idx = tid + 256 * i;
            int r = idx >> 3, c = idx & 7;
            uint32_t byte = r * 128 + c * 16;
            uint32_t sw = byte ^ ((byte >> 3) & 0x70);
            size_t goA = (size_t)(m0 + r) * K + k0 + c * 8;
            size_t goB = (size_t)(n0 + r) * K + k0 + c * 8;
            cp16(s0 + sw,         Ah + goA);
            cp16(s0 + 16384 + sw, Bh + goB);
            cp16(s0 + 32768 + sw, Bl + goB);
        }
        asm volatile("cp.async.commit_group;" ::: "memory");
    };

    float acc[4][4][4];
    #pragma unroll
    for (int i = 0; i < 4; i++)
        #pragma unroll
        for (int j = 0; j < 4; j++)
            #pragma unroll
            for (int c = 0; c < 4; c++) acc[i][j][c] = 0.f;

    const int nIter = K / GB_K;
    stage_load(0, 0);

    const int a_row = lane & 15;
    const int a_ch  = lane >> 4;
    const int b_row = (lane & 7) + ((lane >> 4) & 1) * 8;
    const int b_ch  = (lane >> 3) & 1;

    for (int it = 0; it < nIter; ++it) {
        if (it + 1 < nIter) stage_load((it + 1) & 1, (it + 1) * GB_K);
        if (it + 1 < nIter) {
            asm volatile("cp.async.wait_group 1;" ::: "memory");
        } else {
            asm volatile("cp.async.wait_group 0;" ::: "memory");
        }
        __syncthreads();

        uint32_t s0 = sb + (it & 1) * STG2;
        uint32_t sAh = s0, sBh = s0 + 16384, sBl = s0 + 32768;

        #pragma unroll
        for (int ks = 0; ks < 4; ks++) {
            uint32_t ahi[4][4], bhi[4][2], blo[4][2];
            #pragma unroll
            for (int i = 0; i < 4; i++) {
                uint32_t byte = (wm0 + i * 16 + a_row) * 128 + (ks * 2 + a_ch) * 16;
                uint32_t sw = byte ^ ((byte >> 3) & 0x70);
                LDSM4(ahi[i][0], ahi[i][1], ahi[i][2], ahi[i][3], sAh + sw);
            }
            #pragma unroll
            for (int jj = 0; jj < 2; jj++) {
                uint32_t byte = (wn0 + jj * 16 + b_row) * 128 + (ks * 2 + b_ch) * 16;
                uint32_t sw = byte ^ ((byte >> 3) & 0x70);
                uint32_t r0, r1, r2, r3;
                LDSM4(r0, r1, r2, r3, sBh + sw);
                bhi[jj * 2][0] = r0; bhi[jj * 2][1] = r1;
                bhi[jj * 2 + 1][0] = r2; bhi[jj * 2 + 1][1] = r3;
                LDSM4(r0, r1, r2, r3, sBl + sw);
                blo[jj * 2][0] = r0; blo[jj * 2][1] = r1;
                blo[jj * 2 + 1][0] = r2; blo[jj * 2 + 1][1] = r3;
            }
            #pragma unroll
            for (int i = 0; i < 4; i++)
                #pragma unroll
                for (int j = 0; j < 4; j++) {
                    MMA16816(acc[i][j], ahi[i], bhi[j]);
                    MMA16816(acc[i][j], ahi[i], blo[j]);
                }
        }
        __syncthreads();
    }

    float gt = 0.f;
    if (EPI == 2 || EPI == 4) gt = tanhf(gate[0]);
    const int cr = lane >> 2;
    const int cc = (lane & 3) * 2;

    #pragma unroll
    for (int i = 0; i < 4; i++) {
        #pragma unroll
        for (int j = 0; j < 4; j++) {
            int gcol = n0 + wn0 + j * 8 + cc;
            #pragma unroll
            for (int half = 0; half < 2; half++) {
                int grow = m0 + wm0 + i * 16 + cr + half * 8;
                float v0 = acc[i][j][half * 2 + 0];
                float v1 = acc[i][j][half * 2 + 1];
                size_t o = (size_t)grow * N + gcol;
                if (EPI == 2) {
                    float2 rr = *(const float2*)(res + o);
                    *(float2*)(Cf + o) = make_float2(rr.x + gt * (v0 + bias[gcol]),
                                                     rr.y + gt * (v1 + bias[gcol + 1]));
                } else if (EPI == 3) {
                    *(uint32_t*)(Ch + o) = pack2h(gelu_f(v0), gelu_f(v1));
                } else if (EPI == 4) {
                    float2 rr = *(const float2*)(res + o);
                    *(float2*)(Cf + o) = make_float2(rr.x + gt * v0, rr.y + gt * v1);
                } else if (EPI == 5) {
                    int ib = grow >> oShift;
                    int ir = grow & ((1 << oShift) - 1);
                    size_t oo = ((size_t)ib * oStride + oOff + ir) * N + gcol;
                    float a0 = (v0 + bias[gcol]) * scale;
                    float a1 = (v1 + bias[gcol + 1]) * scale;
                    hlf h0, l0, h1, l1;
                    hsplit(a0, &h0, &l0);
                    hsplit(a1, &h1, &l1);
                    *(__half2*)(Ch + oo) = __half2(h0, h1);
                    *(__half2*)(Cl + oo) = __half2(l0, l1);
                } else {  // EPI 6
                    int ib = grow >> oShift;
                    int ir = grow & ((1 << oShift) - 1);
                    size_t oo = ((size_t)ib * oStride + oOff + ir) * N + gcol;
                    *(uint32_t*)(Ch + oo) = pack2h((v0 + bias[gcol]) * scale,
                                                   (v1 + bias[gcol + 1]) * scale);
                }
            }
        }
    }
}

// ---------------- register-resident FA2 attention (fp16; V single) ----------------
#define AQ_H 0u
#define AQ_L 32768u
#define AKV  65536u
#define AST  49408u
#define ATTN_SMEM (65536 + 2 * 49408)

__global__ __launch_bounds__(256) void attn_fa2(
    const hlf* __restrict__ Qh, const hlf* __restrict__ Ql,
    const hlf* __restrict__ Kh, const hlf* __restrict__ Kl,
    const hlf* __restrict__ Vh,
    const float* __restrict__ qmask, const float* __restrict__ kvmask,
    hlf* __restrict__ Oh) {
    extern __shared__ __align__(1024) char smem[];
    uint32_t sb = s2u(smem);

    const int qt = blockIdx.x, h = blockIdx.y, b = blockIdx.z;
    const int q0 = qt * 128;
    const int tid = threadIdx.x, wid = tid >> 5, lane = tid & 31;
    const int wrow = wid * 16;
    const int a_row = lane & 15, a_ch = lane >> 4;
    const int b_row = (lane & 7) + ((lane >> 4) & 1) * 8;
    const int b_ch  = (lane >> 3) & 1;
    const int cr = lane >> 2, cc = (lane & 3) * 2;

    auto kv_load = [&](int st, int t) {
        uint32_t s0 = sb + AKV + st * AST;
        int kv0 = t * 64;
        #pragma unroll
        for (int i = 0; i < 4; i++) {
            int idx = tid + 256 * i;
            int r = idx >> 4, c16 = idx & 15;
            uint32_t off = r * 256 + (((uint32_t)(c16 ^ (r & 7))) << 4);
            size_t go = (size_t)(b * SKV_ + kv0 + r) * D_ + h * HD_ + c16 * 8;
            cp16(s0 + off,          Kh + go);
            cp16(s0 + 16384 + off,  Kl + go);
            cp16(s0 + 32768 + off,  Vh + go);
        }
        if (tid < 16)
            cp16(s0 + 49152 + tid * 16, kvmask + b * SKV_ + t * 64 + tid * 4);
        asm volatile("cp.async.commit_group;" ::: "memory");
    };

    #pragma unroll
    for (int i = 0; i < 8; i++) {
        int idx = tid + 256 * i;
        int r = idx >> 4, c16 = idx & 15;
        uint32_t off = r * 256 + (((uint32_t)(c16 ^ (r & 7))) << 4);
        size_t go = (size_t)(b * SQ_ + q0 + r) * D_ + h * HD_ + c16 * 8;
        cp16(sb + AQ_H + off, Qh + go);
        cp16(sb + AQ_L + off, Ql + go);
    }
    asm volatile("cp.async.commit_group;" ::: "memory");
    kv_load(0, 0);
    asm volatile("cp.async.wait_group 0;" ::: "memory");
    __syncthreads();

    uint32_t qhf[8][4], qlf[8][4];
    #pragma unroll
    for (int ks = 0; ks < 8; ks++) {
        int row = wrow + a_row;
        int c16 = ks * 2 + a_ch;
        uint32_t off = row * 256 + (((uint32_t)(c16 ^ (row & 7))) << 4);
        LDSM4(qhf[ks][0], qhf[ks][1], qhf[ks][2], qhf[ks][3], sb + AQ_H + off);
        LDSM4(qlf[ks][0], qlf[ks][1], qlf[ks][2], qlf[ks][3], sb + AQ_L + off);
    }

    const float qm0 = qmask[b * SQ_ + q0 + wrow + cr];
    const float qm8 = qmask[b * SQ_ + q0 + wrow + cr + 8];

    float m0 = -1e30f, m8 = -1e30f, l0 = 0.f, l8 = 0.f;
    float oacc[16][4];
    #pragma unroll
    for (int j = 0; j < 16; j++)
        #pragma unroll
        for (int c = 0; c < 4; c++) oacc[j][c] = 0.f;

    const int T = SKV_ / 64;
    for (int t = 0; t < T; ++t) {
        if (t + 1 < T) kv_load((t + 1) & 1, t + 1);
        if (t + 1 < T) {
            asm volatile("cp.async.wait_group 1;" ::: "memory");
        } else {
            asm volatile("cp.async.wait_group 0;" ::: "memory");
        }
        __syncthreads();

        uint32_t s0 = sb + AKV + (t & 1) * AST;
        uint32_t sKh = s0, sKl = s0 + 16384, sVh = s0 + 32768;
        const float* msk = (const float*)(smem + AKV + (t & 1) * AST + 49152);

        float sacc[8][4];
        #pragma unroll
        for (int j = 0; j < 8; j++)
            #pragma unroll
            for (int c = 0; c < 4; c++) sacc[j][c] = 0.f;

        #pragma unroll
        for (int ks = 0; ks < 8; ks++) {
            #pragma unroll
            for (int jj = 0; jj < 4; jj++) {
                int row = jj * 16 + b_row;
                int c16 = ks * 2 + b_ch;
                uint32_t off = row * 256 + (((uint32_t)(c16 ^ (row & 7))) << 4);
                uint32_t k0, k1, k2, k3, e0, e1, e2, e3;
                LDSM4(k0, k1, k2, k3, sKh + off);
                LDSM4(e0, e1, e2, e3, sKl + off);
                uint32_t bh0[2] = {k0, k1}, bh1[2] = {k2, k3};
                uint32_t bl0[2] = {e0, e1}, bl1[2] = {e2, e3};
                MMA16816(sacc[jj * 2],     qhf[ks], bh0);
                MMA16816(sacc[jj * 2],     qhf[ks], bl0);
                MMA16816(sacc[jj * 2],     qlf[ks], bh0);
                MMA16816(sacc[jj * 2 + 1], qhf[ks], bh1);
                MMA16816(sacc[jj * 2 + 1], qhf[ks], bl1);
                MMA16816(sacc[jj * 2 + 1], qlf[ks], bh1);
            }
        }

        #pragma unroll
        for (int j = 0; j < 8; j++) {
            float2 km = *(const float2*)&msk[j * 8 + cc];
            if (qm0 == 0.f || km.x == 0.f) sacc[j][0] = -3.0e38f;
            if (qm0 == 0.f || km.y == 0.f) sacc[j][1] = -3.0e38f;
            if (qm8 == 0.f || km.x == 0.f) sacc[j][2] = -3.0e38f;
            if (qm8 == 0.f || km.y == 0.f) sacc[j][3] = -3.0e38f;
        }
        float mx0 = sacc[0][0], mx8 = sacc[0][2];
        #pragma unroll
        for (int j = 0; j < 8; j++) {
            mx0 = fmaxf(mx0, fmaxf(sacc[j][0], sacc[j][1]));
            mx8 = fmaxf(mx8, fmaxf(sacc[j][2], sacc[j][3]));
        }
        mx0 = fmaxf(mx0, __shfl_xor_sync(0xffffffffu, mx0, 1));
        mx0 = fmaxf(mx0, __shfl_xor_sync(0xffffffffu, mx0, 2));
        mx8 = fmaxf(mx8, __shfl_xor_sync(0xffffffffu, mx8, 1));
        mx8 = fmaxf(mx8, __shfl_xor_sync(0xffffffffu, mx8, 2));
        float m0n = fmaxf(m0, mx0), m8n = fmaxf(m8, mx8);
        float al0 = __expf(m0 - m0n), al8 = __expf(m8 - m8n);
        float sum0 = 0.f, sum8 = 0.f;
        #pragma unroll
        for (int j = 0; j < 8; j++) {
            sacc[j][0] = __expf(sacc[j][0] - m0n);
            sacc[j][1] = __expf(sacc[j][1] - m0n);
            sacc[j][2] = __expf(sacc[j][2] - m8n);
            sacc[j][3] = __expf(sacc[j][3] - m8n);
            sum0 += sacc[j][0] + sacc[j][1];
            sum8 += sacc[j][2] + sacc[j][3];
        }
        sum0 += __shfl_xor_sync(0xffffffffu, sum0, 1);
        sum0 += __shfl_xor_sync(0xffffffffu, sum0, 2);
        sum8 += __shfl_xor_sync(0xffffffffu, sum8, 1);
        sum8 += __shfl_xor_sync(0xffffffffu, sum8, 2);
        l0 = l0 * al0 + sum0; l8 = l8 * al8 + sum8;
        m0 = m0n; m8 = m8n;

        #pragma unroll
        for (int j = 0; j < 16; j++) {
            oacc[j][0] *= al0; oacc[j][1] *= al0;
            oacc[j][2] *= al8; oacc[j][3] *= al8;
        }

        // O += P @ V (P split hi/lo in regs, V single)
        #pragma unroll
        for (int ks = 0; ks < 4; ks++) {
            uint32_t ph[4], pl[4];
            {
                float v00 = sacc[ks * 2][0],     v01 = sacc[ks * 2][1];
                float v02 = sacc[ks * 2][2],     v03 = sacc[ks * 2][3];
                float v10 = sacc[ks * 2 + 1][0], v11 = sacc[ks * 2 + 1][1];
                float v12 = sacc[ks * 2 + 1][2], v13 = sacc[ks * 2 + 1][3];
                ph[0] = pack2h(v00, v01); ph[1] = pack2h(v02, v03);
                ph[2] = pack2h(v10, v11); ph[3] = pack2h(v12, v13);
                __half2 h0 = *(__half2*)&ph[0];
                __half2 h1 = *(__half2*)&ph[1];
                __half2 h2 = *(__half2*)&ph[2];
                __half2 h3 = *(__half2*)&ph[3];
                pl[0] = pack2h(v00 - __half2float(h0.x), v01 - __half2float(h0.y));
                pl[1] = pack2h(v02 - __half2float(h1.x), v03 - __half2float(h1.y));
                pl[2] = pack2h(v10 - __half2float(h2.x), v11 - __half2float(h2.y));
                pl[3] = pack2h(v12 - __half2float(h3.x), v13 - __half2float(h3.y));
            }
            #pragma unroll
            for (int ng = 0; ng < 8; ng++) {
                int k_row = ks * 16 + (lane & 15);
                int c16v = ng * 2 + (lane >> 4);
                uint32_t off = k_row * 256 + (((uint32_t)(c16v ^ (k_row & 7))) << 4);
                uint32_t v0, v1, v2, v3;
                LDSM4T(v0, v1, v2, v3, sVh + off);
                uint32_t bh0[2] = {v0, v1}, bh1[2] = {v2, v3};
                MMA16816(oacc[ng * 2],     ph, bh0);
                MMA16816(oacc[ng * 2],     pl, bh0);
                MMA16816(oacc[ng * 2 + 1], ph, bh1);
                MMA16816(oacc[ng * 2 + 1], pl, bh1);
            }
        }
        __syncthreads();
    }

    float inv0 = 1.0f / l0, inv8 = 1.0f / l8;
    #pragma unroll
    for (int j = 0; j < 16; j++) {
        int gcol = h * HD_ + j * 8 + cc;
        int r0 = q0 + wrow + cr;
        size_t o0 = (size_t)(b * SQ_ + r0) * D_ + gcol;
        size_t o8 = o0 + (size_t)8 * D_;
        *(uint32_t*)(Oh + o0) = pack2h(oacc[j][0] * inv0, oacc[j][1] * inv0);
        *(uint32_t*)(Oh + o8) = pack2h(oacc[j][2] * inv8, oacc[j][3] * inv8);
    }
}

// ---------------- launcher ----------------
extern "C" void kernel_launch(void* const* d_in, const int* in_sizes, int n_in,
                              void* d_out, int out_size) {
    const float* x     = (const float*)d_in[0];
    const float* pkv   = (const float*)d_in[1];
    const float* skv   = (const float*)d_in[2];
    const float* mkv   = (const float*)d_in[3];
    const float* qmask = (const float*)d_in[4];
    const float* pmask = (const float*)d_in[5];
    const float* smask = (const float*)d_in[6];
    const float* mmask = (const float*)d_in[7];
    const float* rmsw  = (const float*)d_in[8];
    const float* Wq  = (const float*)d_in[9];   const float* bq  = (const float*)d_in[10];
    const float* Wkp = (const float*)d_in[11];  const float* bkp = (const float*)d_in[12];
    const float* Wvp = (const float*)d_in[13];  const float* bvp = (const float*)d_in[14];
    const float* Wks = (const float*)d_in[15];  const float* bks = (const float*)d_in[16];
    const float* Wvs = (const float*)d_in[17];  const float* bvs = (const float*)d_in[18];
    const float* Wkm = (const float*)d_in[19];  const float* bkm = (const float*)d_in[20];
    const float* Wvm = (const float*)d_in[21];  const float* bvm = (const float*)d_in[22];
    const float* Wo  = (const float*)d_in[23];  const float* bo  = (const float*)d_in[24];
    const float* lng = (const float*)d_in[25];  const float* lnb = (const float*)d_in[26];
    const float* W1  = (const float*)d_in[27];  const float* W2  = (const float*)d_in[28];
    const float* ga  = (const float*)d_in[29];  const float* gf  = (const float*)d_in[30];
    float* out = (float*)d_out;

    float *hh, *kvm;
    cudaGetSymbolAddress((void**)&hh,  g_h);
    cudaGetSymbolAddress((void**)&kvm, g_kvmask);

    hlf *qn,*ap,*as,*am,*qh,*ql,*kh,*kl,*vh,*cxh,*lnh,*ffh;
    cudaGetSymbolAddress((void**)&qn,  g_qn);
    cudaGetSymbolAddress((void**)&ap,  g_ap);
    cudaGetSymbolAddress((void**)&as,  g_as);
    cudaGetSymbolAddress((void**)&am,  g_am);
    cudaGetSymbolAddress((void**)&qh,  g_qh);    cudaGetSymbolAddress((void**)&ql,  g_ql);
    cudaGetSymbolAddress((void**)&kh,  g_kh);    cudaGetSymbolAddress((void**)&kl,  g_kl);
    cudaGetSymbolAddress((void**)&vh,  g_vh);
    cudaGetSymbolAddress((void**)&cxh, g_cx_h);
    cudaGetSymbolAddress((void**)&lnh, g_ln_h);
    cudaGetSymbolAddress((void**)&ffh, g_ff_h);

    hlf *tWqh,*tWql,*tWkph,*tWkpl,*tWvph,*tWvpl,*tWksh,*tWksl,*tWvsh,*tWvsl;
    hlf *tWkmh,*tWkml,*tWvmh,*tWvml,*tWoh,*tWol,*tW1h,*tW1l,*tW2h,*tW2l;
    cudaGetSymbolAddress((void**)&tWqh,  g_Wq_h);   cudaGetSymbolAddress((void**)&tWql,  g_Wq_l);
    cudaGetSymbolAddress((void**)&tWkph, g_Wkp_h);  cudaGetSymbolAddress((void**)&tWkpl, g_Wkp_l);
    cudaGetSymbolAddress((void**)&tWvph, g_Wvp_h);  cudaGetSymbolAddress((void**)&tWvpl, g_Wvp_l);
    cudaGetSymbolAddress((void**)&tWksh, g_Wks_h);  cudaGetSymbolAddress((void**)&tWksl, g_Wks_l);
    cudaGetSymbolAddress((void**)&tWvsh, g_Wvs_h);  cudaGetSymbolAddress((void**)&tWvsl, g_Wvs_l);
    cudaGetSymbolAddress((void**)&tWkmh, g_Wkm_h);  cudaGetSymbolAddress((void**)&tWkml, g_Wkm_l);
    cudaGetSymbolAddress((void**)&tWvmh, g_Wvm_h);  cudaGetSymbolAddress((void**)&tWvml, g_Wvm_l);
    cudaGetSymbolAddress((void**)&tWoh,  g_Wo_h);   cudaGetSymbolAddress((void**)&tWol,  g_Wo_l);
    cudaGetSymbolAddress((void**)&tW1h,  g_W1_h);   cudaGetSymbolAddress((void**)&tW1l,  g_W1_l);
    cudaGetSymbolAddress((void**)&tW2h,  g_W2_h);   cudaGetSymbolAddress((void**)&tW2l,  g_W2_l);

    cudaFuncSetAttribute(gemm2<2>, cudaFuncAttributeMaxDynamicSharedMemorySize, GEMM2_SMEM);
    cudaFuncSetAttribute(gemm2<3>, cudaFuncAttributeMaxDynamicSharedMemorySize, GEMM2_SMEM);
    cudaFuncSetAttribute(gemm2<4>, cudaFuncAttributeMaxDynamicSharedMemorySize, GEMM2_SMEM);
    cudaFuncSetAttribute(gemm2<5>, cudaFuncAttributeMaxDynamicSharedMemorySize, GEMM2_SMEM);
    cudaFuncSetAttribute(gemm2<6>, cudaFuncAttributeMaxDynamicSharedMemorySize, GEMM2_SMEM);
    cudaFuncSetAttribute(attn_fa2, cudaFuncAttributeMaxDynamicSharedMemorySize, ATTN_SMEM);

    // weight transpose+split
    wsplit_T<<<dim3(D_ / 64,     D_ / 64),     256>>>(Wq,  tWqh,  tWql,  D_,     D_);
    wsplit_T<<<dim3(D_ / 64,     DP_ / 64),    256>>>(Wkp, tWkph, tWkpl, DP_,    D_);
    wsplit_T<<<dim3(D_ / 64,     DP_ / 64),    256>>>(Wvp, tWvph, tWvpl, DP_,    D_);
    wsplit_T<<<dim3(D_ / 64,     DS_ / 64),    256>>>(Wks, tWksh, tWksl, DS_,    D_);
    wsplit_T<<<dim3(D_ / 64,     DS_ / 64),    256>>>(Wvs, tWvsh, tWvsl, DS_,    D_);
    wsplit_T<<<dim3(D_ / 64,     DM_ / 64),    256>>>(Wkm, tWkmh, tWkml, DM_,    D_);
    wsplit_T<<<dim3(D_ / 64,     DM_ / 64),    256>>>(Wvm, tWvmh, tWvml, DM_,    D_);
    wsplit_T<<<dim3(D_ / 64,     D_ / 64),     256>>>(Wo,  tWoh,  tWol,  D_,     D_);
    wsplit_T<<<dim3(INNER_ / 64, D_ / 64),     256>>>(W1,  tW1h,  tW1l,  D_,     INNER_);
    wsplit_T<<<dim3(D_ / 64,     INNER_ / 64), 256>>>(W2,  tW2h,  tW2l,  INNER_, D_);

    // activation packs + mask concat
    rmsnorm_h<<<B_ * SQ_, 256>>>(x, rmsw, qn);
    pack_k<<<(B_ * SP_ * DP_ / 4 + 255) / 256, 256>>>(pkv, ap, B_ * SP_ * DP_ / 4);
    pack_k<<<(B_ * SS_ * DS_ / 4 + 255) / 256, 256>>>(skv, as, B_ * SS_ * DS_ / 4);
    pack_k<<<(B_ * SM_ * DM_ / 4 + 255) / 256, 256>>>(mkv, am, B_ * SM_ * DM_ / 4);
    maskcat_k<<<(B_ * SKV_ + 255) / 256, 256>>>(pmask, smask, mmask, kvm);

    // Q/K projections (2-term, hi/lo out, remap). Q: scale 0.25 folded.
    gemm2<5><<<dim3(16, 16), 256, GEMM2_SMEM>>>(qn, tWqh, tWql, bq, nullptr, nullptr,
        nullptr, qh, ql, 2048, 2048, 2048, 0.25f, 10, 1024, 0);
    gemm2<5><<<dim3(16, 16), 256, GEMM2_SMEM>>>(ap, tWkph, tWkpl, bkp, nullptr, nullptr,
        nullptr, kh, kl, 2048, 2048, 1280, 1.f, 10, SKV_, 0);
    gemm2<5><<<dim3(16, 16), 256, GEMM2_SMEM>>>(as, tWksh, tWksl, bks, nullptr, nullptr,
        nullptr, kh, kl, 2048, 2048, 1024, 1.f, 10, SKV_, SP_);
    gemm2<5><<<dim3(16, 8), 256, GEMM2_SMEM>>>(am, tWkmh, tWkml, bkm, nullptr, nullptr,
        nullptr, kh, kl, 1024, 2048, 768, 1.f, 9, SKV_, SP_ + SS_);

    // V projections (2-term, single out, remap)
    gemm2<6><<<dim3(16, 16), 256, GEMM2_SMEM>>>(ap, tWvph, tWvpl, bvp, nullptr, nullptr,
        nullptr, vh, nullptr, 2048, 2048, 1280, 1.f, 10, SKV_, 0);
    gemm2<6><<<dim3(16, 16), 256, GEMM2_SMEM>>>(as, tWvsh, tWvsl, bvs, nullptr, nullptr,
        nullptr, vh, nullptr, 2048, 2048, 1024, 1.f, 10, SKV_, SP_);
    gemm2<6><<<dim3(16, 8), 256, GEMM2_SMEM>>>(am, tWvmh, tWvml, bvm, nullptr, nullptr,
        nullptr, vh, nullptr, 1024, 2048, 768, 1.f, 9, SKV_, SP_ + SS_);

    // attention -> ctx single fp16
    attn_fa2<<<dim3(8, 16, 2), 256, ATTN_SMEM>>>(qh, ql, kh, kl, vh,
                                                 qmask, kvm, cxh);

    // h = x + tanh(ga)*(ctx@Wo + bo)   (2-term)
    gemm2<2><<<dim3(16, 16), 256, GEMM2_SMEM>>>(cxh, tWoh, tWol, bo, x, ga,
        hh, nullptr, nullptr, 2048, 2048, 2048, 1.f, 0, 0, 0);

    // LayerNorm -> single fp16
    layernorm_h<<<B_ * SQ_, 256>>>(hh, lng, lnb, lnh);

    // FFW (2-term)
    gemm2<3><<<dim3(64, 16), 256, GEMM2_SMEM>>>(lnh, tW1h, tW1l, nullptr, nullptr, nullptr,
        nullptr, ffh, nullptr, 2048, INNER_, 2048, 1.f, 0, 0, 0);
    gemm2<4><<<dim3(16, 16), 256, GEMM2_SMEM>>>(ffh, tW2h, tW2l, nullptr, hh, gf,
        out, nullptr, nullptr, 2048, 2048, INNER_, 1.f, 0, 0, 0);
}

// round 10
// speedup vs baseline: 1.7441x; 1.0642x over previous
#include <cuda_runtime.h>
#include <cuda_fp16.h>
#include <math.h>
#include <stdint.h>

typedef __half hlf;

// ---------------- problem dims ----------------
#define B_    2
#define SQ_   1024
#define D_    2048
#define H_    16
#define HD_   128
#define SP_   1024
#define SS_   1024
#define SM_   512
#define SKV_  2560
#define DP_   1280
#define DS_   1024
#define DM_   768
#define INNER_ 8192

// ---------------- scratch (device globals; no allocations) ----------------
__device__ float g_h  [B_*SQ_*D_];
__device__ float g_kvmask[B_*SKV_];
__device__ hlf g_qn  [B_*SQ_*D_];
__device__ hlf g_ap  [B_*SP_*DP_];
__device__ hlf g_as  [B_*SS_*DS_];
__device__ hlf g_am  [B_*SM_*DM_];
__device__ hlf g_qh  [B_*SQ_*D_];
__device__ hlf g_kh  [B_*SKV_*D_];  __device__ hlf g_kl  [B_*SKV_*D_];
__device__ hlf g_vh  [B_*SKV_*D_];
__device__ hlf g_cx_h[B_*SQ_*D_];
__device__ hlf g_ln_h[B_*SQ_*D_];
__device__ hlf g_ff_h[B_*SQ_*INNER_];
__device__ hlf g_Wq_h [D_*D_];       __device__ hlf g_Wq_l [D_*D_];
__device__ hlf g_Wkp_h[D_*DP_];      __device__ hlf g_Wkp_l[D_*DP_];
__device__ hlf g_Wvp_h[D_*DP_];      __device__ hlf g_Wvp_l[D_*DP_];
__device__ hlf g_Wks_h[D_*DS_];      __device__ hlf g_Wks_l[D_*DS_];
__device__ hlf g_Wvs_h[D_*DS_];      __device__ hlf g_Wvs_l[D_*DS_];
__device__ hlf g_Wkm_h[D_*DM_];      __device__ hlf g_Wkm_l[D_*DM_];
__device__ hlf g_Wvm_h[D_*DM_];      __device__ hlf g_Wvm_l[D_*DM_];
__device__ hlf g_Wo_h [D_*D_];       __device__ hlf g_Wo_l [D_*D_];
__device__ hlf g_W1_h [INNER_*D_];   __device__ hlf g_W1_l [INNER_*D_];
__device__ hlf g_W2_h [D_*INNER_];   __device__ hlf g_W2_l [D_*INNER_];

// ---------------- helpers ----------------
__device__ __forceinline__ uint32_t s2u(const void* p) {
    uint32_t a;
    asm("{ .reg .u64 t; cvta.to.shared.u64 t, %1; cvt.u32.u64 %0, t; }" : "=r"(a) : "l"(p));
    return a;
}
__device__ __forceinline__ void cp16(uint32_t s, const void* g) {
    asm volatile("cp.async.cg.shared.global [%0], [%1], 16;" :: "r"(s), "l"(g) : "memory");
}
#define LDSM4(r0, r1, r2, r3, addr) \
    asm volatile("ldmatrix.sync.aligned.m8n8.x4.shared.b16 {%0,%1,%2,%3}, [%4];" \
                 : "=r"(r0), "=r"(r1), "=r"(r2), "=r"(r3) : "r"(addr))
#define LDSM4T(r0, r1, r2, r3, addr) \
    asm volatile("ldmatrix.sync.aligned.m8n8.x4.trans.shared.b16 {%0,%1,%2,%3}, [%4];" \
                 : "=r"(r0), "=r"(r1), "=r"(r2), "=r"(r3) : "r"(addr))
#define MMA16816(d, a, b) \
    asm volatile("mma.sync.aligned.m16n8k16.row.col.f32.f16.f16.f32 " \
                 "{%0,%1,%2,%3},{%4,%5,%6,%7},{%8,%9},{%0,%1,%2,%3};" \
                 : "+f"((d)[0]), "+f"((d)[1]), "+f"((d)[2]), "+f"((d)[3]) \
                 : "r"((a)[0]), "r"((a)[1]), "r"((a)[2]), "r"((a)[3]), \
                   "r"((b)[0]), "r"((b)[1]))

__device__ __forceinline__ float gelu_f(float x) {
    return 0.5f * x * (1.0f + erff(x * 0.70710678118654752f));
}
__device__ __forceinline__ void hsplit(float v, hlf* h, hlf* l) {
    hlf hh = __float2half_rn(v);
    *h = hh;
    *l = __float2half_rn(v - __half2float(hh));
}
__device__ __forceinline__ uint32_t pack2h(float a, float b) {
    __half2 t = __floats2half2_rn(a, b);
    return *(uint32_t*)&t;
}
__device__ __forceinline__ uint2 pack4h(float4 v) {
    return make_uint2(pack2h(v.x, v.y), pack2h(v.z, v.w));
}

// ---------------- block reduce ----------------
__device__ __forceinline__ float blockReduceSum(float v) {
    __shared__ float sh[32];
    __syncthreads();
    int lane = threadIdx.x & 31, w = threadIdx.x >> 5;
    #pragma unroll
    for (int o = 16; o > 0; o >>= 1) v += __shfl_xor_sync(0xffffffffu, v, o);
    if (lane == 0) sh[w] = v;
    __syncthreads();
    float r = 0.f;
    if (threadIdx.x < (blockDim.x >> 5)) r = sh[threadIdx.x];
    if (w == 0) {
        #pragma unroll
        for (int o = 16; o > 0; o >>= 1) r += __shfl_xor_sync(0xffffffffu, r, o);
        if (lane == 0) sh[0] = r;
    }
    __syncthreads();
    return sh[0];
}

// ---------------- RMSNorm -> single fp16 ----------------
__global__ __launch_bounds__(256) void rmsnorm_h(const float* __restrict__ x,
                                                 const float* __restrict__ w,
                                                 hlf* __restrict__ yh) {
    int row = blockIdx.x;
    const float4* xr = (const float4*)(x + (size_t)row * D_);
    const float4* wr = (const float4*)w;
    float ss = 0.f;
    float4 xv[2];
    #pragma unroll
    for (int i = 0; i < 2; i++) {
        xv[i] = xr[threadIdx.x + 256 * i];
        ss += xv[i].x * xv[i].x + xv[i].y * xv[i].y + xv[i].z * xv[i].z + xv[i].w * xv[i].w;
    }
    ss = blockReduceSum(ss);
    float inv = rsqrtf(ss / (float)D_ + 1e-6f);
    uint2* yh2 = (uint2*)(yh + (size_t)row * D_);
    #pragma unroll
    for (int i = 0; i < 2; i++) {
        int t = threadIdx.x + 256 * i;
        float4 wv = wr[t];
        float4 v = make_float4(xv[i].x * inv * wv.x, xv[i].y * inv * wv.y,
                               xv[i].z * inv * wv.z, xv[i].w * inv * wv.w);
        yh2[t] = pack4h(v);
    }
}

// ---------------- LayerNorm -> single fp16 ----------------
__global__ __launch_bounds__(256) void layernorm_h(const float* __restrict__ x,
                                                   const float* __restrict__ gg,
                                                   const float* __restrict__ bb,
                                                   hlf* __restrict__ yh) {
    int row = blockIdx.x;
    const float4* xr = (const float4*)(x + (size_t)row * D_);
    float4 xv[2];
    float s = 0.f;
    #pragma unroll
    for (int i = 0; i < 2; i++) {
        xv[i] = xr[threadIdx.x + 256 * i];
        s += xv[i].x + xv[i].y + xv[i].z + xv[i].w;
    }
    s = blockReduceSum(s);
    float mu = s / (float)D_;
    float vs = 0.f;
    #pragma unroll
    for (int i = 0; i < 2; i++) {
        float dx = xv[i].x - mu, dy = xv[i].y - mu, dz = xv[i].z - mu, dw = xv[i].w - mu;
        vs += dx * dx + dy * dy + dz * dz + dw * dw;
    }
    vs = blockReduceSum(vs);
    float inv = rsqrtf(vs / (float)D_ + 1e-5f);
    uint2* yh2 = (uint2*)(yh + (size_t)row * D_);
    #pragma unroll
    for (int i = 0; i < 2; i++) {
        int t = threadIdx.x + 256 * i;
        float4 gv = ((const float4*)gg)[t];
        float4 bv = ((const float4*)bb)[t];
        float4 v = make_float4((xv[i].x - mu) * inv * gv.x + bv.x,
                               (xv[i].y - mu) * inv * gv.y + bv.y,
                               (xv[i].z - mu) * inv * gv.z + bv.z,
                               (xv[i].w - mu) * inv * gv.w + bv.w);
        yh2[t] = pack4h(v);
    }
}

// fp32 -> single fp16 pack (n multiple of 4)
__global__ __launch_bounds__(256) void pack_k(const float* __restrict__ x,
                                              hlf* __restrict__ h, int n4) {
    int i = blockIdx.x * 256 + threadIdx.x;
    if (i >= n4) return;
    float4 v = ((const float4*)x)[i];
    ((uint2*)h)[i] = pack4h(v);
}

__global__ __launch_bounds__(256) void maskcat_k(const float* __restrict__ pm,
                                                 const float* __restrict__ sm,
                                                 const float* __restrict__ mm,
                                                 float* __restrict__ out) {
    int i = blockIdx.x * 256 + threadIdx.x;
    if (i >= B_ * SKV_) return;
    int b = i / SKV_, s = i % SKV_;
    float v;
    if (s < SP_) v = pm[b * SP_ + s];
    else if (s < SP_ + SS_) v = sm[b * SS_ + s - SP_];
    else v = mm[b * SM_ + s - SP_ - SS_];
    out[i] = v;
}

// ---------------- weight transpose+split: W[K,N] -> T[N,K] hi/lo ----------------
__global__ __launch_bounds__(256) void wsplit_T(const float* __restrict__ W,
                                                hlf* __restrict__ Th,
                                                hlf* __restrict__ Tl,
                                                int K, int N) {
    __shared__ float tile[64][65];
    const int tid = threadIdx.x;
    const int n0 = blockIdx.x * 64, k0 = blockIdx.y * 64;
    #pragma unroll
    for (int i = 0; i < 4; i++) {
        int idx = tid + 256 * i;
        int r = idx >> 4, c4 = (idx & 15) * 4;
        float4 v = *(const float4*)&W[(size_t)(k0 + r) * N + n0 + c4];
        tile[r][c4] = v.x; tile[r][c4 + 1] = v.y;
        tile[r][c4 + 2] = v.z; tile[r][c4 + 3] = v.w;
    }
    __syncthreads();
    #pragma unroll
    for (int i = 0; i < 2; i++) {
        int idx = tid + 256 * i;
        int n = idx >> 3, kc = (idx & 7) * 8;
        float v0 = tile[kc + 0][n], v1 = tile[kc + 1][n];
        float v2 = tile[kc + 2][n], v3 = tile[kc + 3][n];
        float v4 = tile[kc + 4][n], v5 = tile[kc + 5][n];
        float v6 = tile[kc + 6][n], v7 = tile[kc + 7][n];
        uint32_t h0 = pack2h(v0, v1), h1 = pack2h(v2, v3);
        uint32_t h2 = pack2h(v4, v5), h3 = pack2h(v6, v7);
        __half2 b0 = *(__half2*)&h0, b1 = *(__half2*)&h1;
        __half2 b2 = *(__half2*)&h2, b3 = *(__half2*)&h3;
        uint32_t l0 = pack2h(v0 - __half2float(b0.x), v1 - __half2float(b0.y));
        uint32_t l1 = pack2h(v2 - __half2float(b1.x), v3 - __half2float(b1.y));
        uint32_t l2 = pack2h(v4 - __half2float(b2.x), v5 - __half2float(b2.y));
        uint32_t l3 = pack2h(v6 - __half2float(b3.x), v7 - __half2float(b3.y));
        size_t o = (size_t)(n0 + n) * K + k0 + kc;
        *(uint4*)(Th + o) = make_uint4(h0, h1, h2, h3);
        *(uint4*)(Tl + o) = make_uint4(l0, l1, l2, l3);
    }
}

// ============== 2-term GEMM (A single fp16, B hi/lo): BM=128, BN=128, BK=64 ==============
// EPI 2: Cf = res + tanh(gate)*(acc + bias)
// EPI 3: Ch = fp16(gelu(acc))
// EPI 4: Cf = res + tanh(gate)*acc
// EPI 5: Ch/Cl = hsplit((acc+bias)*scale), row remap (K concat)
// EPI 6: Ch = fp16((acc+bias)*scale), row remap (Q/V concat)
#define GB_K 64
#define STG2 49152
#define GEMM2_SMEM (2 * STG2)

template <int EPI>
__global__ __launch_bounds__(256, 2) void gemm2(
    const hlf* __restrict__ Ah,
    const hlf* __restrict__ Bh, const hlf* __restrict__ Bl,
    const float* __restrict__ bias, const float* __restrict__ res,
    const float* __restrict__ gate,
    float* __restrict__ Cf, hlf* __restrict__ Ch, hlf* __restrict__ Cl,
    int M, int N, int K, float scale, int oShift, int oStride, int oOff) {
    extern __shared__ __align__(1024) char smem[];
    uint32_t sb = s2u(smem);
    const int tid = threadIdx.x, wid = tid >> 5, lane = tid & 31;
    const int n0 = blockIdx.x * 128, m0 = blockIdx.y * 128;
    const int wm0 = (wid >> 2) * 64;
    const int wn0 = (wid & 3) * 32;

    auto stage_load = [&](int st, int k0) {
        uint32_t s0 = sb + st * STG2;
        #pragma unroll
        for (int i = 0; i < 4; i++) {
            int idx = tid + 256 * i;
            int r = idx >> 3, c = idx & 7;
            uint32_t byte = r * 128 + c * 16;
            uint32_t sw = byte ^ ((byte >> 3) & 0x70);
            size_t goA = (size_t)(m0 + r) * K + k0 + c * 8;
            size_t goB = (size_t)(n0 + r) * K + k0 + c * 8;
            cp16(s0 + sw,         Ah + goA);
            cp16(s0 + 16384 + sw, Bh + goB);
            cp16(s0 + 32768 + sw, Bl + goB);
        }
        asm volatile("cp.async.commit_group;" ::: "memory");
    };

    float acc[4][4][4];
    #pragma unroll
    for (int i = 0; i < 4; i++)
        #pragma unroll
        for (int j = 0; j < 4; j++)
            #pragma unroll
            for (int c = 0; c < 4; c++) acc[i][j][c] = 0.f;

    const int nIter = K / GB_K;
    stage_load(0, 0);

    const int a_row = lane & 15;
    const int a_ch  = lane >> 4;
    const int b_row = (lane & 7) + ((lane >> 4) & 1) * 8;
    const int b_ch  = (lane >> 3) & 1;

    for (int it = 0; it < nIter; ++it) {
        if (it + 1 < nIter) stage_load((it + 1) & 1, (it + 1) * GB_K);
        if (it + 1 < nIter) {
            asm volatile("cp.async.wait_group 1;" ::: "memory");
        } else {
            asm volatile("cp.async.wait_group 0;" ::: "memory");
        }
        __syncthreads();

        uint32_t s0 = sb + (it & 1) * STG2;
        uint32_t sAh = s0, sBh = s0 + 16384, sBl = s0 + 32768;

        #pragma unroll
        for (int ks = 0; ks < 4; ks++) {
            uint32_t ahi[4][4], bhi[4][2], blo[4][2];
            #pragma unroll
            for (int i = 0; i < 4; i++) {
                uint32_t byte = (wm0 + i * 16 + a_row) * 128 + (ks * 2 + a_ch) * 16;
                uint32_t sw = byte ^ ((byte >> 3) & 0x70);
                LDSM4(ahi[i][0], ahi[i][1], ahi[i][2], ahi[i][3], sAh + sw);
            }
            #pragma unroll
            for (int jj = 0; jj < 2; jj++) {
                uint32_t byte = (wn0 + jj * 16 + b_row) * 128 + (ks * 2 + b_ch) * 16;
                uint32_t sw = byte ^ ((byte >> 3) & 0x70);
                uint32_t r0, r1, r2, r3;
                LDSM4(r0, r1, r2, r3, sBh + sw);
                bhi[jj * 2][0] = r0; bhi[jj * 2][1] = r1;
                bhi[jj * 2 + 1][0] = r2; bhi[jj * 2 + 1][1] = r3;
                LDSM4(r0, r1, r2, r3, sBl + sw);
                blo[jj * 2][0] = r0; blo[jj * 2][1] = r1;
                blo[jj * 2 + 1][0] = r2; blo[jj * 2 + 1][1] = r3;
            }
            #pragma unroll
            for (int i = 0; i < 4; i++)
                #pragma unroll
                for (int j = 0; j < 4; j++) {
                    MMA16816(acc[i][j], ahi[i], bhi[j]);
                    MMA16816(acc[i][j], ahi[i], blo[j]);
                }
        }
        __syncthreads();
    }

    float gt = 0.f;
    if (EPI == 2 || EPI == 4) gt = tanhf(gate[0]);
    const int cr = lane >> 2;
    const int cc = (lane & 3) * 2;

    #pragma unroll
    for (int i = 0; i < 4; i++) {
        #pragma unroll
        for (int j = 0; j < 4; j++) {
            int gcol = n0 + wn0 + j * 8 + cc;
            #pragma unroll
            for (int half = 0; half < 2; half++) {
                int grow = m0 + wm0 + i * 16 + cr + half * 8;
                float v0 = acc[i][j][half * 2 + 0];
                float v1 = acc[i][j][half * 2 + 1];
                size_t o = (size_t)grow * N + gcol;
                if (EPI == 2) {
                    float2 rr = *(const float2*)(res + o);
                    *(float2*)(Cf + o) = make_float2(rr.x + gt * (v0 + bias[gcol]),
                                                     rr.y + gt * (v1 + bias[gcol + 1]));
                } else if (EPI == 3) {
                    *(uint32_t*)(Ch + o) = pack2h(gelu_f(v0), gelu_f(v1));
                } else if (EPI == 4) {
                    float2 rr = *(const float2*)(res + o);
                    *(float2*)(Cf + o) = make_float2(rr.x + gt * v0, rr.y + gt * v1);
                } else if (EPI == 5) {
                    int ib = grow >> oShift;
                    int ir = grow & ((1 << oShift) - 1);
                    size_t oo = ((size_t)ib * oStride + oOff + ir) * N + gcol;
                    float a0 = (v0 + bias[gcol]) * scale;
                    float a1 = (v1 + bias[gcol + 1]) * scale;
                    hlf h0, l0, h1, l1;
                    hsplit(a0, &h0, &l0);
                    hsplit(a1, &h1, &l1);
                    *(__half2*)(Ch + oo) = __half2(h0, h1);
                    *(__half2*)(Cl + oo) = __half2(l0, l1);
                } else {  // EPI 6
                    int ib = grow >> oShift;
                    int ir = grow & ((1 << oShift) - 1);
                    size_t oo = ((size_t)ib * oStride + oOff + ir) * N + gcol;
                    *(uint32_t*)(Ch + oo) = pack2h((v0 + bias[gcol]) * scale,
                                                   (v1 + bias[gcol + 1]) * scale);
                }
            }
        }
    }
}

// ---------------- register-resident FA2 attention (Q single, K hi/lo, P/V single) ----------------
// smem: Q 32K | 2 stages x (Kh 16K | Kl 16K | Vh 16K | mask 256B)
#define AQ_H 0u
#define AKV  32768u
#define AST  49408u
#define ATTN_SMEM (32768 + 2 * 49408)

__global__ __launch_bounds__(256) void attn_fa2(
    const hlf* __restrict__ Qh,
    const hlf* __restrict__ Kh, const hlf* __restrict__ Kl,
    const hlf* __restrict__ Vh,
    const float* __restrict__ qmask, const float* __restrict__ kvmask,
    hlf* __restrict__ Oh) {
    extern __shared__ __align__(1024) char smem[];
    uint32_t sb = s2u(smem);

    const int qt = blockIdx.x, h = blockIdx.y, b = blockIdx.z;
    const int q0 = qt * 128;
    const int tid = threadIdx.x, wid = tid >> 5, lane = tid & 31;
    const int wrow = wid * 16;
    const int a_row = lane & 15, a_ch = lane >> 4;
    const int b_row = (lane & 7) + ((lane >> 4) & 1) * 8;
    const int b_ch  = (lane >> 3) & 1;
    const int cr = lane >> 2, cc = (lane & 3) * 2;

    auto kv_load = [&](int st, int t) {
        uint32_t s0 = sb + AKV + st * AST;
        int kv0 = t * 64;
        #pragma unroll
        for (int i = 0; i < 4; i++) {
            int idx = tid + 256 * i;
            int r = idx >> 4, c16 = idx & 15;
            uint32_t off = r * 256 + (((uint32_t)(c16 ^ (r & 7))) << 4);
            size_t go = (size_t)(b * SKV_ + kv0 + r) * D_ + h * HD_ + c16 * 8;
            cp16(s0 + off,          Kh + go);
            cp16(s0 + 16384 + off,  Kl + go);
            cp16(s0 + 32768 + off,  Vh + go);
        }
        if (tid < 16)
            cp16(s0 + 49152 + tid * 16, kvmask + b * SKV_ + t * 64 + tid * 4);
        asm volatile("cp.async.commit_group;" ::: "memory");
    };

    #pragma unroll
    for (int i = 0; i < 8; i++) {
        int idx = tid + 256 * i;
        int r = idx >> 4, c16 = idx & 15;
        uint32_t off = r * 256 + (((uint32_t)(c16 ^ (r & 7))) << 4);
        size_t go = (size_t)(b * SQ_ + q0 + r) * D_ + h * HD_ + c16 * 8;
        cp16(sb + AQ_H + off, Qh + go);
    }
    asm volatile("cp.async.commit_group;" ::: "memory");
    kv_load(0, 0);
    asm volatile("cp.async.wait_group 0;" ::: "memory");
    __syncthreads();

    uint32_t qhf[8][4];
    #pragma unroll
    for (int ks = 0; ks < 8; ks++) {
        int row = wrow + a_row;
        int c16 = ks * 2 + a_ch;
        uint32_t off = row * 256 + (((uint32_t)(c16 ^ (row & 7))) << 4);
        LDSM4(qhf[ks][0], qhf[ks][1], qhf[ks][2], qhf[ks][3], sb + AQ_H + off);
    }

    const float qm0 = qmask[b * SQ_ + q0 + wrow + cr];
    const float qm8 = qmask[b * SQ_ + q0 + wrow + cr + 8];

    float m0 = -1e30f, m8 = -1e30f, l0 = 0.f, l8 = 0.f;
    float oacc[16][4];
    #pragma unroll
    for (int j = 0; j < 16; j++)
        #pragma unroll
        for (int c = 0; c < 4; c++) oacc[j][c] = 0.f;

    const int T = SKV_ / 64;
    for (int t = 0; t < T; ++t) {
        if (t + 1 < T) kv_load((t + 1) & 1, t + 1);
        if (t + 1 < T) {
            asm volatile("cp.async.wait_group 1;" ::: "memory");
        } else {
            asm volatile("cp.async.wait_group 0;" ::: "memory");
        }
        __syncthreads();

        uint32_t s0 = sb + AKV + (t & 1) * AST;
        uint32_t sKh = s0, sKl = s0 + 16384, sVh = s0 + 32768;
        const float* msk = (const float*)(smem + AKV + (t & 1) * AST + 49152);

        float sacc[8][4];
        #pragma unroll
        for (int j = 0; j < 8; j++)
            #pragma unroll
            for (int c = 0; c < 4; c++) sacc[j][c] = 0.f;

        #pragma unroll
        for (int ks = 0; ks < 8; ks++) {
            #pragma unroll
            for (int jj = 0; jj < 4; jj++) {
                int row = jj * 16 + b_row;
                int c16 = ks * 2 + b_ch;
                uint32_t off = row * 256 + (((uint32_t)(c16 ^ (row & 7))) << 4);
                uint32_t k0, k1, k2, k3, e0, e1, e2, e3;
                LDSM4(k0, k1, k2, k3, sKh + off);
                LDSM4(e0, e1, e2, e3, sKl + off);
                uint32_t bh0[2] = {k0, k1}, bh1[2] = {k2, k3};
                uint32_t bl0[2] = {e0, e1}, bl1[2] = {e2, e3};
                MMA16816(sacc[jj * 2],     qhf[ks], bh0);
                MMA16816(sacc[jj * 2],     qhf[ks], bl0);
                MMA16816(sacc[jj * 2 + 1], qhf[ks], bh1);
                MMA16816(sacc[jj * 2 + 1], qhf[ks], bl1);
            }
        }

        #pragma unroll
        for (int j = 0; j < 8; j++) {
            float2 km = *(const float2*)&msk[j * 8 + cc];
            if (qm0 == 0.f || km.x == 0.f) sacc[j][0] = -3.0e38f;
            if (qm0 == 0.f || km.y == 0.f) sacc[j][1] = -3.0e38f;
            if (qm8 == 0.f || km.x == 0.f) sacc[j][2] = -3.0e38f;
            if (qm8 == 0.f || km.y == 0.f) sacc[j][3] = -3.0e38f;
        }
        float mx0 = sacc[0][0], mx8 = sacc[0][2];
        #pragma unroll
        for (int j = 0; j < 8; j++) {
            mx0 = fmaxf(mx0, fmaxf(sacc[j][0], sacc[j][1]));
            mx8 = fmaxf(mx8, fmaxf(sacc[j][2], sacc[j][3]));
        }
        mx0 = fmaxf(mx0, __shfl_xor_sync(0xffffffffu, mx0, 1));
        mx0 = fmaxf(mx0, __shfl_xor_sync(0xffffffffu, mx0, 2));
        mx8 = fmaxf(mx8, __shfl_xor_sync(0xffffffffu, mx8, 1));
        mx8 = fmaxf(mx8, __shfl_xor_sync(0xffffffffu, mx8, 2));
        float m0n = fmaxf(m0, mx0), m8n = fmaxf(m8, mx8);
        float al0 = __expf(m0 - m0n), al8 = __expf(m8 - m8n);
        float sum0 = 0.f, sum8 = 0.f;
        #pragma unroll
        for (int j = 0; j < 8; j++) {
            sacc[j][0] = __expf(sacc[j][0] - m0n);
            sacc[j][1] = __expf(sacc[j][1] - m0n);
            sacc[j][2] = __expf(sacc[j][2] - m8n);
            sacc[j][3] = __expf(sacc[j][3] - m8n);
            sum0 += sacc[j][0] + sacc[j][1];
            sum8 += sacc[j][2] + sacc[j][3];
        }
        sum0 += __shfl_xor_sync(0xffffffffu, sum0, 1);
        sum0 += __shfl_xor_sync(0xffffffffu, sum0, 2);
        sum8 += __shfl_xor_sync(0xffffffffu, sum8, 1);
        sum8 += __shfl_xor_sync(0xffffffffu, sum8, 2);
        l0 = l0 * al0 + sum0; l8 = l8 * al8 + sum8;
        m0 = m0n; m8 = m8n;

        #pragma unroll
        for (int j = 0; j < 16; j++) {
            oacc[j][0] *= al0; oacc[j][1] *= al0;
            oacc[j][2] *= al8; oacc[j][3] *= al8;
        }

        // O += P @ V (P single fp16, V single)
        #pragma unroll
        for (int ks = 0; ks < 4; ks++) {
            uint32_t ph[4];
            ph[0] = pack2h(sacc[ks * 2][0],     sacc[ks * 2][1]);
            ph[1] = pack2h(sacc[ks * 2][2],     sacc[ks * 2][3]);
            ph[2] = pack2h(sacc[ks * 2 + 1][0], sacc[ks * 2 + 1][1]);
            ph[3] = pack2h(sacc[ks * 2 + 1][2], sacc[ks * 2 + 1][3]);
            #pragma unroll
            for (int ng = 0; ng < 8; ng++) {
                int k_row = ks * 16 + (lane & 15);
                int c16v = ng * 2 + (lane >> 4);
                uint32_t off = k_row * 256 + (((uint32_t)(c16v ^ (k_row & 7))) << 4);
                uint32_t v0, v1, v2, v3;
                LDSM4T(v0, v1, v2, v3, sVh + off);
                uint32_t bh0[2] = {v0, v1}, bh1[2] = {v2, v3};
                MMA16816(oacc[ng * 2],     ph, bh0);
                MMA16816(oacc[ng * 2 + 1], ph, bh1);
            }
        }
        __syncthreads();
    }

    float inv0 = 1.0f / l0, inv8 = 1.0f / l8;
    #pragma unroll
    for (int j = 0; j < 16; j++) {
        int gcol = h * HD_ + j * 8 + cc;
        int r0 = q0 + wrow + cr;
        size_t o0 = (size_t)(b * SQ_ + r0) * D_ + gcol;
        size_t o8 = o0 + (size_t)8 * D_;
        *(uint32_t*)(Oh + o0) = pack2h(oacc[j][0] * inv0, oacc[j][1] * inv0);
        *(uint32_t*)(Oh + o8) = pack2h(oacc[j][2] * inv8, oacc[j][3] * inv8);
    }
}

// ---------------- launcher ----------------
extern "C" void kernel_launch(void* const* d_in, const int* in_sizes, int n_in,
                              void* d_out, int out_size) {
    const float* x     = (const float*)d_in[0];
    const float* pkv   = (const float*)d_in[1];
    const float* skv   = (const float*)d_in[2];
    const float* mkv   = (const float*)d_in[3];
    const float* qmask = (const float*)d_in[4];
    const float* pmask = (const float*)d_in[5];
    const float* smask = (const float*)d_in[6];
    const float* mmask = (const float*)d_in[7];
    const float* rmsw  = (const float*)d_in[8];
    const float* Wq  = (const float*)d_in[9];   const float* bq  = (const float*)d_in[10];
    const float* Wkp = (const float*)d_in[11];  const float* bkp = (const float*)d_in[12];
    const float* Wvp = (const float*)d_in[13];  const float* bvp = (const float*)d_in[14];
    const float* Wks = (const float*)d_in[15];  const float* bks = (const float*)d_in[16];
    const float* Wvs = (const float*)d_in[17];  const float* bvs = (const float*)d_in[18];
    const float* Wkm = (const float*)d_in[19];  const float* bkm = (const float*)d_in[20];
    const float* Wvm = (const float*)d_in[21];  const float* bvm = (const float*)d_in[22];
    const float* Wo  = (const float*)d_in[23];  const float* bo  = (const float*)d_in[24];
    const float* lng = (const float*)d_in[25];  const float* lnb = (const float*)d_in[26];
    const float* W1  = (const float*)d_in[27];  const float* W2  = (const float*)d_in[28];
    const float* ga  = (const float*)d_in[29];  const float* gf  = (const float*)d_in[30];
    float* out = (float*)d_out;

    float *hh, *kvm;
    cudaGetSymbolAddress((void**)&hh,  g_h);
    cudaGetSymbolAddress((void**)&kvm, g_kvmask);

    hlf *qn,*ap,*as,*am,*qh,*kh,*kl,*vh,*cxh,*lnh,*ffh;
    cudaGetSymbolAddress((void**)&qn,  g_qn);
    cudaGetSymbolAddress((void**)&ap,  g_ap);
    cudaGetSymbolAddress((void**)&as,  g_as);
    cudaGetSymbolAddress((void**)&am,  g_am);
    cudaGetSymbolAddress((void**)&qh,  g_qh);
    cudaGetSymbolAddress((void**)&kh,  g_kh);    cudaGetSymbolAddress((void**)&kl,  g_kl);
    cudaGetSymbolAddress((void**)&vh,  g_vh);
    cudaGetSymbolAddress((void**)&cxh, g_cx_h);
    cudaGetSymbolAddress((void**)&lnh, g_ln_h);
    cudaGetSymbolAddress((void**)&ffh, g_ff_h);

    hlf *tWqh,*tWql,*tWkph,*tWkpl,*tWvph,*tWvpl,*tWksh,*tWksl,*tWvsh,*tWvsl;
    hlf *tWkmh,*tWkml,*tWvmh,*tWvml,*tWoh,*tWol,*tW1h,*tW1l,*tW2h,*tW2l;
    cudaGetSymbolAddress((void**)&tWqh,  g_Wq_h);   cudaGetSymbolAddress((void**)&tWql,  g_Wq_l);
    cudaGetSymbolAddress((void**)&tWkph, g_Wkp_h);  cudaGetSymbolAddress((void**)&tWkpl, g_Wkp_l);
    cudaGetSymbolAddress((void**)&tWvph, g_Wvp_h);  cudaGetSymbolAddress((void**)&tWvpl, g_Wvp_l);
    cudaGetSymbolAddress((void**)&tWksh, g_Wks_h);  cudaGetSymbolAddress((void**)&tWksl, g_Wks_l);
    cudaGetSymbolAddress((void**)&tWvsh, g_Wvs_h);  cudaGetSymbolAddress((void**)&tWvsl, g_Wvs_l);
    cudaGetSymbolAddress((void**)&tWkmh, g_Wkm_h);  cudaGetSymbolAddress((void**)&tWkml, g_Wkm_l);
    cudaGetSymbolAddress((void**)&tWvmh, g_Wvm_h);  cudaGetSymbolAddress((void**)&tWvml, g_Wvm_l);
    cudaGetSymbolAddress((void**)&tWoh,  g_Wo_h);   cudaGetSymbolAddress((void**)&tWol,  g_Wo_l);
    cudaGetSymbolAddress((void**)&tW1h,  g_W1_h);   cudaGetSymbolAddress((void**)&tW1l,  g_W1_l);
    cudaGetSymbolAddress((void**)&tW2h,  g_W2_h);   cudaGetSymbolAddress((void**)&tW2l,  g_W2_l);

    cudaFuncSetAttribute(gemm2<2>, cudaFuncAttributeMaxDynamicSharedMemorySize, GEMM2_SMEM);
    cudaFuncSetAttribute(gemm2<3>, cudaFuncAttributeMaxDynamicSharedMemorySize, GEMM2_SMEM);
    cudaFuncSetAttribute(gemm2<4>, cudaFuncAttributeMaxDynamicSharedMemorySize, GEMM2_SMEM);
    cudaFuncSetAttribute(gemm2<5>, cudaFuncAttributeMaxDynamicSharedMemorySize, GEMM2_SMEM);
    cudaFuncSetAttribute(gemm2<6>, cudaFuncAttributeMaxDynamicSharedMemorySize, GEMM2_SMEM);
    cudaFuncSetAttribute(attn_fa2, cudaFuncAttributeMaxDynamicSharedMemorySize, ATTN_SMEM);

    // weight transpose+split
    wsplit_T<<<dim3(D_ / 64,     D_ / 64),     256>>>(Wq,  tWqh,  tWql,  D_,     D_);
    wsplit_T<<<dim3(D_ / 64,     DP_ / 64),    256>>>(Wkp, tWkph, tWkpl, DP_,    D_);
    wsplit_T<<<dim3(D_ / 64,     DP_ / 64),    256>>>(Wvp, tWvph, tWvpl, DP_,    D_);
    wsplit_T<<<dim3(D_ / 64,     DS_ / 64),    256>>>(Wks, tWksh, tWksl, DS_,    D_);
    wsplit_T<<<dim3(D_ / 64,     DS_ / 64),    256>>>(Wvs, tWvsh, tWvsl, DS_,    D_);
    wsplit_T<<<dim3(D_ / 64,     DM_ / 64),    256>>>(Wkm, tWkmh, tWkml, DM_,    D_);
    wsplit_T<<<dim3(D_ / 64,     DM_ / 64),    256>>>(Wvm, tWvmh, tWvml, DM_,    D_);
    wsplit_T<<<dim3(D_ / 64,     D_ / 64),     256>>>(Wo,  tWoh,  tWol,  D_,     D_);
    wsplit_T<<<dim3(INNER_ / 64, D_ / 64),     256>>>(W1,  tW1h,  tW1l,  D_,     INNER_);
    wsplit_T<<<dim3(D_ / 64,     INNER_ / 64), 256>>>(W2,  tW2h,  tW2l,  INNER_, D_);

    // activation packs + mask concat
    rmsnorm_h<<<B_ * SQ_, 256>>>(x, rmsw, qn);
    pack_k<<<(B_ * SP_ * DP_ / 4 + 255) / 256, 256>>>(pkv, ap, B_ * SP_ * DP_ / 4);
    pack_k<<<(B_ * SS_ * DS_ / 4 + 255) / 256, 256>>>(skv, as, B_ * SS_ * DS_ / 4);
    pack_k<<<(B_ * SM_ * DM_ / 4 + 255) / 256, 256>>>(mkv, am, B_ * SM_ * DM_ / 4);
    maskcat_k<<<(B_ * SKV_ + 255) / 256, 256>>>(pmask, smask, mmask, kvm);

    // Q projection (2-term, SINGLE out; scale 0.25 folded)
    gemm2<6><<<dim3(16, 16), 256, GEMM2_SMEM>>>(qn, tWqh, tWql, bq, nullptr, nullptr,
        nullptr, qh, nullptr, 2048, 2048, 2048, 0.25f, 10, 1024, 0);

    // K projections (2-term, hi/lo out, remap)
    gemm2<5><<<dim3(16, 16), 256, GEMM2_SMEM>>>(ap, tWkph, tWkpl, bkp, nullptr, nullptr,
        nullptr, kh, kl, 2048, 2048, 1280, 1.f, 10, SKV_, 0);
    gemm2<5><<<dim3(16, 16), 256, GEMM2_SMEM>>>(as, tWksh, tWksl, bks, nullptr, nullptr,
        nullptr, kh, kl, 2048, 2048, 1024, 1.f, 10, SKV_, SP_);
    gemm2<5><<<dim3(16, 8), 256, GEMM2_SMEM>>>(am, tWkmh, tWkml, bkm, nullptr, nullptr,
        nullptr, kh, kl, 1024, 2048, 768, 1.f, 9, SKV_, SP_ + SS_);

    // V projections (2-term, single out, remap)
    gemm2<6><<<dim3(16, 16), 256, GEMM2_SMEM>>>(ap, tWvph, tWvpl, bvp, nullptr, nullptr,
        nullptr, vh, nullptr, 2048, 2048, 1280, 1.f, 10, SKV_, 0);
    gemm2<6><<<dim3(16, 16), 256, GEMM2_SMEM>>>(as, tWvsh, tWvsl, bvs, nullptr, nullptr,
        nullptr, vh, nullptr, 2048, 2048, 1024, 1.f, 10, SKV_, SP_);
    gemm2<6><<<dim3(16, 8), 256, GEMM2_SMEM>>>(am, tWvmh, tWvml, bvm, nullptr, nullptr,
        nullptr, vh, nullptr, 1024, 2048, 768, 1.f, 9, SKV_, SP_ + SS_);

    // attention -> ctx single fp16
    attn_fa2<<<dim3(8, 16, 2), 256, ATTN_SMEM>>>(qh, kh, kl, vh,
                                                 qmask, kvm, cxh);

    // h = x + tanh(ga)*(ctx@Wo + bo)   (2-term)
    gemm2<2><<<dim3(16, 16), 256, GEMM2_SMEM>>>(cxh, tWoh, tWol, bo, x, ga,
        hh, nullptr, nullptr, 2048, 2048, 2048, 1.f, 0, 0, 0);

    // LayerNorm -> single fp16
    layernorm_h<<<B_ * SQ_, 256>>>(hh, lng, lnb, lnh);

    // FFW (2-term)
    gemm2<3><<<dim3(64, 16), 256, GEMM2_SMEM>>>(lnh, tW1h, tW1l, nullptr, nullptr, nullptr,
        nullptr, ffh, nullptr, 2048, INNER_, 2048, 1.f, 0, 0, 0);
    gemm2<4><<<dim3(16, 16), 256, GEMM2_SMEM>>>(ffh, tW2h, tW2l, nullptr, hh, gf,
        out, nullptr, nullptr, 2048, 2048, INNER_, 1.f, 0, 0, 0);
}

// round 11
// speedup vs baseline: 2.7839x; 1.5962x over previous
#include <cuda_runtime.h>
#include <cuda_fp16.h>
#include <math.h>
#include <stdint.h>

typedef __half hlf;

// ---------------- problem dims ----------------
#define B_    2
#define SQ_   1024
#define D_    2048
#define H_    16
#define HD_   128
#define SP_   1024
#define SS_   1024
#define SM_   512
#define SKV_  2560
#define DP_   1280
#define DS_   1024
#define DM_   768
#define INNER_ 8192

// ---------------- scratch (device globals; no allocations) ----------------
__device__ float g_h  [B_*SQ_*D_];
__device__ float g_kvmask[B_*SKV_];
__device__ hlf g_qn  [B_*SQ_*D_];
__device__ hlf g_ap  [B_*SP_*DP_];
__device__ hlf g_as  [B_*SS_*DS_];
__device__ hlf g_am  [B_*SM_*DM_];
__device__ hlf g_qh  [B_*SQ_*D_];
__device__ hlf g_kh  [B_*SKV_*D_];
__device__ hlf g_vh  [B_*SKV_*D_];
__device__ hlf g_cx_h[B_*SQ_*D_];
__device__ hlf g_ln_h[B_*SQ_*D_];
__device__ hlf g_ff_h[B_*SQ_*INNER_];
__device__ hlf g_Wq  [D_*D_];
__device__ hlf g_Wkp [D_*DP_];
__device__ hlf g_Wvp [D_*DP_];
__device__ hlf g_Wks [D_*DS_];
__device__ hlf g_Wvs [D_*DS_];
__device__ hlf g_Wkm [D_*DM_];
__device__ hlf g_Wvm [D_*DM_];
__device__ hlf g_Wo  [D_*D_];
__device__ hlf g_W1  [INNER_*D_];
__device__ hlf g_W2  [D_*INNER_];

// ---------------- helpers ----------------
__device__ __forceinline__ uint32_t s2u(const void* p) {
    uint32_t a;
    asm("{ .reg .u64 t; cvta.to.shared.u64 t, %1; cvt.u32.u64 %0, t; }" : "=r"(a) : "l"(p));
    return a;
}
__device__ __forceinline__ void cp16(uint32_t s, const void* g) {
    asm volatile("cp.async.cg.shared.global [%0], [%1], 16;" :: "r"(s), "l"(g) : "memory");
}
#define LDSM4(r0, r1, r2, r3, addr) \
    asm volatile("ldmatrix.sync.aligned.m8n8.x4.shared.b16 {%0,%1,%2,%3}, [%4];" \
                 : "=r"(r0), "=r"(r1), "=r"(r2), "=r"(r3) : "r"(addr))
#define LDSM4T(r0, r1, r2, r3, addr) \
    asm volatile("ldmatrix.sync.aligned.m8n8.x4.trans.shared.b16 {%0,%1,%2,%3}, [%4];" \
                 : "=r"(r0), "=r"(r1), "=r"(r2), "=r"(r3) : "r"(addr))
#define MMA16816(d, a, b) \
    asm volatile("mma.sync.aligned.m16n8k16.row.col.f32.f16.f16.f32 " \
                 "{%0,%1,%2,%3},{%4,%5,%6,%7},{%8,%9},{%0,%1,%2,%3};" \
                 : "+f"((d)[0]), "+f"((d)[1]), "+f"((d)[2]), "+f"((d)[3]) \
                 : "r"((a)[0]), "r"((a)[1]), "r"((a)[2]), "r"((a)[3]), \
                   "r"((b)[0]), "r"((b)[1]))

__device__ __forceinline__ float gelu_f(float x) {
    return 0.5f * x * (1.0f + erff(x * 0.70710678118654752f));
}
__device__ __forceinline__ uint32_t pack2h(float a, float b) {
    __half2 t = __floats2half2_rn(a, b);
    return *(uint32_t*)&t;
}
__device__ __forceinline__ uint2 pack4h(float4 v) {
    return make_uint2(pack2h(v.x, v.y), pack2h(v.z, v.w));
}

// ---------------- block reduce ----------------
__device__ __forceinline__ float blockReduceSum(float v) {
    __shared__ float sh[32];
    __syncthreads();
    int lane = threadIdx.x & 31, w = threadIdx.x >> 5;
    #pragma unroll
    for (int o = 16; o > 0; o >>= 1) v += __shfl_xor_sync(0xffffffffu, v, o);
    if (lane == 0) sh[w] = v;
    __syncthreads();
    float r = 0.f;
    if (threadIdx.x < (blockDim.x >> 5)) r = sh[threadIdx.x];
    if (w == 0) {
        #pragma unroll
        for (int o = 16; o > 0; o >>= 1) r += __shfl_xor_sync(0xffffffffu, r, o);
        if (lane == 0) sh[0] = r;
    }
    __syncthreads();
    return sh[0];
}

// ---------------- RMSNorm -> single fp16 ----------------
__global__ __launch_bounds__(256) void rmsnorm_h(const float* __restrict__ x,
                                                 const float* __restrict__ w,
                                                 hlf* __restrict__ yh) {
    int row = blockIdx.x;
    const float4* xr = (const float4*)(x + (size_t)row * D_);
    const float4* wr = (const float4*)w;
    float ss = 0.f;
    float4 xv[2];
    #pragma unroll
    for (int i = 0; i < 2; i++) {
        xv[i] = xr[threadIdx.x + 256 * i];
        ss += xv[i].x * xv[i].x + xv[i].y * xv[i].y + xv[i].z * xv[i].z + xv[i].w * xv[i].w;
    }
    ss = blockReduceSum(ss);
    float inv = rsqrtf(ss / (float)D_ + 1e-6f);
    uint2* yh2 = (uint2*)(yh + (size_t)row * D_);
    #pragma unroll
    for (int i = 0; i < 2; i++) {
        int t = threadIdx.x + 256 * i;
        float4 wv = wr[t];
        float4 v = make_float4(xv[i].x * inv * wv.x, xv[i].y * inv * wv.y,
                               xv[i].z * inv * wv.z, xv[i].w * inv * wv.w);
        yh2[t] = pack4h(v);
    }
}

// ---------------- LayerNorm -> single fp16 ----------------
__global__ __launch_bounds__(256) void layernorm_h(const float* __restrict__ x,
                                                   const float* __restrict__ gg,
                                                   const float* __restrict__ bb,
                                                   hlf* __restrict__ yh) {
    int row = blockIdx.x;
    const float4* xr = (const float4*)(x + (size_t)row * D_);
    float4 xv[2];
    float s = 0.f;
    #pragma unroll
    for (int i = 0; i < 2; i++) {
        xv[i] = xr[threadIdx.x + 256 * i];
        s += xv[i].x + xv[i].y + xv[i].z + xv[i].w;
    }
    s = blockReduceSum(s);
    float mu = s / (float)D_;
    float vs = 0.f;
    #pragma unroll
    for (int i = 0; i < 2; i++) {
        float dx = xv[i].x - mu, dy = xv[i].y - mu, dz = xv[i].z - mu, dw = xv[i].w - mu;
        vs += dx * dx + dy * dy + dz * dz + dw * dw;
    }
    vs = blockReduceSum(vs);
    float inv = rsqrtf(vs / (float)D_ + 1e-5f);
    uint2* yh2 = (uint2*)(yh + (size_t)row * D_);
    #pragma unroll
    for (int i = 0; i < 2; i++) {
        int t = threadIdx.x + 256 * i;
        float4 gv = ((const float4*)gg)[t];
        float4 bv = ((const float4*)bb)[t];
        float4 v = make_float4((xv[i].x - mu) * inv * gv.x + bv.x,
                               (xv[i].y - mu) * inv * gv.y + bv.y,
                               (xv[i].z - mu) * inv * gv.z + bv.z,
                               (xv[i].w - mu) * inv * gv.w + bv.w);
        yh2[t] = pack4h(v);
    }
}

// fp32 -> single fp16 pack (n multiple of 4)
__global__ __launch_bounds__(256) void pack_k(const float* __restrict__ x,
                                              hlf* __restrict__ h, int n4) {
    int i = blockIdx.x * 256 + threadIdx.x;
    if (i >= n4) return;
    float4 v = ((const float4*)x)[i];
    ((uint2*)h)[i] = pack4h(v);
}

__global__ __launch_bounds__(256) void maskcat_k(const float* __restrict__ pm,
                                                 const float* __restrict__ sm,
                                                 const float* __restrict__ mm,
                                                 float* __restrict__ out) {
    int i = blockIdx.x * 256 + threadIdx.x;
    if (i >= B_ * SKV_) return;
    int b = i / SKV_, s = i % SKV_;
    float v;
    if (s < SP_) v = pm[b * SP_ + s];
    else if (s < SP_ + SS_) v = sm[b * SS_ + s - SP_];
    else v = mm[b * SM_ + s - SP_ - SS_];
    out[i] = v;
}

// ---------------- weight transpose+pack: W[K,N] -> T[N,K] single fp16 ----------------
__global__ __launch_bounds__(256) void wpack_T(const float* __restrict__ W,
                                               hlf* __restrict__ Th,
                                               int K, int N) {
    __shared__ float tile[64][65];
    const int tid = threadIdx.x;
    const int n0 = blockIdx.x * 64, k0 = blockIdx.y * 64;
    #pragma unroll
    for (int i = 0; i < 4; i++) {
        int idx = tid + 256 * i;
        int r = idx >> 4, c4 = (idx & 15) * 4;
        float4 v = *(const float4*)&W[(size_t)(k0 + r) * N + n0 + c4];
        tile[r][c4] = v.x; tile[r][c4 + 1] = v.y;
        tile[r][c4 + 2] = v.z; tile[r][c4 + 3] = v.w;
    }
    __syncthreads();
    #pragma unroll
    for (int i = 0; i < 2; i++) {
        int idx = tid + 256 * i;
        int n = idx >> 3, kc = (idx & 7) * 8;
        uint32_t h0 = pack2h(tile[kc + 0][n], tile[kc + 1][n]);
        uint32_t h1 = pack2h(tile[kc + 2][n], tile[kc + 3][n]);
        uint32_t h2 = pack2h(tile[kc + 4][n], tile[kc + 5][n]);
        uint32_t h3 = pack2h(tile[kc + 6][n], tile[kc + 7][n]);
        size_t o = (size_t)(n0 + n) * K + k0 + kc;
        *(uint4*)(Th + o) = make_uint4(h0, h1, h2, h3);
    }
}

// ============== plain fp16 GEMM (A single, B single): BM=128, BN=128, BK=64 ==============
// EPI 2: Cf = res + tanh(gate)*(acc + bias)
// EPI 3: Ch = fp16(gelu(acc))
// EPI 4: Cf = res + tanh(gate)*acc
// EPI 6: Ch = fp16((acc+bias)*scale), row remap (Q/K/V concat)
#define GB_K 64
#define STG1 32768
#define GEMM1_SMEM (2 * STG1)

template <int EPI>
__global__ __launch_bounds__(256, 2) void gemm1(
    const hlf* __restrict__ Ah,
    const hlf* __restrict__ Bh,
    const float* __restrict__ bias, const float* __restrict__ res,
    const float* __restrict__ gate,
    float* __restrict__ Cf, hlf* __restrict__ Ch,
    int M, int N, int K, float scale, int oShift, int oStride, int oOff) {
    extern __shared__ __align__(1024) char smem[];
    uint32_t sb = s2u(smem);
    const int tid = threadIdx.x, wid = tid >> 5, lane = tid & 31;
    const int n0 = blockIdx.x * 128, m0 = blockIdx.y * 128;
    const int wm0 = (wid >> 2) * 64;
    const int wn0 = (wid & 3) * 32;

    auto stage_load = [&](int st, int k0) {
        uint32_t s0 = sb + st * STG1;
        #pragma unroll
        for (int i = 0; i < 4; i++) {
            int idx = tid + 256 * i;
            int r = idx >> 3, c = idx & 7;
            uint32_t byte = r * 128 + c * 16;
            uint32_t sw = byte ^ ((byte >> 3) & 0x70);
            size_t goA = (size_t)(m0 + r) * K + k0 + c * 8;
            size_t goB = (size_t)(n0 + r) * K + k0 + c * 8;
            cp16(s0 + sw,         Ah + goA);
            cp16(s0 + 16384 + sw, Bh + goB);
        }
        asm volatile("cp.async.commit_group;" ::: "memory");
    };

    float acc[4][4][4];
    #pragma unroll
    for (int i = 0; i < 4; i++)
        #pragma unroll
        for (int j = 0; j < 4; j++)
            #pragma unroll
            for (int c = 0; c < 4; c++) acc[i][j][c] = 0.f;

    const int nIter = K / GB_K;
    stage_load(0, 0);

    const int a_row = lane & 15;
    const int a_ch  = lane >> 4;
    const int b_row = (lane & 7) + ((lane >> 4) & 1) * 8;
    const int b_ch  = (lane >> 3) & 1;

    for (int it = 0; it < nIter; ++it) {
        if (it + 1 < nIter) stage_load((it + 1) & 1, (it + 1) * GB_K);
        if (it + 1 < nIter) {
            asm volatile("cp.async.wait_group 1;" ::: "memory");
        } else {
            asm volatile("cp.async.wait_group 0;" ::: "memory");
        }
        __syncthreads();

        uint32_t s0 = sb + (it & 1) * STG1;
        uint32_t sAh = s0, sBh = s0 + 16384;

        #pragma unroll
        for (int ks = 0; ks < 4; ks++) {
            uint32_t ahi[4][4], bhi[4][2];
            #pragma unroll
            for (int i = 0; i < 4; i++) {
                uint32_t byte = (wm0 + i * 16 + a_row) * 128 + (ks * 2 + a_ch) * 16;
                uint32_t sw = byte ^ ((byte >> 3) & 0x70);
                LDSM4(ahi[i][0], ahi[i][1], ahi[i][2], ahi[i][3], sAh + sw);
            }
            #pragma unroll
            for (int jj = 0; jj < 2; jj++) {
                uint32_t byte = (wn0 + jj * 16 + b_row) * 128 + (ks * 2 + b_ch) * 16;
                uint32_t sw = byte ^ ((byte >> 3) & 0x70);
                uint32_t r0, r1, r2, r3;
                LDSM4(r0, r1, r2, r3, sBh + sw);
                bhi[jj * 2][0] = r0; bhi[jj * 2][1] = r1;
                bhi[jj * 2 + 1][0] = r2; bhi[jj * 2 + 1][1] = r3;
            }
            #pragma unroll
            for (int i = 0; i < 4; i++)
                #pragma unroll
                for (int j = 0; j < 4; j++) {
                    MMA16816(acc[i][j], ahi[i], bhi[j]);
                }
        }
        __syncthreads();
    }

    float gt = 0.f;
    if (EPI == 2 || EPI == 4) gt = tanhf(gate[0]);
    const int cr = lane >> 2;
    const int cc = (lane & 3) * 2;

    #pragma unroll
    for (int i = 0; i < 4; i++) {
        #pragma unroll
        for (int j = 0; j < 4; j++) {
            int gcol = n0 + wn0 + j * 8 + cc;
            #pragma unroll
            for (int half = 0; half < 2; half++) {
                int grow = m0 + wm0 + i * 16 + cr + half * 8;
                float v0 = acc[i][j][half * 2 + 0];
                float v1 = acc[i][j][half * 2 + 1];
                size_t o = (size_t)grow * N + gcol;
                if (EPI == 2) {
                    float2 rr = *(const float2*)(res + o);
                    *(float2*)(Cf + o) = make_float2(rr.x + gt * (v0 + bias[gcol]),
                                                     rr.y + gt * (v1 + bias[gcol + 1]));
                } else if (EPI == 3) {
                    *(uint32_t*)(Ch + o) = pack2h(gelu_f(v0), gelu_f(v1));
                } else if (EPI == 4) {
                    float2 rr = *(const float2*)(res + o);
                    *(float2*)(Cf + o) = make_float2(rr.x + gt * v0, rr.y + gt * v1);
                } else {  // EPI 6
                    int ib = grow >> oShift;
                    int ir = grow & ((1 << oShift) - 1);
                    size_t oo = ((size_t)ib * oStride + oOff + ir) * N + gcol;
                    *(uint32_t*)(Ch + oo) = pack2h((v0 + bias[gcol]) * scale,
                                                   (v1 + bias[gcol + 1]) * scale);
                }
            }
        }
    }
}

// ---------------- register-resident FA2 attention (all single fp16) ----------------
// smem: Q 32K | 2 stages x (Kh 16K | Vh 16K | mask 256B)
#define AQ_H 0u
#define AKV  32768u
#define AST  33024u
#define ATTN_SMEM (32768 + 2 * 33024)

__global__ __launch_bounds__(256) void attn_fa2(
    const hlf* __restrict__ Qh,
    const hlf* __restrict__ Kh,
    const hlf* __restrict__ Vh,
    const float* __restrict__ qmask, const float* __restrict__ kvmask,
    hlf* __restrict__ Oh) {
    extern __shared__ __align__(1024) char smem[];
    uint32_t sb = s2u(smem);

    const int qt = blockIdx.x, h = blockIdx.y, b = blockIdx.z;
    const int q0 = qt * 128;
    const int tid = threadIdx.x, wid = tid >> 5, lane = tid & 31;
    const int wrow = wid * 16;
    const int a_row = lane & 15, a_ch = lane >> 4;
    const int b_row = (lane & 7) + ((lane >> 4) & 1) * 8;
    const int b_ch  = (lane >> 3) & 1;
    const int cr = lane >> 2, cc = (lane & 3) * 2;

    auto kv_load = [&](int st, int t) {
        uint32_t s0 = sb + AKV + st * AST;
        int kv0 = t * 64;
        #pragma unroll
        for (int i = 0; i < 4; i++) {
            int idx = tid + 256 * i;
            int r = idx >> 4, c16 = idx & 15;
            uint32_t off = r * 256 + (((uint32_t)(c16 ^ (r & 7))) << 4);
            size_t go = (size_t)(b * SKV_ + kv0 + r) * D_ + h * HD_ + c16 * 8;
            cp16(s0 + off,          Kh + go);
            cp16(s0 + 16384 + off,  Vh + go);
        }
        if (tid < 16)
            cp16(s0 + 32768 + tid * 16, kvmask + b * SKV_ + t * 64 + tid * 4);
        asm volatile("cp.async.commit_group;" ::: "memory");
    };

    #pragma unroll
    for (int i = 0; i < 8; i++) {
        int idx = tid + 256 * i;
        int r = idx >> 4, c16 = idx & 15;
        uint32_t off = r * 256 + (((uint32_t)(c16 ^ (r & 7))) << 4);
        size_t go = (size_t)(b * SQ_ + q0 + r) * D_ + h * HD_ + c16 * 8;
        cp16(sb + AQ_H + off, Qh + go);
    }
    asm volatile("cp.async.commit_group;" ::: "memory");
    kv_load(0, 0);
    asm volatile("cp.async.wait_group 0;" ::: "memory");
    __syncthreads();

    uint32_t qhf[8][4];
    #pragma unroll
    for (int ks = 0; ks < 8; ks++) {
        int row = wrow + a_row;
        int c16 = ks * 2 + a_ch;
        uint32_t off = row * 256 + (((uint32_t)(c16 ^ (row & 7))) << 4);
        LDSM4(qhf[ks][0], qhf[ks][1], qhf[ks][2], qhf[ks][3], sb + AQ_H + off);
    }

    const float qm0 = qmask[b * SQ_ + q0 + wrow + cr];
    const float qm8 = qmask[b * SQ_ + q0 + wrow + cr + 8];

    float m0 = -1e30f, m8 = -1e30f, l0 = 0.f, l8 = 0.f;
    float oacc[16][4];
    #pragma unroll
    for (int j = 0; j < 16; j++)
        #pragma unroll
        for (int c = 0; c < 4; c++) oacc[j][c] = 0.f;

    const int T = SKV_ / 64;
    for (int t = 0; t < T; ++t) {
        if (t + 1 < T) kv_load((t + 1) & 1, t + 1);
        if (t + 1 < T) {
            asm volatile("cp.async.wait_group 1;" ::: "memory");
        } else {
            asm volatile("cp.async.wait_group 0;" ::: "memory");
        }
        __syncthreads();

        uint32_t s0 = sb + AKV + (t & 1) * AST;
        uint32_t sKh = s0, sVh = s0 + 16384;
        const float* msk = (const float*)(smem + AKV + (t & 1) * AST + 32768);

        float sacc[8][4];
        #pragma unroll
        for (int j = 0; j < 8; j++)
            #pragma unroll
            for (int c = 0; c < 4; c++) sacc[j][c] = 0.f;

        #pragma unroll
        for (int ks = 0; ks < 8; ks++) {
            #pragma unroll
            for (int jj = 0; jj < 4; jj++) {
                int row = jj * 16 + b_row;
                int c16 = ks * 2 + b_ch;
                uint32_t off = row * 256 + (((uint32_t)(c16 ^ (row & 7))) << 4);
                uint32_t k0, k1, k2, k3;
                LDSM4(k0, k1, k2, k3, sKh + off);
                uint32_t bh0[2] = {k0, k1}, bh1[2] = {k2, k3};
                MMA16816(sacc[jj * 2],     qhf[ks], bh0);
                MMA16816(sacc[jj * 2 + 1], qhf[ks], bh1);
            }
        }

        #pragma unroll
        for (int j = 0; j < 8; j++) {
            float2 km = *(const float2*)&msk[j * 8 + cc];
            if (qm0 == 0.f || km.x == 0.f) sacc[j][0] = -3.0e38f;
            if (qm0 == 0.f || km.y == 0.f) sacc[j][1] = -3.0e38f;
            if (qm8 == 0.f || km.x == 0.f) sacc[j][2] = -3.0e38f;
            if (qm8 == 0.f || km.y == 0.f) sacc[j][3] = -3.0e38f;
        }
        float mx0 = sacc[0][0], mx8 = sacc[0][2];
        #pragma unroll
        for (int j = 0; j < 8; j++) {
            mx0 = fmaxf(mx0, fmaxf(sacc[j][0], sacc[j][1]));
            mx8 = fmaxf(mx8, fmaxf(sacc[j][2], sacc[j][3]));
        }
        mx0 = fmaxf(mx0, __shfl_xor_sync(0xffffffffu, mx0, 1));
        mx0 = fmaxf(mx0, __shfl_xor_sync(0xffffffffu, mx0, 2));
        mx8 = fmaxf(mx8, __shfl_xor_sync(0xffffffffu, mx8, 1));
        mx8 = fmaxf(mx8, __shfl_xor_sync(0xffffffffu, mx8, 2));
        float m0n = fmaxf(m0, mx0), m8n = fmaxf(m8, mx8);
        float al0 = __expf(m0 - m0n), al8 = __expf(m8 - m8n);
        float sum0 = 0.f, sum8 = 0.f;
        #pragma unroll
        for (int j = 0; j < 8; j++) {
            sacc[j][0] = __expf(sacc[j][0] - m0n);
            sacc[j][1] = __expf(sacc[j][1] - m0n);
            sacc[j][2] = __expf(sacc[j][2] - m8n);
            sacc[j][3] = __expf(sacc[j][3] - m8n);
            sum0 += sacc[j][0] + sacc[j][1];
            sum8 += sacc[j][2] + sacc[j][3];
        }
        sum0 += __shfl_xor_sync(0xffffffffu, sum0, 1);
        sum0 += __shfl_xor_sync(0xffffffffu, sum0, 2);
        sum8 += __shfl_xor_sync(0xffffffffu, sum8, 1);
        sum8 += __shfl_xor_sync(0xffffffffu, sum8, 2);
        l0 = l0 * al0 + sum0; l8 = l8 * al8 + sum8;
        m0 = m0n; m8 = m8n;

        #pragma unroll
        for (int j = 0; j < 16; j++) {
            oacc[j][0] *= al0; oacc[j][1] *= al0;
            oacc[j][2] *= al8; oacc[j][3] *= al8;
        }

        // O += P @ V (P single fp16, V single)
        #pragma unroll
        for (int ks = 0; ks < 4; ks++) {
            uint32_t ph[4];
            ph[0] = pack2h(sacc[ks * 2][0],     sacc[ks * 2][1]);
            ph[1] = pack2h(sacc[ks * 2][2],     sacc[ks * 2][3]);
            ph[2] = pack2h(sacc[ks * 2 + 1][0], sacc[ks * 2 + 1][1]);
            ph[3] = pack2h(sacc[ks * 2 + 1][2], sacc[ks * 2 + 1][3]);
            #pragma unroll
            for (int ng = 0; ng < 8; ng++) {
                int k_row = ks * 16 + (lane & 15);
                int c16v = ng * 2 + (lane >> 4);
                uint32_t off = k_row * 256 + (((uint32_t)(c16v ^ (k_row & 7))) << 4);
                uint32_t v0, v1, v2, v3;
                LDSM4T(v0, v1, v2, v3, sVh + off);
                uint32_t bh0[2] = {v0, v1}, bh1[2] = {v2, v3};
                MMA16816(oacc[ng * 2],     ph, bh0);
                MMA16816(oacc[ng * 2 + 1], ph, bh1);
            }
        }
        __syncthreads();
    }

    float inv0 = 1.0f / l0, inv8 = 1.0f / l8;
    #pragma unroll
    for (int j = 0; j < 16; j++) {
        int gcol = h * HD_ + j * 8 + cc;
        int r0 = q0 + wrow + cr;
        size_t o0 = (size_t)(b * SQ_ + r0) * D_ + gcol;
        size_t o8 = o0 + (size_t)8 * D_;
        *(uint32_t*)(Oh + o0) = pack2h(oacc[j][0] * inv0, oacc[j][1] * inv0);
        *(uint32_t*)(Oh + o8) = pack2h(oacc[j][2] * inv8, oacc[j][3] * inv8);
    }
}

// ---------------- launcher ----------------
extern "C" void kernel_launch(void* const* d_in, const int* in_sizes, int n_in,
                              void* d_out, int out_size) {
    const float* x     = (const float*)d_in[0];
    const float* pkv   = (const float*)d_in[1];
    const float* skv   = (const float*)d_in[2];
    const float* mkv   = (const float*)d_in[3];
    const float* qmask = (const float*)d_in[4];
    const float* pmask = (const float*)d_in[5];
    const float* smask = (const float*)d_in[6];
    const float* mmask = (const float*)d_in[7];
    const float* rmsw  = (const float*)d_in[8];
    const float* Wq  = (const float*)d_in[9];   const float* bq  = (const float*)d_in[10];
    const float* Wkp = (const float*)d_in[11];  const float* bkp = (const float*)d_in[12];
    const float* Wvp = (const float*)d_in[13];  const float* bvp = (const float*)d_in[14];
    const float* Wks = (const float*)d_in[15];  const float* bks = (const float*)d_in[16];
    const float* Wvs = (const float*)d_in[17];  const float* bvs = (const float*)d_in[18];
    const float* Wkm = (const float*)d_in[19];  const float* bkm = (const float*)d_in[20];
    const float* Wvm = (const float*)d_in[21];  const float* bvm = (const float*)d_in[22];
    const float* Wo  = (const float*)d_in[23];  const float* bo  = (const float*)d_in[24];
    const float* lng = (const float*)d_in[25];  const float* lnb = (const float*)d_in[26];
    const float* W1  = (const float*)d_in[27];  const float* W2  = (const float*)d_in[28];
    const float* ga  = (const float*)d_in[29];  const float* gf  = (const float*)d_in[30];
    float* out = (float*)d_out;

    float *hh, *kvm;
    cudaGetSymbolAddress((void**)&hh,  g_h);
    cudaGetSymbolAddress((void**)&kvm, g_kvmask);

    hlf *qn,*ap,*as,*am,*qh,*kh,*vh,*cxh,*lnh,*ffh;
    cudaGetSymbolAddress((void**)&qn,  g_qn);
    cudaGetSymbolAddress((void**)&ap,  g_ap);
    cudaGetSymbolAddress((void**)&as,  g_as);
    cudaGetSymbolAddress((void**)&am,  g_am);
    cudaGetSymbolAddress((void**)&qh,  g_qh);
    cudaGetSymbolAddress((void**)&kh,  g_kh);
    cudaGetSymbolAddress((void**)&vh,  g_vh);
    cudaGetSymbolAddress((void**)&cxh, g_cx_h);
    cudaGetSymbolAddress((void**)&lnh, g_ln_h);
    cudaGetSymbolAddress((void**)&ffh, g_ff_h);

    hlf *tWq,*tWkp,*tWvp,*tWks,*tWvs,*tWkm,*tWvm,*tWo,*tW1,*tW2;
    cudaGetSymbolAddress((void**)&tWq,  g_Wq);
    cudaGetSymbolAddress((void**)&tWkp, g_Wkp);
    cudaGetSymbolAddress((void**)&tWvp, g_Wvp);
    cudaGetSymbolAddress((void**)&tWks, g_Wks);
    cudaGetSymbolAddress((void**)&tWvs, g_Wvs);
    cudaGetSymbolAddress((void**)&tWkm, g_Wkm);
    cudaGetSymbolAddress((void**)&tWvm, g_Wvm);
    cudaGetSymbolAddress((void**)&tWo,  g_Wo);
    cudaGetSymbolAddress((void**)&tW1,  g_W1);
    cudaGetSymbolAddress((void**)&tW2,  g_W2);

    cudaFuncSetAttribute(gemm1<2>, cudaFuncAttributeMaxDynamicSharedMemorySize, GEMM1_SMEM);
    cudaFuncSetAttribute(gemm1<3>, cudaFuncAttributeMaxDynamicSharedMemorySize, GEMM1_SMEM);
    cudaFuncSetAttribute(gemm1<4>, cudaFuncAttributeMaxDynamicSharedMemorySize, GEMM1_SMEM);
    cudaFuncSetAttribute(gemm1<6>, cudaFuncAttributeMaxDynamicSharedMemorySize, GEMM1_SMEM);
    cudaFuncSetAttribute(attn_fa2, cudaFuncAttributeMaxDynamicSharedMemorySize, ATTN_SMEM);

    // weight transpose+pack (single fp16)
    wpack_T<<<dim3(D_ / 64,     D_ / 64),     256>>>(Wq,  tWq,  D_,     D_);
    wpack_T<<<dim3(D_ / 64,     DP_ / 64),    256>>>(Wkp, tWkp, DP_,    D_);
    wpack_T<<<dim3(D_ / 64,     DP_ / 64),    256>>>(Wvp, tWvp, DP_,    D_);
    wpack_T<<<dim3(D_ / 64,     DS_ / 64),    256>>>(Wks, tWks, DS_,    D_);
    wpack_T<<<dim3(D_ / 64,     DS_ / 64),    256>>>(Wvs, tWvs, DS_,    D_);
    wpack_T<<<dim3(D_ / 64,     DM_ / 64),    256>>>(Wkm, tWkm, DM_,    D_);
    wpack_T<<<dim3(D_ / 64,     DM_ / 64),    256>>>(Wvm, tWvm, DM_,    D_);
    wpack_T<<<dim3(D_ / 64,     D_ / 64),     256>>>(Wo,  tWo,  D_,     D_);
    wpack_T<<<dim3(INNER_ / 64, D_ / 64),     256>>>(W1,  tW1,  D_,     INNER_);
    wpack_T<<<dim3(D_ / 64,     INNER_ / 64), 256>>>(W2,  tW2,  INNER_, D_);

    // activation packs + mask concat
    rmsnorm_h<<<B_ * SQ_, 256>>>(x, rmsw, qn);
    pack_k<<<(B_ * SP_ * DP_ / 4 + 255) / 256, 256>>>(pkv, ap, B_ * SP_ * DP_ / 4);
    pack_k<<<(B_ * SS_ * DS_ / 4 + 255) / 256, 256>>>(skv, as, B_ * SS_ * DS_ / 4);
    pack_k<<<(B_ * SM_ * DM_ / 4 + 255) / 256, 256>>>(mkv, am, B_ * SM_ * DM_ / 4);
    maskcat_k<<<(B_ * SKV_ + 255) / 256, 256>>>(pmask, smask, mmask, kvm);

    // Q projection (scale 0.25 folded)
    gemm1<6><<<dim3(16, 16), 256, GEMM1_SMEM>>>(qn, tWq, bq, nullptr, nullptr,
        nullptr, qh, 2048, 2048, 2048, 0.25f, 10, 1024, 0);

    // K projections (remap to concat [B,SKV,D])
    gemm1<6><<<dim3(16, 16), 256, GEMM1_SMEM>>>(ap, tWkp, bkp, nullptr, nullptr,
        nullptr, kh, 2048, 2048, 1280, 1.f, 10, SKV_, 0);
    gemm1<6><<<dim3(16, 16), 256, GEMM1_SMEM>>>(as, tWks, bks, nullptr, nullptr,
        nullptr, kh, 2048, 2048, 1024, 1.f, 10, SKV_, SP_);
    gemm1<6><<<dim3(16, 8), 256, GEMM1_SMEM>>>(am, tWkm, bkm, nullptr, nullptr,
        nullptr, kh, 1024, 2048, 768, 1.f, 9, SKV_, SP_ + SS_);

    // V projections
    gemm1<6><<<dim3(16, 16), 256, GEMM1_SMEM>>>(ap, tWvp, bvp, nullptr, nullptr,
        nullptr, vh, 2048, 2048, 1280, 1.f, 10, SKV_, 0);
    gemm1<6><<<dim3(16, 16), 256, GEMM1_SMEM>>>(as, tWvs, bvs, nullptr, nullptr,
        nullptr, vh, 2048, 2048, 1024, 1.f, 10, SKV_, SP_);
    gemm1<6><<<dim3(16, 8), 256, GEMM1_SMEM>>>(am, tWvm, bvm, nullptr, nullptr,
        nullptr, vh, 1024, 2048, 768, 1.f, 9, SKV_, SP_ + SS_);

    // attention -> ctx single fp16
    attn_fa2<<<dim3(8, 16, 2), 256, ATTN_SMEM>>>(qh, kh, vh, qmask, kvm, cxh);

    // h = x + tanh(ga)*(ctx@Wo + bo)
    gemm1<2><<<dim3(16, 16), 256, GEMM1_SMEM>>>(cxh, tWo, bo, x, ga,
        hh, nullptr, 2048, 2048, 2048, 1.f, 0, 0, 0);

    // LayerNorm -> single fp16
    layernorm_h<<<B_ * SQ_, 256>>>(hh, lng, lnb, lnh);

    // FFW
    gemm1<3><<<dim3(64, 16), 256, GEMM1_SMEM>>>(lnh, tW1, nullptr, nullptr, nullptr,
        nullptr, ffh, 2048, INNER_, 2048, 1.f, 0, 0, 0);
    gemm1<4><<<dim3(16, 16), 256, GEMM1_SMEM>>>(ffh, tW2, nullptr, hh, gf,
        out, nullptr, 2048, 2048, INNER_, 1.f, 0, 0, 0);
}